// round 2
// baseline (speedup 1.0000x reference)
#include <cuda_runtime.h>
#include <cuda_bf16.h>
#include <mma.h>
#include <math.h>

using namespace nvcuda;

// ---------------- problem constants ----------------
#define NROWS 65536
#define HDIM  512
#define MD    128
#define PROTO 12
#define KR    1408   // 2H + 3*MD
#define KF    2048   // 4H
#define RSCALE 0.2f

// ---------------- scratch (device globals; allocation-free) ----------------
__device__ __align__(16) float g_RIN  [(size_t)NROWS * KR];
__device__ __align__(16) float g_H1   [(size_t)NROWS * HDIM];
__device__ __align__(16) float g_FEATS[(size_t)NROWS * KF];
__device__ __align__(16) float g_HMU  [(size_t)NROWS * HDIM];
__device__ __align__(16) float g_HMG  [(size_t)NROWS * HDIM];
__device__ __align__(16) float g_DELTA[(size_t)NROWS * HDIM];
__device__ __align__(16) float g_GATE [(size_t)NROWS * HDIM];

// ---------------- helpers ----------------
__device__ __forceinline__ float gelu_exact(float x) {
    return 0.5f * x * (1.0f + erff(x * 0.70710678118654752440f));
}

__device__ __forceinline__ float block_sum_256(float v, float* sbuf) {
    #pragma unroll
    for (int o = 16; o; o >>= 1) v += __shfl_xor_sync(0xffffffffu, v, o);
    int w = threadIdx.x >> 5;
    if ((threadIdx.x & 31) == 0) sbuf[w] = v;
    __syncthreads();
    if (threadIdx.x < 32) {
        float s = (threadIdx.x < 8) ? sbuf[threadIdx.x] : 0.0f;
        #pragma unroll
        for (int o = 4; o; o >>= 1) s += __shfl_xor_sync(0xffffffffu, s, o);
        if (threadIdx.x == 0) sbuf[0] = s;
    }
    __syncthreads();
    float r = sbuf[0];
    __syncthreads();
    return r;
}

__device__ __forceinline__ double block_sum_256d(double v, double* sbuf) {
    #pragma unroll
    for (int o = 16; o; o >>= 1) v += __shfl_xor_sync(0xffffffffu, v, o);
    int w = threadIdx.x >> 5;
    if ((threadIdx.x & 31) == 0) sbuf[w] = v;
    __syncthreads();
    if (threadIdx.x < 32) {
        double s = (threadIdx.x < 8) ? sbuf[threadIdx.x] : 0.0;
        #pragma unroll
        for (int o = 4; o; o >>= 1) s += __shfl_xor_sync(0xffffffffu, s, o);
        if (threadIdx.x == 0) sbuf[0] = s;
    }
    __syncthreads();
    double r = sbuf[0];
    __syncthreads();
    return r;
}

// 2Sum based compensated add: (sum, comp) += v  (branch-free, exact error term)
__device__ __forceinline__ void twosum_acc(float& sum, float& comp, float v) {
    float s = sum + v;
    float z = s - sum;
    float e = (sum - (s - z)) + (v - z);
    sum = s;
    comp += e;
}

// ---------------- kernel 1: gather router input [N,1408] ----------------
__global__ void k_gather(const float* __restrict__ pair, const float* __restrict__ ep,
                         const int* __restrict__ sid, const int* __restrict__ hc,
                         const int* __restrict__ ps,
                         const float* __restrict__ se, const float* __restrict__ he,
                         const float* __restrict__ soe) {
    int row = blockIdx.x;
    int s = min(max(sid[row], 0), 2048);
    int h = min(max(hc[row], 0), 9);
    int p = min(max(ps[row], 0), 7);
    float* dst = &g_RIN[(size_t)row * KR];
    const float* pr = &pair[(size_t)row * HDIM];
    const float* er = &ep[(size_t)row * HDIM];
    for (int c = threadIdx.x; c < KR; c += blockDim.x) {
        float v;
        if      (c < 512)  v = pr[c];
        else if (c < 1024) v = er[c - 512];
        else if (c < 1152) v = se[s * MD + (c - 1024)];
        else if (c < 1280) v = he[h * MD + (c - 1152)];
        else               v = soe[p * MD + (c - 1280)];
        dst[c] = v;
    }
}

// ---------------- tf32 wmma GEMM: C[M,NC] = A[M,K] @ B[K,NC] ----------------
// BM=128, BN=64, BK=16; 8 warps (4x2), each warp 32x32 (2x2 m16n16k8 frags)
// EXACT=true: 4-term tf32 split (hi/lo x hi/lo) + per-chunk accumulators merged
//             via 2Sum compensation -> near-exact fp32 GEMM.
#define BM 128
#define BN 64
#define BK 16

template <bool EXACT>
__global__ void __launch_bounds__(256) gemm_tf32(const float* __restrict__ A,
                                                 const float* __restrict__ B,
                                                 float* __restrict__ C,
                                                 int K, int NC) {
    const int m0 = blockIdx.y * BM;
    const int n0 = blockIdx.x * BN;
    __shared__ float As[BM][BK + 4];
    __shared__ float Bs[BK][BN + 4];
    const int tid  = threadIdx.x;
    const int warp = tid >> 5;
    const int wr   = warp >> 1;   // 0..3
    const int wc   = warp & 1;    // 0..1

    wmma::fragment<wmma::accumulator, 16, 16, 8, float> cacc[2][2];
    float sum[2][2][8];
    float comp[2][2][8];
    #pragma unroll
    for (int i = 0; i < 2; i++)
        #pragma unroll
        for (int j = 0; j < 2; j++) {
            wmma::fill_fragment(cacc[i][j], 0.0f);
            #pragma unroll
            for (int t = 0; t < 8; t++) { sum[i][j][t] = 0.0f; comp[i][j][t] = 0.0f; }
        }

    for (int kt = 0; kt < K; kt += BK) {
        #pragma unroll
        for (int r = 0; r < 2; r++) {
            int idx = tid + r * 256;
            int row = idx >> 2;
            int c4  = (idx & 3) << 2;
            const float4 v = *reinterpret_cast<const float4*>(
                &A[(size_t)(m0 + row) * K + kt + c4]);
            As[row][c4 + 0] = v.x; As[row][c4 + 1] = v.y;
            As[row][c4 + 2] = v.z; As[row][c4 + 3] = v.w;
        }
        {
            int row = tid >> 4;
            int c4  = (tid & 15) << 2;
            const float4 v = *reinterpret_cast<const float4*>(
                &B[(size_t)(kt + row) * NC + n0 + c4]);
            Bs[row][c4 + 0] = v.x; Bs[row][c4 + 1] = v.y;
            Bs[row][c4 + 2] = v.z; Bs[row][c4 + 3] = v.w;
        }
        __syncthreads();

        #pragma unroll
        for (int ks = 0; ks < BK; ks += 8) {
            wmma::fragment<wmma::matrix_a, 16, 16, 8, wmma::precision::tf32, wmma::row_major> af[2], afl[2];
            wmma::fragment<wmma::matrix_b, 16, 16, 8, wmma::precision::tf32, wmma::row_major> bf[2], bfl[2];
            #pragma unroll
            for (int i = 0; i < 2; i++) {
                wmma::load_matrix_sync(af[i], &As[wr * 32 + i * 16][ks], BK + 4);
                #pragma unroll
                for (int t = 0; t < af[i].num_elements; t++) {
                    float v  = af[i].x[t];
                    float hi = wmma::__float_to_tf32(v);
                    af[i].x[t] = hi;
                    if (EXACT) afl[i].x[t] = wmma::__float_to_tf32(v - hi);
                }
            }
            #pragma unroll
            for (int j = 0; j < 2; j++) {
                wmma::load_matrix_sync(bf[j], &Bs[ks][wc * 32 + j * 16], BN + 4);
                #pragma unroll
                for (int t = 0; t < bf[j].num_elements; t++) {
                    float v  = bf[j].x[t];
                    float hi = wmma::__float_to_tf32(v);
                    bf[j].x[t] = hi;
                    if (EXACT) bfl[j].x[t] = wmma::__float_to_tf32(v - hi);
                }
            }
            #pragma unroll
            for (int i = 0; i < 2; i++)
                #pragma unroll
                for (int j = 0; j < 2; j++) {
                    if (EXACT) {
                        wmma::mma_sync(cacc[i][j], afl[i], bfl[j], cacc[i][j]);
                        wmma::mma_sync(cacc[i][j], af[i],  bfl[j], cacc[i][j]);
                        wmma::mma_sync(cacc[i][j], afl[i], bf[j],  cacc[i][j]);
                    }
                    wmma::mma_sync(cacc[i][j], af[i], bf[j], cacc[i][j]);
                }
        }
        if (EXACT) {
            // merge chunk accumulator into compensated running sum, reset chunk
            #pragma unroll
            for (int i = 0; i < 2; i++)
                #pragma unroll
                for (int j = 0; j < 2; j++)
                    #pragma unroll
                    for (int t = 0; t < 8; t++) {
                        twosum_acc(sum[i][j][t], comp[i][j][t], cacc[i][j].x[t]);
                        cacc[i][j].x[t] = 0.0f;
                    }
        }
        __syncthreads();
    }

    #pragma unroll
    for (int i = 0; i < 2; i++)
        #pragma unroll
        for (int j = 0; j < 2; j++) {
            if (EXACT) {
                #pragma unroll
                for (int t = 0; t < 8; t++)
                    cacc[i][j].x[t] = sum[i][j][t] + comp[i][j][t];
            }
            float* Cp = C + (size_t)(m0 + wr * 32 + i * 16) * NC + n0 + wc * 32 + j * 16;
            wmma::store_matrix_sync(Cp, cacc[i][j], NC, wmma::mem_row_major);
        }
}

// ---------------- kernel 3: router LN + GELU (fp64 reductions, in-place g_H1) ----
__global__ void k_lngelu_router(const float* __restrict__ b, const float* __restrict__ g,
                                const float* __restrict__ beta) {
    __shared__ double sbuf[8];
    int row = blockIdx.x, t = threadIdx.x;
    float* x = &g_H1[(size_t)row * HDIM];
    float x0 = x[t] + b[t];
    float x1 = x[t + 256] + b[t + 256];
    double mean = block_sum_256d((double)x0 + (double)x1, sbuf) * (1.0 / 512.0);
    double e0 = (double)x0 - mean, e1 = (double)x1 - mean;
    double var = block_sum_256d(e0 * e0 + e1 * e1, sbuf) * (1.0 / 512.0);
    float rs = (float)(1.0 / sqrt(var + 1e-5));
    float d0 = (float)e0, d1 = (float)e1;
    x[t]       = gelu_exact(d0 * rs * g[t] + beta[t]);
    x[t + 256] = gelu_exact(d1 * rs * g[t + 256] + beta[t + 256]);
}

// ---------------- kernel 4: logits (compensated), softmax, top-4, ctx, feats ----
__global__ void k_router2(const float* __restrict__ ep,
                          const float* __restrict__ w2, const float* __restrict__ b2,
                          const float* __restrict__ proto,
                          float* __restrict__ outC, float* __restrict__ outW) {
    __shared__ float sh[HDIM];
    __shared__ float sl[PROTO];
    __shared__ float sw[PROTO];
    int row = blockIdx.x, t = threadIdx.x;    // 128 threads
    const float* hrow = &g_H1[(size_t)row * HDIM];
    for (int c = t; c < HDIM; c += 128) sh[c] = hrow[c];
    __syncthreads();
    int warp = t >> 5, lane = t & 31;
    for (int l = warp; l < PROTO; l += 4) {
        // TwoProduct (FMA) + 2Sum compensated dot: near-exact fp32
        float s = 0.0f, cmp = 0.0f;
        for (int c = lane; c < HDIM; c += 32) {
            float a = sh[c], w = w2[c * PROTO + l];
            float p  = a * w;
            float pe = fmaf(a, w, -p);        // exact product error
            twosum_acc(s, cmp, p);
            cmp += pe;
        }
        // reduce (s, cmp) across lanes
        #pragma unroll
        for (int o = 16; o; o >>= 1) {
            s   += __shfl_xor_sync(0xffffffffu, s, o);
            cmp += __shfl_xor_sync(0xffffffffu, cmp, o);
        }
        if (lane == 0) sl[l] = (s + cmp) + b2[l];
    }
    __syncthreads();
    if (t == 0) {
        float w[PROTO];
        float mx = -1e30f;
        #pragma unroll
        for (int i = 0; i < PROTO; i++) mx = fmaxf(mx, sl[i]);
        float ssum = 0.0f;
        #pragma unroll
        for (int i = 0; i < PROTO; i++) { w[i] = expf(sl[i] - mx); ssum += w[i]; }
        float inv = 1.0f / ssum;
        #pragma unroll
        for (int i = 0; i < PROTO; i++) w[i] *= inv;
        bool sel[PROTO];
        #pragma unroll
        for (int i = 0; i < PROTO; i++) sel[i] = false;
        for (int k = 0; k < 4; k++) {
            int bi = -1; float bv = -1e30f;
            #pragma unroll
            for (int i = 0; i < PROTO; i++)
                if (!sel[i] && w[i] > bv) { bv = w[i]; bi = i; }
            sel[bi] = true;
        }
        float s2 = 0.0f;
        #pragma unroll
        for (int i = 0; i < PROTO; i++) { float v = sel[i] ? w[i] : 0.0f; sw[i] = v; s2 += v; }
        float d = 1.0f / fmaxf(s2, 1e-6f);
        #pragma unroll
        for (int i = 0; i < PROTO; i++) sw[i] *= d;
    }
    __syncthreads();
    if (t < PROTO) outW[(size_t)row * PROTO + t] = sw[t];
    const float* eprow = &ep[(size_t)row * HDIM];
    float* frow = &g_FEATS[(size_t)row * KF];
    for (int j = t; j < HDIM; j += 128) {
        float c = 0.0f;
        #pragma unroll
        for (int p = 0; p < PROTO; p++) c += sw[p] * proto[p * HDIM + j];
        float e = eprow[j];
        outC[(size_t)row * HDIM + j] = c;
        frow[j]         = e;
        frow[512  + j]  = c;
        frow[1024 + j]  = fabsf(e - c);
        frow[1536 + j]  = e * c;
    }
}

// ---------------- kernel 7: mu LN+GELU (g_HMU), mg GELU (g_HMG), in-place -------
__global__ void k_act(const float* __restrict__ b_mu, const float* __restrict__ g_mu,
                      const float* __restrict__ be_mu, const float* __restrict__ b_mg) {
    __shared__ float sbuf[8];
    int row = blockIdx.x, t = threadIdx.x;
    float* xm = &g_HMU[(size_t)row * HDIM];
    float* xg = &g_HMG[(size_t)row * HDIM];
    float m0 = xm[t] + b_mu[t];
    float m1 = xm[t + 256] + b_mu[t + 256];
    float mean = block_sum_256(m0 + m1, sbuf) * (1.0f / 512.0f);
    float d0 = m0 - mean, d1 = m1 - mean;
    float var = block_sum_256(d0 * d0 + d1 * d1, sbuf) * (1.0f / 512.0f);
    float rs = rsqrtf(var + 1e-5f);
    xm[t]       = gelu_exact(d0 * rs * g_mu[t] + be_mu[t]);
    xm[t + 256] = gelu_exact(d1 * rs * g_mu[t + 256] + be_mu[t + 256]);
    xg[t]       = gelu_exact(xg[t] + b_mg[t]);
    xg[t + 256] = gelu_exact(xg[t + 256] + b_mg[t + 256]);
}

// ---------------- kernel 10: gate, residual, final LN -> updated ----------------
__global__ void k_final(const float* __restrict__ ep, const float* __restrict__ mub2,
                        const float* __restrict__ mgb2, const float* __restrict__ ng,
                        const float* __restrict__ nb, float* __restrict__ outU) {
    __shared__ float sbuf[8];
    int row = blockIdx.x, t = threadIdx.x;
    const float* e  = &ep[(size_t)row * HDIM];
    const float* d  = &g_DELTA[(size_t)row * HDIM];
    const float* gp = &g_GATE[(size_t)row * HDIM];
    float u[2];
    #pragma unroll
    for (int r = 0; r < 2; r++) {
        int c = t + r * 256;
        float delta = d[c] + mub2[c];
        float gg    = gp[c] + mgb2[c];
        float gate  = 1.0f / (1.0f + expf(-gg));
        u[r] = e[c] + RSCALE * gate * delta;
    }
    float mean = block_sum_256(u[0] + u[1], sbuf) * (1.0f / 512.0f);
    float d0 = u[0] - mean, d1 = u[1] - mean;
    float var = block_sum_256(d0 * d0 + d1 * d1, sbuf) * (1.0f / 512.0f);
    float rs = rsqrtf(var + 1e-5f);
    outU[(size_t)row * HDIM + t]       = d0 * rs * ng[t] + nb[t];
    outU[(size_t)row * HDIM + t + 256] = d1 * rs * ng[t + 256] + nb[t + 256];
}

// ---------------- launch ----------------
extern "C" void kernel_launch(void* const* d_in, const int* in_sizes, int n_in,
                              void* d_out, int out_size) {
    const float* pair = (const float*)d_in[0];
    const float* ep   = (const float*)d_in[1];
    const int*   sid  = (const int*)d_in[2];
    const int*   hc   = (const int*)d_in[3];
    const int*   ps   = (const int*)d_in[4];
    const float* se   = (const float*)d_in[5];
    const float* he   = (const float*)d_in[6];
    const float* soe  = (const float*)d_in[7];
    const float* proto= (const float*)d_in[8];
    const float* rw1  = (const float*)d_in[9];
    const float* rb1  = (const float*)d_in[10];
    const float* rlg  = (const float*)d_in[11];
    const float* rlb  = (const float*)d_in[12];
    const float* rw2  = (const float*)d_in[13];
    const float* rb2  = (const float*)d_in[14];
    const float* muw1 = (const float*)d_in[15];
    const float* mub1 = (const float*)d_in[16];
    const float* mulg = (const float*)d_in[17];
    const float* mulb = (const float*)d_in[18];
    const float* muw2 = (const float*)d_in[19];
    const float* mub2 = (const float*)d_in[20];
    const float* mgw1 = (const float*)d_in[21];
    const float* mgb1 = (const float*)d_in[22];
    const float* mgw2 = (const float*)d_in[23];
    const float* mgb2 = (const float*)d_in[24];
    const float* ng   = (const float*)d_in[25];
    const float* nb   = (const float*)d_in[26];

    float* outU = (float*)d_out;
    float* outC = outU + (size_t)NROWS * HDIM;
    float* outW = outC + (size_t)NROWS * HDIM;

    float *pRIN, *pH1, *pFEATS, *pHMU, *pHMG, *pDELTA, *pGATE;
    cudaGetSymbolAddress((void**)&pRIN,   g_RIN);
    cudaGetSymbolAddress((void**)&pH1,    g_H1);
    cudaGetSymbolAddress((void**)&pFEATS, g_FEATS);
    cudaGetSymbolAddress((void**)&pHMU,   g_HMU);
    cudaGetSymbolAddress((void**)&pHMG,   g_HMG);
    cudaGetSymbolAddress((void**)&pDELTA, g_DELTA);
    cudaGetSymbolAddress((void**)&pGATE,  g_GATE);

    dim3 gemm_block(256);
    dim3 grid_r(HDIM / BN, NROWS / BM);   // (8, 512)

    k_gather<<<NROWS, 128>>>(pair, ep, sid, hc, ps, se, he, soe);
    gemm_tf32<true><<<grid_r, gemm_block>>>(pRIN, rw1, pH1, KR, HDIM);
    k_lngelu_router<<<NROWS, 256>>>(rb1, rlg, rlb);
    k_router2<<<NROWS, 128>>>(ep, rw2, rb2, proto, outC, outW);
    gemm_tf32<false><<<grid_r, gemm_block>>>(pFEATS, muw1, pHMU, KF, HDIM);
    gemm_tf32<false><<<grid_r, gemm_block>>>(pFEATS, mgw1, pHMG, KF, HDIM);
    k_act<<<NROWS, 256>>>(mub1, mulg, mulb, mgb1);
    gemm_tf32<false><<<grid_r, gemm_block>>>(pHMU, muw2, pDELTA, HDIM, HDIM);
    gemm_tf32<false><<<grid_r, gemm_block>>>(pHMG, mgw2, pGATE, HDIM, HDIM);
    k_final<<<NROWS, 256>>>(ep, mub2, mgb2, ng, nb, outU);
}

// round 3
// speedup vs baseline: 1.5158x; 1.5158x over previous
#include <cuda_runtime.h>
#include <cuda_bf16.h>
#include <mma.h>
#include <math.h>

using namespace nvcuda;

// ---------------- problem constants ----------------
#define NROWS 65536
#define HDIM  512
#define MD    128
#define PROTO 12
#define KR    1408   // 2H + 3*MD
#define KF    2048   // 4H
#define RSCALE 0.2f

typedef __nv_bfloat16 bf16;

// ---------------- scratch (device globals; allocation-free) ----------------
__device__ __align__(16) float g_RIN  [(size_t)NROWS * KR];     // router input fp32
__device__ __align__(16) float g_H1   [(size_t)NROWS * HDIM];   // router hidden fp32
__device__ __align__(16) bf16  g_FEATSH[(size_t)NROWS * KF];    // feats bf16
__device__ __align__(16) float g_H12  [(size_t)NROWS * 1024];   // [hmu | hmg] fp32
__device__ __align__(16) bf16  g_HMUH [(size_t)NROWS * HDIM];   // act(hmu) bf16
__device__ __align__(16) bf16  g_HMGH [(size_t)NROWS * HDIM];   // act(hmg) bf16
__device__ __align__(16) float g_DELTA[(size_t)NROWS * HDIM];
__device__ __align__(16) float g_GATE [(size_t)NROWS * HDIM];
// converted weights
__device__ __align__(16) bf16  g_W1   [(size_t)KF * 1024];      // [muw1 | mgw1] bf16
__device__ __align__(16) bf16  g_W2MU [(size_t)HDIM * HDIM];
__device__ __align__(16) bf16  g_W2MG [(size_t)HDIM * HDIM];
__device__ __align__(16) float g_W2T  [(size_t)PROTO * HDIM];   // router_w2 transposed

// ---------------- helpers ----------------
__device__ __forceinline__ float gelu_exact(float x) {
    return 0.5f * x * (1.0f + erff(x * 0.70710678118654752440f));
}

__device__ __forceinline__ float block_sum_256(float v, float* sbuf) {
    #pragma unroll
    for (int o = 16; o; o >>= 1) v += __shfl_xor_sync(0xffffffffu, v, o);
    int w = threadIdx.x >> 5;
    if ((threadIdx.x & 31) == 0) sbuf[w] = v;
    __syncthreads();
    if (threadIdx.x < 32) {
        float s = (threadIdx.x < 8) ? sbuf[threadIdx.x] : 0.0f;
        #pragma unroll
        for (int o = 4; o; o >>= 1) s += __shfl_xor_sync(0xffffffffu, s, o);
        if (threadIdx.x == 0) sbuf[0] = s;
    }
    __syncthreads();
    float r = sbuf[0];
    __syncthreads();
    return r;
}

__device__ __forceinline__ double block_sum_256d(double v, double* sbuf) {
    #pragma unroll
    for (int o = 16; o; o >>= 1) v += __shfl_xor_sync(0xffffffffu, v, o);
    int w = threadIdx.x >> 5;
    if ((threadIdx.x & 31) == 0) sbuf[w] = v;
    __syncthreads();
    if (threadIdx.x < 32) {
        double s = (threadIdx.x < 8) ? sbuf[threadIdx.x] : 0.0;
        #pragma unroll
        for (int o = 4; o; o >>= 1) s += __shfl_xor_sync(0xffffffffu, s, o);
        if (threadIdx.x == 0) sbuf[0] = s;
    }
    __syncthreads();
    double r = sbuf[0];
    __syncthreads();
    return r;
}

__device__ __forceinline__ void twosum_acc(float& sum, float& comp, float v) {
    float s = sum + v;
    float z = s - sum;
    float e = (sum - (s - z)) + (v - z);
    sum = s;
    comp += e;
}

// ---------------- kernel 0: weight prep (bf16 conversion + w2 transpose) -------
__global__ void k_prep(const float* __restrict__ muw1, const float* __restrict__ mgw1,
                       const float* __restrict__ muw2, const float* __restrict__ mgw2,
                       const float* __restrict__ rw2) {
    int i = blockIdx.x * 256 + threadIdx.x;
    if (i < KF * HDIM) {
        int r = i / HDIM, c = i % HDIM;
        g_W1[(size_t)r * 1024 + c]       = __float2bfloat16_rn(muw1[i]);
        g_W1[(size_t)r * 1024 + 512 + c] = __float2bfloat16_rn(mgw1[i]);
    }
    if (i < HDIM * HDIM) {
        g_W2MU[i] = __float2bfloat16_rn(muw2[i]);
        g_W2MG[i] = __float2bfloat16_rn(mgw2[i]);
    }
    if (i < HDIM * PROTO) {
        int c = i / PROTO, l = i % PROTO;
        g_W2T[l * HDIM + c] = rw2[i];
    }
}

// ---------------- kernel 1: gather router input [N,1408] (float4) -------------
__global__ void k_gather(const float* __restrict__ pair, const float* __restrict__ ep,
                         const int* __restrict__ sid, const int* __restrict__ hc,
                         const int* __restrict__ ps,
                         const float* __restrict__ se, const float* __restrict__ he,
                         const float* __restrict__ soe) {
    int row = blockIdx.x;
    int s = min(max(sid[row], 0), 2048);
    int h = min(max(hc[row], 0), 9);
    int p = min(max(ps[row], 0), 7);
    float4* dst = reinterpret_cast<float4*>(&g_RIN[(size_t)row * KR]);
    const float4* pr  = reinterpret_cast<const float4*>(&pair[(size_t)row * HDIM]);
    const float4* er  = reinterpret_cast<const float4*>(&ep[(size_t)row * HDIM]);
    const float4* sev = reinterpret_cast<const float4*>(&se[s * MD]);
    const float4* hev = reinterpret_cast<const float4*>(&he[h * MD]);
    const float4* sov = reinterpret_cast<const float4*>(&soe[p * MD]);
    for (int v = threadIdx.x; v < KR / 4; v += blockDim.x) {
        float4 f;
        if      (v < 128) f = pr[v];
        else if (v < 256) f = er[v - 128];
        else if (v < 288) f = sev[v - 256];
        else if (v < 320) f = hev[v - 288];
        else              f = sov[v - 320];
        dst[v] = f;
    }
}

// ---------------- router GEMM: exact fp32 via 4-term tf32 split ----------------
// C[M,512] = A[M,1408] @ B[1408,512]; BM=128, BN=64, BK=32, double-buffered.
#define RBM 128
#define RBN 64
#define RBK 32
#define R_AS 4608   // 128*36 floats per A buffer
#define R_BS 2176   // 32*68 floats per B buffer
#define R_BUF (R_AS + R_BS)

__global__ void __launch_bounds__(256) gemm_router(const float* __restrict__ A,
                                                   const float* __restrict__ B,
                                                   float* __restrict__ C,
                                                   int K, int NC) {
    extern __shared__ float dyn[];
    const int m0 = blockIdx.y * RBM;
    const int n0 = blockIdx.x * RBN;
    const int tid  = threadIdx.x;
    const int warp = tid >> 5;
    const int wr   = warp >> 1;   // 0..3
    const int wc   = warp & 1;    // 0..1

    wmma::fragment<wmma::accumulator, 16, 16, 8, float> cacc[2][2];
    float sum[2][2][8], comp[2][2][8];
    #pragma unroll
    for (int i = 0; i < 2; i++)
        #pragma unroll
        for (int j = 0; j < 2; j++) {
            wmma::fill_fragment(cacc[i][j], 0.0f);
            #pragma unroll
            for (int t = 0; t < 8; t++) { sum[i][j][t] = 0.0f; comp[i][j][t] = 0.0f; }
        }

    // preload first tile into buffer 0
    {
        float* As = dyn;
        float* Bs = dyn + R_AS;
        #pragma unroll
        for (int r = 0; r < 4; r++) {
            int idx = tid + r * 256;
            int row = idx >> 3, c4 = (idx & 7) << 2;
            float4 v = *reinterpret_cast<const float4*>(&A[(size_t)(m0 + row) * K + c4]);
            *reinterpret_cast<float4*>(&As[row * 36 + c4]) = v;
        }
        #pragma unroll
        for (int r = 0; r < 2; r++) {
            int idx = tid + r * 256;
            int row = idx >> 4, c4 = (idx & 15) << 2;
            float4 v = *reinterpret_cast<const float4*>(&B[(size_t)row * NC + n0 + c4]);
            *reinterpret_cast<float4*>(&Bs[row * 68 + c4]) = v;
        }
    }
    __syncthreads();

    int cur = 0;
    for (int kt = 0; kt < K; kt += RBK) {
        float4 pa[4], pb[2];
        const bool has_next = (kt + RBK) < K;
        if (has_next) {
            int nkt = kt + RBK;
            #pragma unroll
            for (int r = 0; r < 4; r++) {
                int idx = tid + r * 256;
                int row = idx >> 3, c4 = (idx & 7) << 2;
                pa[r] = *reinterpret_cast<const float4*>(&A[(size_t)(m0 + row) * K + nkt + c4]);
            }
            #pragma unroll
            for (int r = 0; r < 2; r++) {
                int idx = tid + r * 256;
                int row = idx >> 4, c4 = (idx & 15) << 2;
                pb[r] = *reinterpret_cast<const float4*>(&B[(size_t)(nkt + row) * NC + n0 + c4]);
            }
        }

        const float* As = dyn + cur * R_BUF;
        const float* Bs = dyn + cur * R_BUF + R_AS;
        #pragma unroll
        for (int ks = 0; ks < RBK; ks += 8) {
            wmma::fragment<wmma::matrix_a, 16, 16, 8, wmma::precision::tf32, wmma::row_major> af[2], afl[2];
            wmma::fragment<wmma::matrix_b, 16, 16, 8, wmma::precision::tf32, wmma::row_major> bf[2], bfl[2];
            #pragma unroll
            for (int i = 0; i < 2; i++) {
                wmma::load_matrix_sync(af[i], &As[(wr * 32 + i * 16) * 36 + ks], 36);
                #pragma unroll
                for (int t = 0; t < af[i].num_elements; t++) {
                    float v  = af[i].x[t];
                    float hi = wmma::__float_to_tf32(v);
                    af[i].x[t]  = hi;
                    afl[i].x[t] = wmma::__float_to_tf32(v - hi);
                }
            }
            #pragma unroll
            for (int j = 0; j < 2; j++) {
                wmma::load_matrix_sync(bf[j], &Bs[ks * 68 + wc * 32 + j * 16], 68);
                #pragma unroll
                for (int t = 0; t < bf[j].num_elements; t++) {
                    float v  = bf[j].x[t];
                    float hi = wmma::__float_to_tf32(v);
                    bf[j].x[t]  = hi;
                    bfl[j].x[t] = wmma::__float_to_tf32(v - hi);
                }
            }
            #pragma unroll
            for (int i = 0; i < 2; i++)
                #pragma unroll
                for (int j = 0; j < 2; j++) {
                    wmma::mma_sync(cacc[i][j], afl[i], bfl[j], cacc[i][j]);
                    wmma::mma_sync(cacc[i][j], af[i],  bfl[j], cacc[i][j]);
                    wmma::mma_sync(cacc[i][j], afl[i], bf[j],  cacc[i][j]);
                    wmma::mma_sync(cacc[i][j], af[i],  bf[j],  cacc[i][j]);
                }
        }
        // merge chunk into compensated running sums
        #pragma unroll
        for (int i = 0; i < 2; i++)
            #pragma unroll
            for (int j = 0; j < 2; j++)
                #pragma unroll
                for (int t = 0; t < 8; t++) {
                    twosum_acc(sum[i][j][t], comp[i][j][t], cacc[i][j].x[t]);
                    cacc[i][j].x[t] = 0.0f;
                }

        if (has_next) {
            float* Asn = dyn + (cur ^ 1) * R_BUF;
            float* Bsn = dyn + (cur ^ 1) * R_BUF + R_AS;
            #pragma unroll
            for (int r = 0; r < 4; r++) {
                int idx = tid + r * 256;
                int row = idx >> 3, c4 = (idx & 7) << 2;
                *reinterpret_cast<float4*>(&Asn[row * 36 + c4]) = pa[r];
            }
            #pragma unroll
            for (int r = 0; r < 2; r++) {
                int idx = tid + r * 256;
                int row = idx >> 4, c4 = (idx & 15) << 2;
                *reinterpret_cast<float4*>(&Bsn[row * 68 + c4]) = pb[r];
            }
        }
        __syncthreads();
        cur ^= 1;
    }

    #pragma unroll
    for (int i = 0; i < 2; i++)
        #pragma unroll
        for (int j = 0; j < 2; j++) {
            #pragma unroll
            for (int t = 0; t < 8; t++)
                cacc[i][j].x[t] = sum[i][j][t] + comp[i][j][t];
            float* Cp = C + (size_t)(m0 + wr * 32 + i * 16) * NC + n0 + wc * 32 + j * 16;
            wmma::store_matrix_sync(Cp, cacc[i][j], NC, wmma::mem_row_major);
        }
}

// ---------------- bf16 GEMM: C[M,NC] = A[M,K] @ B[K,NC] -----------------------
// BM=128, BN=128, BK=32; 8 warps (4x2), each warp 32x64 (2x4 m16n16k16 frags);
// double-buffered smem with register prefetch.
#define HBM 128
#define HBN 128
#define HBK 32

__global__ void __launch_bounds__(256) gemm_bf16(const bf16* __restrict__ A,
                                                 const bf16* __restrict__ B,
                                                 float* __restrict__ C,
                                                 int K, int NC) {
    __shared__ bf16 As[2][HBM][HBK + 8];    // stride 40
    __shared__ bf16 Bs[2][HBK][HBN + 8];    // stride 136
    const int m0 = blockIdx.y * HBM;
    const int n0 = blockIdx.x * HBN;
    const int tid  = threadIdx.x;
    const int warp = tid >> 5;
    const int wr   = warp >> 1;   // 0..3 -> 32 rows each
    const int wc   = warp & 1;    // 0..1 -> 64 cols each

    wmma::fragment<wmma::accumulator, 16, 16, 16, float> acc[2][4];
    #pragma unroll
    for (int i = 0; i < 2; i++)
        #pragma unroll
        for (int j = 0; j < 4; j++) wmma::fill_fragment(acc[i][j], 0.0f);

    // preload tile 0
    #pragma unroll
    for (int r = 0; r < 2; r++) {
        int idx = tid + r * 256;
        int row = idx >> 2, c8 = (idx & 3) << 3;
        float4 v = *reinterpret_cast<const float4*>(&A[(size_t)(m0 + row) * K + c8]);
        *reinterpret_cast<float4*>(&As[0][row][c8]) = v;
    }
    #pragma unroll
    for (int r = 0; r < 2; r++) {
        int idx = tid + r * 256;
        int row = idx >> 4, c8 = (idx & 15) << 3;
        float4 v = *reinterpret_cast<const float4*>(&B[(size_t)row * NC + n0 + c8]);
        *reinterpret_cast<float4*>(&Bs[0][row][c8]) = v;
    }
    __syncthreads();

    int cur = 0;
    for (int kt = 0; kt < K; kt += HBK) {
        float4 pa[2], pb[2];
        const bool has_next = (kt + HBK) < K;
        if (has_next) {
            int nkt = kt + HBK;
            #pragma unroll
            for (int r = 0; r < 2; r++) {
                int idx = tid + r * 256;
                int row = idx >> 2, c8 = (idx & 3) << 3;
                pa[r] = *reinterpret_cast<const float4*>(&A[(size_t)(m0 + row) * K + nkt + c8]);
            }
            #pragma unroll
            for (int r = 0; r < 2; r++) {
                int idx = tid + r * 256;
                int row = idx >> 4, c8 = (idx & 15) << 3;
                pb[r] = *reinterpret_cast<const float4*>(&B[(size_t)(nkt + row) * NC + n0 + c8]);
            }
        }

        #pragma unroll
        for (int ks = 0; ks < HBK; ks += 16) {
            wmma::fragment<wmma::matrix_a, 16, 16, 16, bf16, wmma::row_major> af[2];
            wmma::fragment<wmma::matrix_b, 16, 16, 16, bf16, wmma::row_major> bfr[4];
            #pragma unroll
            for (int i = 0; i < 2; i++)
                wmma::load_matrix_sync(af[i], &As[cur][wr * 32 + i * 16][ks], HBK + 8);
            #pragma unroll
            for (int j = 0; j < 4; j++)
                wmma::load_matrix_sync(bfr[j], &Bs[cur][ks][wc * 64 + j * 16], HBN + 8);
            #pragma unroll
            for (int i = 0; i < 2; i++)
                #pragma unroll
                for (int j = 0; j < 4; j++)
                    wmma::mma_sync(acc[i][j], af[i], bfr[j], acc[i][j]);
        }

        if (has_next) {
            #pragma unroll
            for (int r = 0; r < 2; r++) {
                int idx = tid + r * 256;
                int row = idx >> 2, c8 = (idx & 3) << 3;
                *reinterpret_cast<float4*>(&As[cur ^ 1][row][c8]) = pa[r];
            }
            #pragma unroll
            for (int r = 0; r < 2; r++) {
                int idx = tid + r * 256;
                int row = idx >> 4, c8 = (idx & 15) << 3;
                *reinterpret_cast<float4*>(&Bs[cur ^ 1][row][c8]) = pb[r];
            }
        }
        __syncthreads();
        cur ^= 1;
    }

    #pragma unroll
    for (int i = 0; i < 2; i++)
        #pragma unroll
        for (int j = 0; j < 4; j++) {
            float* Cp = C + (size_t)(m0 + wr * 32 + i * 16) * NC + n0 + wc * 64 + j * 16;
            wmma::store_matrix_sync(Cp, acc[i][j], NC, wmma::mem_row_major);
        }
}

// ---------------- kernel 3: router LN + GELU (fp64 reductions, in-place) ------
__global__ void k_lngelu_router(const float* __restrict__ b, const float* __restrict__ g,
                                const float* __restrict__ beta) {
    __shared__ double sbuf[8];
    int row = blockIdx.x, t = threadIdx.x;
    float* x = &g_H1[(size_t)row * HDIM];
    float x0 = x[t] + b[t];
    float x1 = x[t + 256] + b[t + 256];
    double mean = block_sum_256d((double)x0 + (double)x1, sbuf) * (1.0 / 512.0);
    double e0 = (double)x0 - mean, e1 = (double)x1 - mean;
    double var = block_sum_256d(e0 * e0 + e1 * e1, sbuf) * (1.0 / 512.0);
    float rs = (float)(1.0 / sqrt(var + 1e-5));
    float d0 = (float)e0, d1 = (float)e1;
    x[t]       = gelu_exact(d0 * rs * g[t] + beta[t]);
    x[t + 256] = gelu_exact(d1 * rs * g[t + 256] + beta[t + 256]);
}

// ---------------- kernel 4: logits (compensated), softmax, top-4, ctx, feats ----
__global__ void k_router2(const float* __restrict__ ep,
                          const float* __restrict__ b2,
                          const float* __restrict__ proto,
                          float* __restrict__ outC, float* __restrict__ outW) {
    __shared__ float sh[HDIM];
    __shared__ float sl[PROTO];
    __shared__ float sw[PROTO];
    int row = blockIdx.x, t = threadIdx.x;    // 128 threads
    const float* hrow = &g_H1[(size_t)row * HDIM];
    for (int c = t; c < HDIM; c += 128) sh[c] = hrow[c];
    __syncthreads();
    int warp = t >> 5, lane = t & 31;
    for (int l = warp; l < PROTO; l += 4) {
        float s = 0.0f, cmp = 0.0f;
        const float* wl = &g_W2T[l * HDIM];
        for (int c = lane; c < HDIM; c += 32) {
            float a = sh[c], w = wl[c];
            float p  = a * w;
            float pe = fmaf(a, w, -p);
            twosum_acc(s, cmp, p);
            cmp += pe;
        }
        #pragma unroll
        for (int o = 16; o; o >>= 1) {
            s   += __shfl_xor_sync(0xffffffffu, s, o);
            cmp += __shfl_xor_sync(0xffffffffu, cmp, o);
        }
        if (lane == 0) sl[l] = (s + cmp) + b2[l];
    }
    __syncthreads();
    if (t == 0) {
        float w[PROTO];
        float mx = -1e30f;
        #pragma unroll
        for (int i = 0; i < PROTO; i++) mx = fmaxf(mx, sl[i]);
        float ssum = 0.0f;
        #pragma unroll
        for (int i = 0; i < PROTO; i++) { w[i] = expf(sl[i] - mx); ssum += w[i]; }
        float inv = 1.0f / ssum;
        #pragma unroll
        for (int i = 0; i < PROTO; i++) w[i] *= inv;
        bool sel[PROTO];
        #pragma unroll
        for (int i = 0; i < PROTO; i++) sel[i] = false;
        for (int k = 0; k < 4; k++) {
            int bi = -1; float bv = -1e30f;
            #pragma unroll
            for (int i = 0; i < PROTO; i++)
                if (!sel[i] && w[i] > bv) { bv = w[i]; bi = i; }
            sel[bi] = true;
        }
        float s2 = 0.0f;
        #pragma unroll
        for (int i = 0; i < PROTO; i++) { float v = sel[i] ? w[i] : 0.0f; sw[i] = v; s2 += v; }
        float d = 1.0f / fmaxf(s2, 1e-6f);
        #pragma unroll
        for (int i = 0; i < PROTO; i++) sw[i] *= d;
    }
    __syncthreads();
    if (t < PROTO) outW[(size_t)row * PROTO + t] = sw[t];
    const float* eprow = &ep[(size_t)row * HDIM];
    bf16* frow = &g_FEATSH[(size_t)row * KF];
    for (int j = t; j < HDIM; j += 128) {
        float c = 0.0f;
        #pragma unroll
        for (int p = 0; p < PROTO; p++) c += sw[p] * proto[p * HDIM + j];
        float e = eprow[j];
        outC[(size_t)row * HDIM + j] = c;
        frow[j]          = __float2bfloat16_rn(e);
        frow[512  + j]   = __float2bfloat16_rn(c);
        frow[1024 + j]   = __float2bfloat16_rn(fabsf(e - c));
        frow[1536 + j]   = __float2bfloat16_rn(e * c);
    }
}

// ---------------- kernel 7: activations -> bf16 hidden --------------------------
__global__ void k_act(const float* __restrict__ b_mu, const float* __restrict__ g_mu,
                      const float* __restrict__ be_mu, const float* __restrict__ b_mg) {
    __shared__ float sbuf[8];
    int row = blockIdx.x, t = threadIdx.x;
    const float* h12 = &g_H12[(size_t)row * 1024];
    float m0 = h12[t] + b_mu[t];
    float m1 = h12[t + 256] + b_mu[t + 256];
    float mean = block_sum_256(m0 + m1, sbuf) * (1.0f / 512.0f);
    float d0 = m0 - mean, d1 = m1 - mean;
    float var = block_sum_256(d0 * d0 + d1 * d1, sbuf) * (1.0f / 512.0f);
    float rs = rsqrtf(var + 1e-5f);
    bf16* xm = &g_HMUH[(size_t)row * HDIM];
    bf16* xg = &g_HMGH[(size_t)row * HDIM];
    xm[t]       = __float2bfloat16_rn(gelu_exact(d0 * rs * g_mu[t] + be_mu[t]));
    xm[t + 256] = __float2bfloat16_rn(gelu_exact(d1 * rs * g_mu[t + 256] + be_mu[t + 256]));
    float gg0 = h12[512 + t] + b_mg[t];
    float gg1 = h12[512 + t + 256] + b_mg[t + 256];
    xg[t]       = __float2bfloat16_rn(gelu_exact(gg0));
    xg[t + 256] = __float2bfloat16_rn(gelu_exact(gg1));
}

// ---------------- kernel 10: gate, residual, final LN -> updated ----------------
__global__ void k_final(const float* __restrict__ ep, const float* __restrict__ mub2,
                        const float* __restrict__ mgb2, const float* __restrict__ ng,
                        const float* __restrict__ nb, float* __restrict__ outU) {
    __shared__ float sbuf[8];
    int row = blockIdx.x, t = threadIdx.x;
    const float* e  = &ep[(size_t)row * HDIM];
    const float* d  = &g_DELTA[(size_t)row * HDIM];
    const float* gp = &g_GATE[(size_t)row * HDIM];
    float u[2];
    #pragma unroll
    for (int r = 0; r < 2; r++) {
        int c = t + r * 256;
        float delta = d[c] + mub2[c];
        float gg    = gp[c] + mgb2[c];
        float gate  = 1.0f / (1.0f + expf(-gg));
        u[r] = e[c] + RSCALE * gate * delta;
    }
    float mean = block_sum_256(u[0] + u[1], sbuf) * (1.0f / 512.0f);
    float d0 = u[0] - mean, d1 = u[1] - mean;
    float var = block_sum_256(d0 * d0 + d1 * d1, sbuf) * (1.0f / 512.0f);
    float rs = rsqrtf(var + 1e-5f);
    outU[(size_t)row * HDIM + t]       = d0 * rs * ng[t] + nb[t];
    outU[(size_t)row * HDIM + t + 256] = d1 * rs * ng[t + 256] + nb[t + 256];
}

// ---------------- launch ----------------
extern "C" void kernel_launch(void* const* d_in, const int* in_sizes, int n_in,
                              void* d_out, int out_size) {
    const float* pair = (const float*)d_in[0];
    const float* ep   = (const float*)d_in[1];
    const int*   sid  = (const int*)d_in[2];
    const int*   hc   = (const int*)d_in[3];
    const int*   ps   = (const int*)d_in[4];
    const float* se   = (const float*)d_in[5];
    const float* he   = (const float*)d_in[6];
    const float* soe  = (const float*)d_in[7];
    const float* proto= (const float*)d_in[8];
    const float* rw1  = (const float*)d_in[9];
    const float* rb1  = (const float*)d_in[10];
    const float* rlg  = (const float*)d_in[11];
    const float* rlb  = (const float*)d_in[12];
    const float* rw2  = (const float*)d_in[13];
    const float* rb2  = (const float*)d_in[14];
    const float* muw1 = (const float*)d_in[15];
    const float* mub1 = (const float*)d_in[16];
    const float* mulg = (const float*)d_in[17];
    const float* mulb = (const float*)d_in[18];
    const float* muw2 = (const float*)d_in[19];
    const float* mub2 = (const float*)d_in[20];
    const float* mgw1 = (const float*)d_in[21];
    const float* mgb1 = (const float*)d_in[22];
    const float* mgw2 = (const float*)d_in[23];
    const float* mgb2 = (const float*)d_in[24];
    const float* ng   = (const float*)d_in[25];
    const float* nb   = (const float*)d_in[26];

    float* outU = (float*)d_out;
    float* outC = outU + (size_t)NROWS * HDIM;
    float* outW = outC + (size_t)NROWS * HDIM;

    float *pRIN, *pH1, *pH12, *pDELTA, *pGATE;
    bf16 *pFEATSH, *pHMUH, *pHMGH, *pW1, *pW2MU, *pW2MG;
    cudaGetSymbolAddress((void**)&pRIN,    g_RIN);
    cudaGetSymbolAddress((void**)&pH1,     g_H1);
    cudaGetSymbolAddress((void**)&pH12,    g_H12);
    cudaGetSymbolAddress((void**)&pDELTA,  g_DELTA);
    cudaGetSymbolAddress((void**)&pGATE,   g_GATE);
    cudaGetSymbolAddress((void**)&pFEATSH, g_FEATSH);
    cudaGetSymbolAddress((void**)&pHMUH,   g_HMUH);
    cudaGetSymbolAddress((void**)&pHMGH,   g_HMGH);
    cudaGetSymbolAddress((void**)&pW1,     g_W1);
    cudaGetSymbolAddress((void**)&pW2MU,   g_W2MU);
    cudaGetSymbolAddress((void**)&pW2MG,   g_W2MG);

    static bool attr_set = false;
    if (!attr_set) {
        cudaFuncSetAttribute(gemm_router, cudaFuncAttributeMaxDynamicSharedMemorySize,
                             2 * R_BUF * (int)sizeof(float));
        attr_set = true;
    }

    // 0. weight prep (bf16 conversion + router w2 transpose)
    k_prep<<<(KF * HDIM + 255) / 256, 256>>>(muw1, mgw1, muw2, mgw2, rw2);
    // 1. gather router input
    k_gather<<<NROWS, 128>>>(pair, ep, sid, hc, ps, se, he, soe);
    // 2. router GEMM (exact fp32 via 4-term tf32 split + compensation)
    {
        dim3 grid(HDIM / RBN, NROWS / RBM);   // (8, 512)
        gemm_router<<<grid, 256, 2 * R_BUF * sizeof(float)>>>(pRIN, rw1, pH1, KR, HDIM);
    }
    // 3. LN + GELU
    k_lngelu_router<<<NROWS, 256>>>(rb1, rlg, rlb);
    // 4. logits/softmax/top4/ctx/feats(bf16)
    k_router2<<<NROWS, 128>>>(ep, rb2, proto, outC, outW);
    // 5. fused mu+mg layer-1 GEMM: [N,2048] x [2048,1024] -> H12
    {
        dim3 grid(1024 / HBN, NROWS / HBM);   // (8, 512)
        gemm_bf16<<<grid, 256>>>(pFEATSH, pW1, pH12, KF, 1024);
    }
    // 6. activations -> bf16
    k_act<<<NROWS, 256>>>(mub1, mulg, mulb, mgb1);
    // 7/8. layer-2 GEMMs
    {
        dim3 grid(HDIM / HBN, NROWS / HBM);   // (4, 512)
        gemm_bf16<<<grid, 256>>>(pHMUH, pW2MU, pDELTA, HDIM, HDIM);
        gemm_bf16<<<grid, 256>>>(pHMGH, pW2MG, pGATE, HDIM, HDIM);
    }
    // 9. gate + residual + final LN
    k_final<<<NROWS, 256>>>(ep, mub2, mgb2, ng, nb, outU);
}

// round 4
// speedup vs baseline: 1.5228x; 1.0046x over previous
#include <cuda_runtime.h>
#include <cuda_bf16.h>
#include <mma.h>
#include <math.h>

using namespace nvcuda;

// ---------------- problem constants ----------------
#define NROWS 65536
#define HDIM  512
#define MD    128
#define PROTO 12
#define KR    1408   // 2H + 3*MD
#define KF    2048   // 4H
#define RSCALE 0.2f

typedef __nv_bfloat16 bf16;

// ---------------- scratch (device globals; allocation-free) ----------------
__device__ __align__(16) float g_RIN  [(size_t)NROWS * KR];     // router input fp32
__device__ __align__(16) float g_H1   [(size_t)NROWS * HDIM];   // router hidden fp32
__device__ __align__(16) bf16  g_FEATSH[(size_t)NROWS * KF];    // feats bf16
__device__ __align__(16) float g_H12  [(size_t)NROWS * 1024];   // [hmu | hmg] fp32
__device__ __align__(16) bf16  g_HMUH [(size_t)NROWS * HDIM];   // act(hmu) bf16
__device__ __align__(16) bf16  g_HMGH [(size_t)NROWS * HDIM];   // act(hmg) bf16
__device__ __align__(16) float g_DELTA[(size_t)NROWS * HDIM];
__device__ __align__(16) float g_GATE [(size_t)NROWS * HDIM];
// converted weights
__device__ __align__(16) bf16  g_W1   [(size_t)KF * 1024];      // [muw1 | mgw1] bf16
__device__ __align__(16) bf16  g_W2MU [(size_t)HDIM * HDIM];
__device__ __align__(16) bf16  g_W2MG [(size_t)HDIM * HDIM];
__device__ __align__(16) float g_W2T  [(size_t)PROTO * HDIM];   // router_w2 transposed

// ---------------- helpers ----------------
__device__ __forceinline__ float gelu_exact(float x) {
    return 0.5f * x * (1.0f + erff(x * 0.70710678118654752440f));
}

__device__ __forceinline__ float block_sum_256(float v, float* sbuf) {
    #pragma unroll
    for (int o = 16; o; o >>= 1) v += __shfl_xor_sync(0xffffffffu, v, o);
    int w = threadIdx.x >> 5;
    if ((threadIdx.x & 31) == 0) sbuf[w] = v;
    __syncthreads();
    if (threadIdx.x < 32) {
        float s = (threadIdx.x < 8) ? sbuf[threadIdx.x] : 0.0f;
        #pragma unroll
        for (int o = 4; o; o >>= 1) s += __shfl_xor_sync(0xffffffffu, s, o);
        if (threadIdx.x == 0) sbuf[0] = s;
    }
    __syncthreads();
    float r = sbuf[0];
    __syncthreads();
    return r;
}

__device__ __forceinline__ double block_sum_256d(double v, double* sbuf) {
    #pragma unroll
    for (int o = 16; o; o >>= 1) v += __shfl_xor_sync(0xffffffffu, v, o);
    int w = threadIdx.x >> 5;
    if ((threadIdx.x & 31) == 0) sbuf[w] = v;
    __syncthreads();
    if (threadIdx.x < 32) {
        double s = (threadIdx.x < 8) ? sbuf[threadIdx.x] : 0.0;
        #pragma unroll
        for (int o = 4; o; o >>= 1) s += __shfl_xor_sync(0xffffffffu, s, o);
        if (threadIdx.x == 0) sbuf[0] = s;
    }
    __syncthreads();
    double r = sbuf[0];
    __syncthreads();
    return r;
}

__device__ __forceinline__ void twosum_acc(float& sum, float& comp, float v) {
    float s = sum + v;
    float z = s - sum;
    float e = (sum - (s - z)) + (v - z);
    sum = s;
    comp += e;
}

// ---------------- kernel 0: weight prep (bf16 conversion + w2 transpose) -------
__global__ void k_prep(const float* __restrict__ muw1, const float* __restrict__ mgw1,
                       const float* __restrict__ muw2, const float* __restrict__ mgw2,
                       const float* __restrict__ rw2) {
    int i = blockIdx.x * 256 + threadIdx.x;
    if (i < KF * HDIM) {
        int r = i / HDIM, c = i % HDIM;
        g_W1[(size_t)r * 1024 + c]       = __float2bfloat16_rn(muw1[i]);
        g_W1[(size_t)r * 1024 + 512 + c] = __float2bfloat16_rn(mgw1[i]);
    }
    if (i < HDIM * HDIM) {
        g_W2MU[i] = __float2bfloat16_rn(muw2[i]);
        g_W2MG[i] = __float2bfloat16_rn(mgw2[i]);
    }
    if (i < HDIM * PROTO) {
        int c = i / PROTO, l = i % PROTO;
        g_W2T[l * HDIM + c] = rw2[i];
    }
}

// ---------------- kernel 1: gather router input [N,1408] (float4) -------------
__global__ void k_gather(const float* __restrict__ pair, const float* __restrict__ ep,
                         const int* __restrict__ sid, const int* __restrict__ hc,
                         const int* __restrict__ ps,
                         const float* __restrict__ se, const float* __restrict__ he,
                         const float* __restrict__ soe) {
    int row = blockIdx.x;
    int s = min(max(sid[row], 0), 2048);
    int h = min(max(hc[row], 0), 9);
    int p = min(max(ps[row], 0), 7);
    float4* dst = reinterpret_cast<float4*>(&g_RIN[(size_t)row * KR]);
    const float4* pr  = reinterpret_cast<const float4*>(&pair[(size_t)row * HDIM]);
    const float4* er  = reinterpret_cast<const float4*>(&ep[(size_t)row * HDIM]);
    const float4* sev = reinterpret_cast<const float4*>(&se[s * MD]);
    const float4* hev = reinterpret_cast<const float4*>(&he[h * MD]);
    const float4* sov = reinterpret_cast<const float4*>(&soe[p * MD]);
    for (int v = threadIdx.x; v < KR / 4; v += blockDim.x) {
        float4 f;
        if      (v < 128) f = pr[v];
        else if (v < 256) f = er[v - 128];
        else if (v < 288) f = sev[v - 256];
        else if (v < 320) f = hev[v - 288];
        else              f = sov[v - 320];
        dst[v] = f;
    }
}

// ---------------- router GEMM: exact fp32 via 4-term tf32 split ----------------
// C[M,512] = A[M,1408] @ B[1408,512]; BM=128, BN=64, BK=32, double-buffered.
#define RBM 128
#define RBN 64
#define RBK 32
#define R_AS 4608   // 128*36 floats per A buffer
#define R_BS 2176   // 32*68 floats per B buffer
#define R_BUF (R_AS + R_BS)

__global__ void __launch_bounds__(256) gemm_router(const float* __restrict__ A,
                                                   const float* __restrict__ B,
                                                   float* __restrict__ C,
                                                   int K, int NC) {
    extern __shared__ float dyn[];
    const int m0 = blockIdx.y * RBM;
    const int n0 = blockIdx.x * RBN;
    const int tid  = threadIdx.x;
    const int warp = tid >> 5;
    const int wr   = warp >> 1;   // 0..3
    const int wc   = warp & 1;    // 0..1

    wmma::fragment<wmma::accumulator, 16, 16, 8, float> cacc[2][2];
    float sum[2][2][8], comp[2][2][8];
    #pragma unroll
    for (int i = 0; i < 2; i++)
        #pragma unroll
        for (int j = 0; j < 2; j++) {
            wmma::fill_fragment(cacc[i][j], 0.0f);
            #pragma unroll
            for (int t = 0; t < 8; t++) { sum[i][j][t] = 0.0f; comp[i][j][t] = 0.0f; }
        }

    // preload first tile into buffer 0
    {
        float* As = dyn;
        float* Bs = dyn + R_AS;
        #pragma unroll
        for (int r = 0; r < 4; r++) {
            int idx = tid + r * 256;
            int row = idx >> 3, c4 = (idx & 7) << 2;
            float4 v = *reinterpret_cast<const float4*>(&A[(size_t)(m0 + row) * K + c4]);
            *reinterpret_cast<float4*>(&As[row * 36 + c4]) = v;
        }
        #pragma unroll
        for (int r = 0; r < 2; r++) {
            int idx = tid + r * 256;
            int row = idx >> 4, c4 = (idx & 15) << 2;
            float4 v = *reinterpret_cast<const float4*>(&B[(size_t)row * NC + n0 + c4]);
            *reinterpret_cast<float4*>(&Bs[row * 68 + c4]) = v;
        }
    }
    __syncthreads();

    int cur = 0;
    for (int kt = 0; kt < K; kt += RBK) {
        float4 pa[4], pb[2];
        const bool has_next = (kt + RBK) < K;
        if (has_next) {
            int nkt = kt + RBK;
            #pragma unroll
            for (int r = 0; r < 4; r++) {
                int idx = tid + r * 256;
                int row = idx >> 3, c4 = (idx & 7) << 2;
                pa[r] = *reinterpret_cast<const float4*>(&A[(size_t)(m0 + row) * K + nkt + c4]);
            }
            #pragma unroll
            for (int r = 0; r < 2; r++) {
                int idx = tid + r * 256;
                int row = idx >> 4, c4 = (idx & 15) << 2;
                pb[r] = *reinterpret_cast<const float4*>(&B[(size_t)(nkt + row) * NC + n0 + c4]);
            }
        }

        const float* As = dyn + cur * R_BUF;
        const float* Bs = dyn + cur * R_BUF + R_AS;
        #pragma unroll
        for (int ks = 0; ks < RBK; ks += 8) {
            wmma::fragment<wmma::matrix_a, 16, 16, 8, wmma::precision::tf32, wmma::row_major> af[2], afl[2];
            wmma::fragment<wmma::matrix_b, 16, 16, 8, wmma::precision::tf32, wmma::row_major> bf[2], bfl[2];
            #pragma unroll
            for (int i = 0; i < 2; i++) {
                wmma::load_matrix_sync(af[i], &As[(wr * 32 + i * 16) * 36 + ks], 36);
                #pragma unroll
                for (int t = 0; t < af[i].num_elements; t++) {
                    float v  = af[i].x[t];
                    float hi = wmma::__float_to_tf32(v);
                    af[i].x[t]  = hi;
                    afl[i].x[t] = wmma::__float_to_tf32(v - hi);
                }
            }
            #pragma unroll
            for (int j = 0; j < 2; j++) {
                wmma::load_matrix_sync(bf[j], &Bs[ks * 68 + wc * 32 + j * 16], 68);
                #pragma unroll
                for (int t = 0; t < bf[j].num_elements; t++) {
                    float v  = bf[j].x[t];
                    float hi = wmma::__float_to_tf32(v);
                    bf[j].x[t]  = hi;
                    bfl[j].x[t] = wmma::__float_to_tf32(v - hi);
                }
            }
            #pragma unroll
            for (int i = 0; i < 2; i++)
                #pragma unroll
                for (int j = 0; j < 2; j++) {
                    wmma::mma_sync(cacc[i][j], afl[i], bfl[j], cacc[i][j]);
                    wmma::mma_sync(cacc[i][j], af[i],  bfl[j], cacc[i][j]);
                    wmma::mma_sync(cacc[i][j], afl[i], bf[j],  cacc[i][j]);
                    wmma::mma_sync(cacc[i][j], af[i],  bf[j],  cacc[i][j]);
                }
        }
        // merge chunk into compensated running sums
        #pragma unroll
        for (int i = 0; i < 2; i++)
            #pragma unroll
            for (int j = 0; j < 2; j++)
                #pragma unroll
                for (int t = 0; t < 8; t++) {
                    twosum_acc(sum[i][j][t], comp[i][j][t], cacc[i][j].x[t]);
                    cacc[i][j].x[t] = 0.0f;
                }

        if (has_next) {
            float* Asn = dyn + (cur ^ 1) * R_BUF;
            float* Bsn = dyn + (cur ^ 1) * R_BUF + R_AS;
            #pragma unroll
            for (int r = 0; r < 4; r++) {
                int idx = tid + r * 256;
                int row = idx >> 3, c4 = (idx & 7) << 2;
                *reinterpret_cast<float4*>(&Asn[row * 36 + c4]) = pa[r];
            }
            #pragma unroll
            for (int r = 0; r < 2; r++) {
                int idx = tid + r * 256;
                int row = idx >> 4, c4 = (idx & 15) << 2;
                *reinterpret_cast<float4*>(&Bsn[row * 68 + c4]) = pb[r];
            }
        }
        __syncthreads();
        cur ^= 1;
    }

    #pragma unroll
    for (int i = 0; i < 2; i++)
        #pragma unroll
        for (int j = 0; j < 2; j++) {
            #pragma unroll
            for (int t = 0; t < 8; t++)
                cacc[i][j].x[t] = sum[i][j][t] + comp[i][j][t];
            float* Cp = C + (size_t)(m0 + wr * 32 + i * 16) * NC + n0 + wc * 32 + j * 16;
            wmma::store_matrix_sync(Cp, cacc[i][j], NC, wmma::mem_row_major);
        }
}

// ---------------- bf16 GEMM: C[M,NC] = A[M,K] @ B[K,NC] -----------------------
// BM=128, BN=128, BK=32; 8 warps (4x2), each warp 32x64 (2x4 m16n16k16 frags);
// double-buffered smem with register prefetch.
#define HBM 128
#define HBN 128
#define HBK 32

__global__ void __launch_bounds__(256) gemm_bf16(const bf16* __restrict__ A,
                                                 const bf16* __restrict__ B,
                                                 float* __restrict__ C,
                                                 int K, int NC) {
    __shared__ bf16 As[2][HBM][HBK + 8];    // stride 40
    __shared__ bf16 Bs[2][HBK][HBN + 8];    // stride 136
    const int m0 = blockIdx.y * HBM;
    const int n0 = blockIdx.x * HBN;
    const int tid  = threadIdx.x;
    const int warp = tid >> 5;
    const int wr   = warp >> 1;   // 0..3 -> 32 rows each
    const int wc   = warp & 1;    // 0..1 -> 64 cols each

    wmma::fragment<wmma::accumulator, 16, 16, 16, float> acc[2][4];
    #pragma unroll
    for (int i = 0; i < 2; i++)
        #pragma unroll
        for (int j = 0; j < 4; j++) wmma::fill_fragment(acc[i][j], 0.0f);

    // preload tile 0
    #pragma unroll
    for (int r = 0; r < 2; r++) {
        int idx = tid + r * 256;
        int row = idx >> 2, c8 = (idx & 3) << 3;
        float4 v = *reinterpret_cast<const float4*>(&A[(size_t)(m0 + row) * K + c8]);
        *reinterpret_cast<float4*>(&As[0][row][c8]) = v;
    }
    #pragma unroll
    for (int r = 0; r < 2; r++) {
        int idx = tid + r * 256;
        int row = idx >> 4, c8 = (idx & 15) << 3;
        float4 v = *reinterpret_cast<const float4*>(&B[(size_t)row * NC + n0 + c8]);
        *reinterpret_cast<float4*>(&Bs[0][row][c8]) = v;
    }
    __syncthreads();

    int cur = 0;
    for (int kt = 0; kt < K; kt += HBK) {
        float4 pa[2], pb[2];
        const bool has_next = (kt + HBK) < K;
        if (has_next) {
            int nkt = kt + HBK;
            #pragma unroll
            for (int r = 0; r < 2; r++) {
                int idx = tid + r * 256;
                int row = idx >> 2, c8 = (idx & 3) << 3;
                pa[r] = *reinterpret_cast<const float4*>(&A[(size_t)(m0 + row) * K + nkt + c8]);
            }
            #pragma unroll
            for (int r = 0; r < 2; r++) {
                int idx = tid + r * 256;
                int row = idx >> 4, c8 = (idx & 15) << 3;
                pb[r] = *reinterpret_cast<const float4*>(&B[(size_t)(nkt + row) * NC + n0 + c8]);
            }
        }

        #pragma unroll
        for (int ks = 0; ks < HBK; ks += 16) {
            wmma::fragment<wmma::matrix_a, 16, 16, 16, bf16, wmma::row_major> af[2];
            wmma::fragment<wmma::matrix_b, 16, 16, 16, bf16, wmma::row_major> bfr[4];
            #pragma unroll
            for (int i = 0; i < 2; i++)
                wmma::load_matrix_sync(af[i], &As[cur][wr * 32 + i * 16][ks], HBK + 8);
            #pragma unroll
            for (int j = 0; j < 4; j++)
                wmma::load_matrix_sync(bfr[j], &Bs[cur][ks][wc * 64 + j * 16], HBN + 8);
            #pragma unroll
            for (int i = 0; i < 2; i++)
                #pragma unroll
                for (int j = 0; j < 4; j++)
                    wmma::mma_sync(acc[i][j], af[i], bfr[j], acc[i][j]);
        }

        if (has_next) {
            #pragma unroll
            for (int r = 0; r < 2; r++) {
                int idx = tid + r * 256;
                int row = idx >> 2, c8 = (idx & 3) << 3;
                *reinterpret_cast<float4*>(&As[cur ^ 1][row][c8]) = pa[r];
            }
            #pragma unroll
            for (int r = 0; r < 2; r++) {
                int idx = tid + r * 256;
                int row = idx >> 4, c8 = (idx & 15) << 3;
                *reinterpret_cast<float4*>(&Bs[cur ^ 1][row][c8]) = pb[r];
            }
        }
        __syncthreads();
        cur ^= 1;
    }

    #pragma unroll
    for (int i = 0; i < 2; i++)
        #pragma unroll
        for (int j = 0; j < 4; j++) {
            float* Cp = C + (size_t)(m0 + wr * 32 + i * 16) * NC + n0 + wc * 64 + j * 16;
            wmma::store_matrix_sync(Cp, acc[i][j], NC, wmma::mem_row_major);
        }
}

// ---------------- kernel 3: router LN + GELU (fp64 reductions, in-place) ------
__global__ void k_lngelu_router(const float* __restrict__ b, const float* __restrict__ g,
                                const float* __restrict__ beta) {
    __shared__ double sbuf[8];
    int row = blockIdx.x, t = threadIdx.x;
    float* x = &g_H1[(size_t)row * HDIM];
    float x0 = x[t] + b[t];
    float x1 = x[t + 256] + b[t + 256];
    double mean = block_sum_256d((double)x0 + (double)x1, sbuf) * (1.0 / 512.0);
    double e0 = (double)x0 - mean, e1 = (double)x1 - mean;
    double var = block_sum_256d(e0 * e0 + e1 * e1, sbuf) * (1.0 / 512.0);
    float rs = (float)(1.0 / sqrt(var + 1e-5));
    float d0 = (float)e0, d1 = (float)e1;
    x[t]       = gelu_exact(d0 * rs * g[t] + beta[t]);
    x[t + 256] = gelu_exact(d1 * rs * g[t + 256] + beta[t + 256]);
}

// ---------------- kernel 4: logits (compensated), softmax, top-4, ctx, feats ----
__global__ void k_router2(const float* __restrict__ ep,
                          const float* __restrict__ b2,
                          const float* __restrict__ proto,
                          float* __restrict__ outC, float* __restrict__ outW) {
    __shared__ float sh[HDIM];
    __shared__ float sl[PROTO];
    __shared__ float sw[PROTO];
    int row = blockIdx.x, t = threadIdx.x;    // 128 threads
    const float* hrow = &g_H1[(size_t)row * HDIM];
    for (int c = t; c < HDIM; c += 128) sh[c] = hrow[c];
    __syncthreads();
    int warp = t >> 5, lane = t & 31;
    for (int l = warp; l < PROTO; l += 4) {
        float s = 0.0f, cmp = 0.0f;
        const float* wl = &g_W2T[l * HDIM];
        for (int c = lane; c < HDIM; c += 32) {
            float a = sh[c], w = wl[c];
            float p  = a * w;
            float pe = fmaf(a, w, -p);
            twosum_acc(s, cmp, p);
            cmp += pe;
        }
        #pragma unroll
        for (int o = 16; o; o >>= 1) {
            s   += __shfl_xor_sync(0xffffffffu, s, o);
            cmp += __shfl_xor_sync(0xffffffffu, cmp, o);
        }
        if (lane == 0) sl[l] = (s + cmp) + b2[l];
    }
    __syncthreads();
    if (t == 0) {
        float w[PROTO];
        float mx = -1e30f;
        #pragma unroll
        for (int i = 0; i < PROTO; i++) mx = fmaxf(mx, sl[i]);
        float ssum = 0.0f;
        #pragma unroll
        for (int i = 0; i < PROTO; i++) { w[i] = expf(sl[i] - mx); ssum += w[i]; }
        float inv = 1.0f / ssum;
        #pragma unroll
        for (int i = 0; i < PROTO; i++) w[i] *= inv;
        bool sel[PROTO];
        #pragma unroll
        for (int i = 0; i < PROTO; i++) sel[i] = false;
        for (int k = 0; k < 4; k++) {
            int bi = -1; float bv = -1e30f;
            #pragma unroll
            for (int i = 0; i < PROTO; i++)
                if (!sel[i] && w[i] > bv) { bv = w[i]; bi = i; }
            sel[bi] = true;
        }
        float s2 = 0.0f;
        #pragma unroll
        for (int i = 0; i < PROTO; i++) { float v = sel[i] ? w[i] : 0.0f; sw[i] = v; s2 += v; }
        float d = 1.0f / fmaxf(s2, 1e-6f);
        #pragma unroll
        for (int i = 0; i < PROTO; i++) sw[i] *= d;
    }
    __syncthreads();
    if (t < PROTO) outW[(size_t)row * PROTO + t] = sw[t];
    const float* eprow = &ep[(size_t)row * HDIM];
    bf16* frow = &g_FEATSH[(size_t)row * KF];
    for (int j = t; j < HDIM; j += 128) {
        float c = 0.0f;
        #pragma unroll
        for (int p = 0; p < PROTO; p++) c += sw[p] * proto[p * HDIM + j];
        float e = eprow[j];
        outC[(size_t)row * HDIM + j] = c;
        frow[j]          = __float2bfloat16_rn(e);
        frow[512  + j]   = __float2bfloat16_rn(c);
        frow[1024 + j]   = __float2bfloat16_rn(fabsf(e - c));
        frow[1536 + j]   = __float2bfloat16_rn(e * c);
    }
}

// ---------------- kernel 7: activations -> bf16 hidden --------------------------
__global__ void k_act(const float* __restrict__ b_mu, const float* __restrict__ g_mu,
                      const float* __restrict__ be_mu, const float* __restrict__ b_mg) {
    __shared__ float sbuf[8];
    int row = blockIdx.x, t = threadIdx.x;
    const float* h12 = &g_H12[(size_t)row * 1024];
    float m0 = h12[t] + b_mu[t];
    float m1 = h12[t + 256] + b_mu[t + 256];
    float mean = block_sum_256(m0 + m1, sbuf) * (1.0f / 512.0f);
    float d0 = m0 - mean, d1 = m1 - mean;
    float var = block_sum_256(d0 * d0 + d1 * d1, sbuf) * (1.0f / 512.0f);
    float rs = rsqrtf(var + 1e-5f);
    bf16* xm = &g_HMUH[(size_t)row * HDIM];
    bf16* xg = &g_HMGH[(size_t)row * HDIM];
    xm[t]       = __float2bfloat16_rn(gelu_exact(d0 * rs * g_mu[t] + be_mu[t]));
    xm[t + 256] = __float2bfloat16_rn(gelu_exact(d1 * rs * g_mu[t + 256] + be_mu[t + 256]));
    float gg0 = h12[512 + t] + b_mg[t];
    float gg1 = h12[512 + t + 256] + b_mg[t + 256];
    xg[t]       = __float2bfloat16_rn(gelu_exact(gg0));
    xg[t + 256] = __float2bfloat16_rn(gelu_exact(gg1));
}

// ---------------- kernel 10: gate, residual, final LN -> updated ----------------
__global__ void k_final(const float* __restrict__ ep, const float* __restrict__ mub2,
                        const float* __restrict__ mgb2, const float* __restrict__ ng,
                        const float* __restrict__ nb, float* __restrict__ outU) {
    __shared__ float sbuf[8];
    int row = blockIdx.x, t = threadIdx.x;
    const float* e  = &ep[(size_t)row * HDIM];
    const float* d  = &g_DELTA[(size_t)row * HDIM];
    const float* gp = &g_GATE[(size_t)row * HDIM];
    float u[2];
    #pragma unroll
    for (int r = 0; r < 2; r++) {
        int c = t + r * 256;
        float delta = d[c] + mub2[c];
        float gg    = gp[c] + mgb2[c];
        float gate  = 1.0f / (1.0f + expf(-gg));
        u[r] = e[c] + RSCALE * gate * delta;
    }
    float mean = block_sum_256(u[0] + u[1], sbuf) * (1.0f / 512.0f);
    float d0 = u[0] - mean, d1 = u[1] - mean;
    float var = block_sum_256(d0 * d0 + d1 * d1, sbuf) * (1.0f / 512.0f);
    float rs = rsqrtf(var + 1e-5f);
    outU[(size_t)row * HDIM + t]       = d0 * rs * ng[t] + nb[t];
    outU[(size_t)row * HDIM + t + 256] = d1 * rs * ng[t + 256] + nb[t + 256];
}

// ---------------- launch ----------------
extern "C" void kernel_launch(void* const* d_in, const int* in_sizes, int n_in,
                              void* d_out, int out_size) {
    const float* pair = (const float*)d_in[0];
    const float* ep   = (const float*)d_in[1];
    const int*   sid  = (const int*)d_in[2];
    const int*   hc   = (const int*)d_in[3];
    const int*   ps   = (const int*)d_in[4];
    const float* se   = (const float*)d_in[5];
    const float* he   = (const float*)d_in[6];
    const float* soe  = (const float*)d_in[7];
    const float* proto= (const float*)d_in[8];
    const float* rw1  = (const float*)d_in[9];
    const float* rb1  = (const float*)d_in[10];
    const float* rlg  = (const float*)d_in[11];
    const float* rlb  = (const float*)d_in[12];
    const float* rw2  = (const float*)d_in[13];
    const float* rb2  = (const float*)d_in[14];
    const float* muw1 = (const float*)d_in[15];
    const float* mub1 = (const float*)d_in[16];
    const float* mulg = (const float*)d_in[17];
    const float* mulb = (const float*)d_in[18];
    const float* muw2 = (const float*)d_in[19];
    const float* mub2 = (const float*)d_in[20];
    const float* mgw1 = (const float*)d_in[21];
    const float* mgb1 = (const float*)d_in[22];
    const float* mgw2 = (const float*)d_in[23];
    const float* mgb2 = (const float*)d_in[24];
    const float* ng   = (const float*)d_in[25];
    const float* nb   = (const float*)d_in[26];

    float* outU = (float*)d_out;
    float* outC = outU + (size_t)NROWS * HDIM;
    float* outW = outC + (size_t)NROWS * HDIM;

    float *pRIN, *pH1, *pH12, *pDELTA, *pGATE;
    bf16 *pFEATSH, *pHMUH, *pHMGH, *pW1, *pW2MU, *pW2MG;
    cudaGetSymbolAddress((void**)&pRIN,    g_RIN);
    cudaGetSymbolAddress((void**)&pH1,     g_H1);
    cudaGetSymbolAddress((void**)&pH12,    g_H12);
    cudaGetSymbolAddress((void**)&pDELTA,  g_DELTA);
    cudaGetSymbolAddress((void**)&pGATE,   g_GATE);
    cudaGetSymbolAddress((void**)&pFEATSH, g_FEATSH);
    cudaGetSymbolAddress((void**)&pHMUH,   g_HMUH);
    cudaGetSymbolAddress((void**)&pHMGH,   g_HMGH);
    cudaGetSymbolAddress((void**)&pW1,     g_W1);
    cudaGetSymbolAddress((void**)&pW2MU,   g_W2MU);
    cudaGetSymbolAddress((void**)&pW2MG,   g_W2MG);

    static bool attr_set = false;
    if (!attr_set) {
        cudaFuncSetAttribute(gemm_router, cudaFuncAttributeMaxDynamicSharedMemorySize,
                             2 * R_BUF * (int)sizeof(float));
        attr_set = true;
    }

    // 0. weight prep (bf16 conversion + router w2 transpose)
    k_prep<<<(KF * HDIM + 255) / 256, 256>>>(muw1, mgw1, muw2, mgw2, rw2);
    // 1. gather router input
    k_gather<<<NROWS, 128>>>(pair, ep, sid, hc, ps, se, he, soe);
    // 2. router GEMM (exact fp32 via 4-term tf32 split + compensation)
    {
        dim3 grid(HDIM / RBN, NROWS / RBM);   // (8, 512)
        gemm_router<<<grid, 256, 2 * R_BUF * sizeof(float)>>>(pRIN, rw1, pH1, KR, HDIM);
    }
    // 3. LN + GELU
    k_lngelu_router<<<NROWS, 256>>>(rb1, rlg, rlb);
    // 4. logits/softmax/top4/ctx/feats(bf16)
    k_router2<<<NROWS, 128>>>(ep, rb2, proto, outC, outW);
    // 5. fused mu+mg layer-1 GEMM: [N,2048] x [2048,1024] -> H12
    {
        dim3 grid(1024 / HBN, NROWS / HBM);   // (8, 512)
        gemm_bf16<<<grid, 256>>>(pFEATSH, pW1, pH12, KF, 1024);
    }
    // 6. activations -> bf16
    k_act<<<NROWS, 256>>>(mub1, mulg, mulb, mgb1);
    // 7/8. layer-2 GEMMs
    {
        dim3 grid(HDIM / HBN, NROWS / HBM);   // (4, 512)
        gemm_bf16<<<grid, 256>>>(pHMUH, pW2MU, pDELTA, HDIM, HDIM);
        gemm_bf16<<<grid, 256>>>(pHMGH, pW2MG, pGATE, HDIM, HDIM);
    }
    // 9. gate + residual + final LN
    k_final<<<NROWS, 256>>>(ep, mub2, mgb2, ng, nb, outU);
}

// round 6
// speedup vs baseline: 2.7260x; 1.7901x over previous
#include <cuda_runtime.h>
#include <cuda_bf16.h>
#include <mma.h>
#include <math.h>
#include <stdint.h>

using namespace nvcuda;

#define NROWS 65536
#define HDIM  512
#define MD    128
#define PROTO 12
#define KR    1408
#define KF    2048
#define RSCALE 0.2f

typedef __nv_bfloat16 bf16;

// ---------------- scratch (device globals; allocation-free) ----------------
__device__ __align__(1024) bf16  g_A2  [(size_t)NROWS * 2 * KR];   // [row][level][k]
__device__ __align__(1024) bf16  g_B0  [(size_t)KR * HDIM];        // hi(rw1) [k][n]
__device__ __align__(1024) bf16  g_B1  [(size_t)KR * HDIM];        // lo(rw1)
__device__ __align__(16)   float g_H1  [(size_t)NROWS * HDIM];     // router hidden (pre-bias)
__device__ __align__(1024) bf16  g_FEATSH[(size_t)NROWS * KF];
__device__ __align__(16)   float g_H12 [(size_t)NROWS * 1024];
__device__ __align__(1024) bf16  g_HMUH[(size_t)NROWS * HDIM];
__device__ __align__(1024) bf16  g_HMGH[(size_t)NROWS * HDIM];
__device__ __align__(16)   float g_DELTA[(size_t)NROWS * HDIM];
__device__ __align__(16)   float g_GATE [(size_t)NROWS * HDIM];
__device__ __align__(1024) bf16  g_W1  [(size_t)KF * 1024];        // [k][mu|mg]
__device__ __align__(1024) bf16  g_W2MU[(size_t)HDIM * HDIM];
__device__ __align__(1024) bf16  g_W2MG[(size_t)HDIM * HDIM];
__device__ __align__(16)   float g_W2T [(size_t)PROTO * HDIM];
__device__ int g_count;
__device__ int g_LIST[NROWS];

// ---------------- helpers ----------------
__device__ __forceinline__ float gelu_exact(float x) {
    return 0.5f * x * (1.0f + erff(x * 0.70710678118654752440f));
}
__device__ __forceinline__ float block_sum_256(float v, float* sbuf) {
    #pragma unroll
    for (int o = 16; o; o >>= 1) v += __shfl_xor_sync(0xffffffffu, v, o);
    int w = threadIdx.x >> 5;
    if ((threadIdx.x & 31) == 0) sbuf[w] = v;
    __syncthreads();
    float r = 0.0f;
    #pragma unroll
    for (int i = 0; i < 8; i++) r += sbuf[i];
    __syncthreads();
    return r;
}
__device__ __forceinline__ double block_sum_128d(double v, double* sbuf) {
    #pragma unroll
    for (int o = 16; o; o >>= 1) v += __shfl_xor_sync(0xffffffffu, v, o);
    int w = threadIdx.x >> 5;
    if ((threadIdx.x & 31) == 0) sbuf[w] = v;
    __syncthreads();
    double r = sbuf[0] + sbuf[1] + sbuf[2] + sbuf[3];
    __syncthreads();
    return r;
}
__device__ __forceinline__ void twosum_acc(float& sum, float& comp, float v) {
    float s = sum + v;
    float z = s - sum;
    float e = (sum - (s - z)) + (v - z);
    sum = s;
    comp += e;
}
__device__ __forceinline__ void split2(float v, bf16& b0, bf16& b1) {
    b0 = __float2bfloat16_rn(v);
    b1 = __float2bfloat16_rn(v - __bfloat162float(b0));
}
__device__ __forceinline__ void cp16(uint32_t dst, const void* src) {
    asm volatile("cp.async.cg.shared.global [%0], [%1], 16;" :: "r"(dst), "l"(src) : "memory");
}
__device__ __forceinline__ uint32_t smem_u32(const void* p) {
    uint32_t a;
    asm("{ .reg .u64 t; cvta.to.shared.u64 t, %1; cvt.u32.u64 %0, t; }" : "=r"(a) : "l"(p));
    return a;
}
#define CP_COMMIT() asm volatile("cp.async.commit_group;" ::: "memory")

// ---------------- k_prep ----------------
__global__ void k_prep(const float* __restrict__ rw1, const float* __restrict__ rw2,
                       const float* __restrict__ muw1, const float* __restrict__ mgw1,
                       const float* __restrict__ muw2, const float* __restrict__ mgw2) {
    int gtid = blockIdx.x * blockDim.x + threadIdx.x;
    int gs = blockDim.x * gridDim.x;
    if (gtid == 0) g_count = 0;
    for (int i = gtid; i < KR * HDIM; i += gs) {
        bf16 b0, b1;
        split2(rw1[i], b0, b1);
        g_B0[i] = b0; g_B1[i] = b1;
    }
    for (int i = gtid; i < KF * HDIM; i += gs) {
        int k = i / HDIM, c = i - k * HDIM;
        g_W1[(size_t)k * 1024 + c]       = __float2bfloat16_rn(muw1[i]);
        g_W1[(size_t)k * 1024 + 512 + c] = __float2bfloat16_rn(mgw1[i]);
    }
    for (int i = gtid; i < HDIM * HDIM; i += gs) {
        g_W2MU[i] = __float2bfloat16_rn(muw2[i]);
        g_W2MG[i] = __float2bfloat16_rn(mgw2[i]);
    }
    for (int i = gtid; i < PROTO * HDIM; i += gs) {
        int l = i / HDIM, c = i - l * HDIM;
        g_W2T[i] = rw2[(size_t)c * PROTO + l];
    }
}

// ---------------- gather + bf16x2 split of router input -----------------------
__global__ void k_gather_split(const float* __restrict__ pair, const float* __restrict__ ep,
                               const int* __restrict__ sid, const int* __restrict__ hc,
                               const int* __restrict__ ps,
                               const float* __restrict__ se, const float* __restrict__ he,
                               const float* __restrict__ soe) {
    int row = blockIdx.x;
    int s = min(max(sid[row], 0), 2048);
    int h = min(max(hc[row], 0), 9);
    int p = min(max(ps[row], 0), 7);
    const float* pr = &pair[(size_t)row * HDIM];
    const float* er = &ep[(size_t)row * HDIM];
    bf16* dst = &g_A2[(size_t)row * 2 * KR];
    for (int k = threadIdx.x; k < KR; k += blockDim.x) {
        float v;
        if      (k < 512)  v = pr[k];
        else if (k < 1024) v = er[k - 512];
        else if (k < 1152) v = se[s * MD + (k - 1024)];
        else if (k < 1280) v = he[h * MD + (k - 1152)];
        else               v = soe[p * MD + (k - 1280)];
        bf16 b0, b1;
        split2(v, b0, b1);
        dst[k] = b0; dst[KR + k] = b1;
    }
}

// ---------------- router GEMM: 3-term bf16 split, wmma, cp.async pipeline -----
// C[M,512] = A0@B0 + A0@B1 + A1@B0 ; tile 128x128, BK=32, double-buffered.
// smem stage layout (bf16 units): As0[128][40], As1[128][40], Bs0[32][136], Bs1[32][136]
#define RS_A  5120
#define RS_B  4352
#define RS_ST (2 * RS_A + 2 * RS_B)   // 18944 bf16 = 37888 B

__global__ void __launch_bounds__(256) gemm_router3(float* __restrict__ C) {
    extern __shared__ __align__(16) bf16 sm[];
    const int tid  = threadIdx.x;
    const int warp = tid >> 5;
    const int wr   = warp >> 1;   // 0..3
    const int wc   = warp & 1;    // 0..1
    const int m0 = blockIdx.y * 128;
    const int n0 = blockIdx.x * 128;
    const uint32_t smb = smem_u32(sm);

    wmma::fragment<wmma::accumulator, 16, 16, 16, float> acc[2][4];
    #pragma unroll
    for (int i = 0; i < 2; i++)
        #pragma unroll
        for (int j = 0; j < 4; j++) wmma::fill_fragment(acc[i][j], 0.0f);

    const bf16* Ab = g_A2 + (size_t)m0 * 2 * KR;

    auto load_stage = [&](int st, int kt) {
        uint32_t sb = smb + st * RS_ST * 2;   // byte address
        // A levels: 128x32 each; 512 chunks of 16B per level
        #pragma unroll
        for (int lv = 0; lv < 2; lv++) {
            uint32_t dstb = sb + lv * RS_A * 2;
            #pragma unroll
            for (int q = 0; q < 2; q++) {
                int idx = tid + q * 256;
                int row = idx >> 2, c8 = (idx & 3) << 3;
                cp16(dstb + row * 80 + c8 * 2,
                     Ab + (size_t)row * 2 * KR + (size_t)lv * KR + kt + c8);
            }
        }
        // B levels: 32x128 each
        #pragma unroll
        for (int q = 0; q < 2; q++) {
            int idx = tid + q * 256;
            int row = idx >> 4, c8 = (idx & 15) << 3;
            cp16(sb + 2 * RS_A * 2 + row * 272 + c8 * 2,
                 g_B0 + (size_t)(kt + row) * HDIM + n0 + c8);
        }
        #pragma unroll
        for (int q = 0; q < 2; q++) {
            int idx = tid + q * 256;
            int row = idx >> 4, c8 = (idx & 15) << 3;
            cp16(sb + (2 * RS_A + RS_B) * 2 + row * 272 + c8 * 2,
                 g_B1 + (size_t)(kt + row) * HDIM + n0 + c8);
        }
        CP_COMMIT();
    };

    load_stage(0, 0);
    load_stage(1, 32);

    const int nch = KR / 32;   // 44
    for (int i = 0; i < nch; i++) {
        int s = i & 1;
        if (i == nch - 1) asm volatile("cp.async.wait_group 0;" ::: "memory");
        else              asm volatile("cp.async.wait_group 1;" ::: "memory");
        __syncthreads();
        const bf16* As0 = sm + s * RS_ST;
        const bf16* As1 = As0 + RS_A;
        const bf16* Bs0 = As0 + 2 * RS_A;
        const bf16* Bs1 = Bs0 + RS_B;
        #pragma unroll
        for (int ks = 0; ks < 32; ks += 16) {
            wmma::fragment<wmma::matrix_a, 16, 16, 16, bf16, wmma::row_major> a0[2], a1[2];
            wmma::fragment<wmma::matrix_b, 16, 16, 16, bf16, wmma::row_major> b0[4], b1[4];
            #pragma unroll
            for (int ii = 0; ii < 2; ii++) {
                wmma::load_matrix_sync(a0[ii], As0 + (wr * 32 + ii * 16) * 40 + ks, 40);
                wmma::load_matrix_sync(a1[ii], As1 + (wr * 32 + ii * 16) * 40 + ks, 40);
            }
            #pragma unroll
            for (int jj = 0; jj < 4; jj++) {
                wmma::load_matrix_sync(b0[jj], Bs0 + ks * 136 + wc * 64 + jj * 16, 136);
                wmma::load_matrix_sync(b1[jj], Bs1 + ks * 136 + wc * 64 + jj * 16, 136);
            }
            #pragma unroll
            for (int ii = 0; ii < 2; ii++)
                #pragma unroll
                for (int jj = 0; jj < 4; jj++) {
                    wmma::mma_sync(acc[ii][jj], a0[ii], b0[jj], acc[ii][jj]);
                    wmma::mma_sync(acc[ii][jj], a0[ii], b1[jj], acc[ii][jj]);
                    wmma::mma_sync(acc[ii][jj], a1[ii], b0[jj], acc[ii][jj]);
                }
        }
        __syncthreads();
        if (i + 2 < nch) load_stage(s, (i + 2) * 32);
    }

    #pragma unroll
    for (int ii = 0; ii < 2; ii++)
        #pragma unroll
        for (int jj = 0; jj < 4; jj++) {
            float* Cp = C + (size_t)(m0 + wr * 32 + ii * 16) * HDIM + n0 + wc * 64 + jj * 16;
            wmma::store_matrix_sync(Cp, acc[ii][jj], HDIM, wmma::mem_row_major);
        }
}

// ---------------- bf16 GEMM (proven): C[M,NC] = A[M,K] @ B[K,NC] --------------
#define HBM 128
#define HBN 128
#define HBK 32
__global__ void __launch_bounds__(256) gemm_bf16(const bf16* __restrict__ A,
                                                 const bf16* __restrict__ B,
                                                 float* __restrict__ C,
                                                 int K, int NC) {
    __shared__ bf16 As[2][HBM][HBK + 8];
    __shared__ bf16 Bs[2][HBK][HBN + 8];
    const int m0 = blockIdx.y * HBM;
    const int n0 = blockIdx.x * HBN;
    const int tid  = threadIdx.x;
    const int warp = tid >> 5;
    const int wr   = warp >> 1;
    const int wc   = warp & 1;

    wmma::fragment<wmma::accumulator, 16, 16, 16, float> acc[2][4];
    #pragma unroll
    for (int i = 0; i < 2; i++)
        #pragma unroll
        for (int j = 0; j < 4; j++) wmma::fill_fragment(acc[i][j], 0.0f);

    #pragma unroll
    for (int r = 0; r < 2; r++) {
        int idx = tid + r * 256;
        int row = idx >> 2, c8 = (idx & 3) << 3;
        float4 v = *reinterpret_cast<const float4*>(&A[(size_t)(m0 + row) * K + c8]);
        *reinterpret_cast<float4*>(&As[0][row][c8]) = v;
    }
    #pragma unroll
    for (int r = 0; r < 2; r++) {
        int idx = tid + r * 256;
        int row = idx >> 4, c8 = (idx & 15) << 3;
        float4 v = *reinterpret_cast<const float4*>(&B[(size_t)row * NC + n0 + c8]);
        *reinterpret_cast<float4*>(&Bs[0][row][c8]) = v;
    }
    __syncthreads();

    int cur = 0;
    for (int kt = 0; kt < K; kt += HBK) {
        float4 pa[2], pb[2];
        const bool has_next = (kt + HBK) < K;
        if (has_next) {
            int nkt = kt + HBK;
            #pragma unroll
            for (int r = 0; r < 2; r++) {
                int idx = tid + r * 256;
                int row = idx >> 2, c8 = (idx & 3) << 3;
                pa[r] = *reinterpret_cast<const float4*>(&A[(size_t)(m0 + row) * K + nkt + c8]);
            }
            #pragma unroll
            for (int r = 0; r < 2; r++) {
                int idx = tid + r * 256;
                int row = idx >> 4, c8 = (idx & 15) << 3;
                pb[r] = *reinterpret_cast<const float4*>(&B[(size_t)(nkt + row) * NC + n0 + c8]);
            }
        }
        #pragma unroll
        for (int ks = 0; ks < HBK; ks += 16) {
            wmma::fragment<wmma::matrix_a, 16, 16, 16, bf16, wmma::row_major> af[2];
            wmma::fragment<wmma::matrix_b, 16, 16, 16, bf16, wmma::row_major> bfr[4];
            #pragma unroll
            for (int i = 0; i < 2; i++)
                wmma::load_matrix_sync(af[i], &As[cur][wr * 32 + i * 16][ks], HBK + 8);
            #pragma unroll
            for (int j = 0; j < 4; j++)
                wmma::load_matrix_sync(bfr[j], &Bs[cur][ks][wc * 64 + j * 16], HBN + 8);
            #pragma unroll
            for (int i = 0; i < 2; i++)
                #pragma unroll
                for (int j = 0; j < 4; j++)
                    wmma::mma_sync(acc[i][j], af[i], bfr[j], acc[i][j]);
        }
        if (has_next) {
            #pragma unroll
            for (int r = 0; r < 2; r++) {
                int idx = tid + r * 256;
                int row = idx >> 2, c8 = (idx & 3) << 3;
                *reinterpret_cast<float4*>(&As[cur ^ 1][row][c8]) = pa[r];
            }
            #pragma unroll
            for (int r = 0; r < 2; r++) {
                int idx = tid + r * 256;
                int row = idx >> 4, c8 = (idx & 15) << 3;
                *reinterpret_cast<float4*>(&Bs[cur ^ 1][row][c8]) = pb[r];
            }
        }
        __syncthreads();
        cur ^= 1;
    }

    #pragma unroll
    for (int i = 0; i < 2; i++)
        #pragma unroll
        for (int j = 0; j < 4; j++) {
            float* Cp = C + (size_t)(m0 + wr * 32 + i * 16) * NC + n0 + wc * 64 + j * 16;
            wmma::store_matrix_sync(Cp, acc[i][j], NC, wmma::mem_row_major);
        }
}

// ---------------- router2: bias+LN+GELU, logits, softmax, top4, flag, ctx, feats
__global__ void k_router2(const float* __restrict__ ep,
                          const float* __restrict__ rb1, const float* __restrict__ rlg,
                          const float* __restrict__ rlb,
                          const float* __restrict__ b2, const float* __restrict__ proto,
                          float* __restrict__ outC, float* __restrict__ outW) {
    __shared__ float sh[HDIM];
    __shared__ double dbuf[4];
    __shared__ float sl[PROTO];
    __shared__ float sw[PROTO];
    int row = blockIdx.x, t = threadIdx.x;    // 128 threads
    const float* hrow = &g_H1[(size_t)row * HDIM];
    float pre[4];
    double msum = 0.0;
    #pragma unroll
    for (int j = 0; j < 4; j++) {
        int c = t + j * 128;
        pre[j] = hrow[c] + rb1[c];
        msum += (double)pre[j];
    }
    double mean = block_sum_128d(msum, dbuf) * (1.0 / 512.0);
    double vsum = 0.0;
    #pragma unroll
    for (int j = 0; j < 4; j++) {
        double e0 = (double)pre[j] - mean;
        vsum += e0 * e0;
    }
    double var = block_sum_128d(vsum, dbuf) * (1.0 / 512.0);
    float rs = (float)(1.0 / sqrt(var + 1e-5));
    #pragma unroll
    for (int j = 0; j < 4; j++) {
        int c = t + j * 128;
        sh[c] = gelu_exact((float)((double)pre[j] - mean) * rs * rlg[c] + rlb[c]);
    }
    __syncthreads();
    int warp = t >> 5, lane = t & 31;
    for (int l = warp; l < PROTO; l += 4) {
        float s = 0.0f, cmp = 0.0f;
        const float* wl = &g_W2T[l * HDIM];
        for (int c = lane; c < HDIM; c += 32) {
            float a = sh[c], w = wl[c];
            float p = a * w;
            float pe = fmaf(a, w, -p);
            twosum_acc(s, cmp, p);
            cmp += pe;
        }
        #pragma unroll
        for (int o = 16; o; o >>= 1) {
            s   += __shfl_xor_sync(0xffffffffu, s, o);
            cmp += __shfl_xor_sync(0xffffffffu, cmp, o);
        }
        if (lane == 0) sl[l] = (s + cmp) + b2[l];
    }
    __syncthreads();
    if (t == 0) {
        float v[PROTO];
        #pragma unroll
        for (int i = 0; i < PROTO; i++) v[i] = sl[i];
        float top5[5];
        #pragma unroll
        for (int k = 0; k < 5; k++) {
            int bi = 0; float bv = -1e30f;
            #pragma unroll
            for (int i = 0; i < PROTO; i++)
                if (v[i] > bv) { bv = v[i]; bi = i; }
            top5[k] = bv; v[bi] = -1e30f;
        }
        if (top5[3] - top5[4] < 2e-4f) {
            int pos = atomicAdd(&g_count, 1);
            g_LIST[pos] = row;
        }
        float w[PROTO];
        float mx = -1e30f;
        #pragma unroll
        for (int i = 0; i < PROTO; i++) mx = fmaxf(mx, sl[i]);
        float ssum = 0.0f;
        #pragma unroll
        for (int i = 0; i < PROTO; i++) { w[i] = expf(sl[i] - mx); ssum += w[i]; }
        float inv = 1.0f / ssum;
        #pragma unroll
        for (int i = 0; i < PROTO; i++) w[i] *= inv;
        bool sel[PROTO];
        #pragma unroll
        for (int i = 0; i < PROTO; i++) sel[i] = false;
        for (int k = 0; k < 4; k++) {
            int bi = -1; float bv = -1e30f;
            #pragma unroll
            for (int i = 0; i < PROTO; i++)
                if (!sel[i] && w[i] > bv) { bv = w[i]; bi = i; }
            sel[bi] = true;
        }
        float s2 = 0.0f;
        #pragma unroll
        for (int i = 0; i < PROTO; i++) { float vv = sel[i] ? w[i] : 0.0f; sw[i] = vv; s2 += vv; }
        float d = 1.0f / fmaxf(s2, 1e-6f);
        #pragma unroll
        for (int i = 0; i < PROTO; i++) sw[i] *= d;
    }
    __syncthreads();
    if (t < PROTO) outW[(size_t)row * PROTO + t] = sw[t];
    const float* eprow = &ep[(size_t)row * HDIM];
    bf16* frow = &g_FEATSH[(size_t)row * KF];
    for (int j = t; j < HDIM; j += 128) {
        float c = 0.0f;
        #pragma unroll
        for (int p = 0; p < PROTO; p++) c += sw[p] * proto[p * HDIM + j];
        float e = eprow[j];
        outC[(size_t)row * HDIM + j] = c;
        frow[j]        = __float2bfloat16_rn(e);
        frow[512 + j]  = __float2bfloat16_rn(c);
        frow[1024 + j] = __float2bfloat16_rn(fabsf(e - c));
        frow[1536 + j] = __float2bfloat16_rn(e * c);
    }
}

// ---------------- rescue: exact recompute for flagged rows --------------------
__global__ void __launch_bounds__(128) k_rescue(
        const float* __restrict__ pair, const float* __restrict__ ep,
        const int* __restrict__ sid, const int* __restrict__ hc, const int* __restrict__ ps,
        const float* __restrict__ se, const float* __restrict__ he, const float* __restrict__ soe,
        const float* __restrict__ rw1, const float* __restrict__ rb1,
        const float* __restrict__ rlg, const float* __restrict__ rlb,
        const float* __restrict__ b2, const float* __restrict__ proto,
        float* __restrict__ outC, float* __restrict__ outW) {
    __shared__ float sa[KR];
    __shared__ float shd[HDIM];
    __shared__ double dbuf[4];
    __shared__ float sl[PROTO];
    __shared__ float sw[PROTO];
    int t = threadIdx.x, warp = t >> 5, lane = t & 31;
    int cnt = g_count;
    for (int li = blockIdx.x; li < cnt; li += gridDim.x) {
        int row = g_LIST[li];
        int s = min(max(sid[row], 0), 2048);
        int h = min(max(hc[row], 0), 9);
        int p = min(max(ps[row], 0), 7);
        const float* pr = &pair[(size_t)row * HDIM];
        const float* er = &ep[(size_t)row * HDIM];
        for (int k = t; k < KR; k += 128) {
            float v;
            if      (k < 512)  v = pr[k];
            else if (k < 1024) v = er[k - 512];
            else if (k < 1152) v = se[s * MD + (k - 1024)];
            else if (k < 1280) v = he[h * MD + (k - 1152)];
            else               v = soe[p * MD + (k - 1280)];
            sa[k] = v;
        }
        __syncthreads();
        float hs[4], hcmp[4];
        #pragma unroll
        for (int j = 0; j < 4; j++) { hs[j] = 0.0f; hcmp[j] = 0.0f; }
        for (int k = 0; k < KR; k++) {
            float a = sa[k];
            const float* wr = &rw1[(size_t)k * HDIM];
            #pragma unroll
            for (int j = 0; j < 4; j++) {
                int c = t + j * 128;
                float w = wr[c];
                float pp = a * w;
                float pe = fmaf(a, w, -pp);
                twosum_acc(hs[j], hcmp[j], pp);
                hcmp[j] += pe;
            }
        }
        float pre[4];
        double msum = 0.0;
        #pragma unroll
        for (int j = 0; j < 4; j++) {
            pre[j] = (hs[j] + hcmp[j]) + rb1[t + j * 128];
            msum += (double)pre[j];
        }
        double mean = block_sum_128d(msum, dbuf) * (1.0 / 512.0);
        double vsum = 0.0;
        #pragma unroll
        for (int j = 0; j < 4; j++) {
            double e0 = (double)pre[j] - mean;
            vsum += e0 * e0;
        }
        double var = block_sum_128d(vsum, dbuf) * (1.0 / 512.0);
        float rs = (float)(1.0 / sqrt(var + 1e-5));
        #pragma unroll
        for (int j = 0; j < 4; j++) {
            int c = t + j * 128;
            shd[c] = gelu_exact((float)((double)pre[j] - mean) * rs * rlg[c] + rlb[c]);
        }
        __syncthreads();
        for (int l = warp; l < PROTO; l += 4) {
            float ss = 0.0f, cmp = 0.0f;
            const float* wl = &g_W2T[l * HDIM];
            for (int c = lane; c < HDIM; c += 32) {
                float a = shd[c], w = wl[c];
                float pp = a * w;
                float pe = fmaf(a, w, -pp);
                twosum_acc(ss, cmp, pp);
                cmp += pe;
            }
            #pragma unroll
            for (int o = 16; o; o >>= 1) {
                ss  += __shfl_xor_sync(0xffffffffu, ss, o);
                cmp += __shfl_xor_sync(0xffffffffu, cmp, o);
            }
            if (lane == 0) sl[l] = (ss + cmp) + b2[l];
        }
        __syncthreads();
        if (t == 0) {
            float w[PROTO];
            float mx = -1e30f;
            #pragma unroll
            for (int i = 0; i < PROTO; i++) mx = fmaxf(mx, sl[i]);
            float ssum = 0.0f;
            #pragma unroll
            for (int i = 0; i < PROTO; i++) { w[i] = expf(sl[i] - mx); ssum += w[i]; }
            float inv = 1.0f / ssum;
            #pragma unroll
            for (int i = 0; i < PROTO; i++) w[i] *= inv;
            bool sel[PROTO];
            #pragma unroll
            for (int i = 0; i < PROTO; i++) sel[i] = false;
            for (int k = 0; k < 4; k++) {
                int bi = -1; float bv = -1e30f;
                #pragma unroll
                for (int i = 0; i < PROTO; i++)
                    if (!sel[i] && w[i] > bv) { bv = w[i]; bi = i; }
                sel[bi] = true;
            }
            float s2 = 0.0f;
            #pragma unroll
            for (int i = 0; i < PROTO; i++) { float vv = sel[i] ? w[i] : 0.0f; sw[i] = vv; s2 += vv; }
            float d = 1.0f / fmaxf(s2, 1e-6f);
            #pragma unroll
            for (int i = 0; i < PROTO; i++) sw[i] *= d;
        }
        __syncthreads();
        if (t < PROTO) outW[(size_t)row * PROTO + t] = sw[t];
        bf16* frow = &g_FEATSH[(size_t)row * KF];
        for (int j = t; j < HDIM; j += 128) {
            float c = 0.0f;
            #pragma unroll
            for (int pp = 0; pp < PROTO; pp++) c += sw[pp] * proto[pp * HDIM + j];
            float e = er[j];
            outC[(size_t)row * HDIM + j] = c;
            frow[j]        = __float2bfloat16_rn(e);
            frow[512 + j]  = __float2bfloat16_rn(c);
            frow[1024 + j] = __float2bfloat16_rn(fabsf(e - c));
            frow[1536 + j] = __float2bfloat16_rn(e * c);
        }
        __syncthreads();
    }
}

// ---------------- activations -> bf16 hidden ----------------------------------
__global__ void k_act(const float* __restrict__ b_mu, const float* __restrict__ g_mu,
                      const float* __restrict__ be_mu, const float* __restrict__ b_mg) {
    __shared__ float sbuf[8];
    int row = blockIdx.x, t = threadIdx.x;
    const float* h12 = &g_H12[(size_t)row * 1024];
    float m0 = h12[t] + b_mu[t];
    float m1 = h12[t + 256] + b_mu[t + 256];
    float mean = block_sum_256(m0 + m1, sbuf) * (1.0f / 512.0f);
    float d0 = m0 - mean, d1 = m1 - mean;
    float var = block_sum_256(d0 * d0 + d1 * d1, sbuf) * (1.0f / 512.0f);
    float rs = rsqrtf(var + 1e-5f);
    bf16* xm = &g_HMUH[(size_t)row * HDIM];
    bf16* xg = &g_HMGH[(size_t)row * HDIM];
    xm[t]       = __float2bfloat16_rn(gelu_exact(d0 * rs * g_mu[t] + be_mu[t]));
    xm[t + 256] = __float2bfloat16_rn(gelu_exact(d1 * rs * g_mu[t + 256] + be_mu[t + 256]));
    xg[t]       = __float2bfloat16_rn(gelu_exact(h12[512 + t] + b_mg[t]));
    xg[t + 256] = __float2bfloat16_rn(gelu_exact(h12[512 + t + 256] + b_mg[t + 256]));
}

// ---------------- final: gate, residual, LN -> updated ------------------------
__global__ void k_final(const float* __restrict__ ep, const float* __restrict__ mub2,
                        const float* __restrict__ mgb2, const float* __restrict__ ng,
                        const float* __restrict__ nb, float* __restrict__ outU) {
    __shared__ float sbuf[8];
    int row = blockIdx.x, t = threadIdx.x;
    const float* e  = &ep[(size_t)row * HDIM];
    const float* d  = &g_DELTA[(size_t)row * HDIM];
    const float* gp = &g_GATE[(size_t)row * HDIM];
    float u[2];
    #pragma unroll
    for (int r = 0; r < 2; r++) {
        int c = t + r * 256;
        float delta = d[c] + mub2[c];
        float gg    = gp[c] + mgb2[c];
        float gate  = 1.0f / (1.0f + expf(-gg));
        u[r] = e[c] + RSCALE * gate * delta;
    }
    float mean = block_sum_256(u[0] + u[1], sbuf) * (1.0f / 512.0f);
    float d0 = u[0] - mean, d1 = u[1] - mean;
    float var = block_sum_256(d0 * d0 + d1 * d1, sbuf) * (1.0f / 512.0f);
    float rs = rsqrtf(var + 1e-5f);
    outU[(size_t)row * HDIM + t]       = d0 * rs * ng[t] + nb[t];
    outU[(size_t)row * HDIM + t + 256] = d1 * rs * ng[t + 256] + nb[t + 256];
}

// ---------------- launch ----------------
extern "C" void kernel_launch(void* const* d_in, const int* in_sizes, int n_in,
                              void* d_out, int out_size) {
    const float* pair = (const float*)d_in[0];
    const float* ep   = (const float*)d_in[1];
    const int*   sid  = (const int*)d_in[2];
    const int*   hc   = (const int*)d_in[3];
    const int*   ps   = (const int*)d_in[4];
    const float* se   = (const float*)d_in[5];
    const float* he   = (const float*)d_in[6];
    const float* soe  = (const float*)d_in[7];
    const float* proto= (const float*)d_in[8];
    const float* rw1  = (const float*)d_in[9];
    const float* rb1  = (const float*)d_in[10];
    const float* rlg  = (const float*)d_in[11];
    const float* rlb  = (const float*)d_in[12];
    const float* rw2  = (const float*)d_in[13];
    const float* rb2  = (const float*)d_in[14];
    const float* muw1 = (const float*)d_in[15];
    const float* mub1 = (const float*)d_in[16];
    const float* mulg = (const float*)d_in[17];
    const float* mulb = (const float*)d_in[18];
    const float* muw2 = (const float*)d_in[19];
    const float* mub2 = (const float*)d_in[20];
    const float* mgw1 = (const float*)d_in[21];
    const float* mgb1 = (const float*)d_in[22];
    const float* mgw2 = (const float*)d_in[23];
    const float* mgb2 = (const float*)d_in[24];
    const float* ng   = (const float*)d_in[25];
    const float* nb   = (const float*)d_in[26];

    float* outU = (float*)d_out;
    float* outC = outU + (size_t)NROWS * HDIM;
    float* outW = outC + (size_t)NROWS * HDIM;

    float *pH1, *pH12, *pDELTA, *pGATE;
    bf16 *pFEATSH, *pHMUH, *pHMGH, *pW1, *pW2MU, *pW2MG;
    cudaGetSymbolAddress((void**)&pH1,     g_H1);
    cudaGetSymbolAddress((void**)&pH12,    g_H12);
    cudaGetSymbolAddress((void**)&pDELTA,  g_DELTA);
    cudaGetSymbolAddress((void**)&pGATE,   g_GATE);
    cudaGetSymbolAddress((void**)&pFEATSH, g_FEATSH);
    cudaGetSymbolAddress((void**)&pHMUH,   g_HMUH);
    cudaGetSymbolAddress((void**)&pHMGH,   g_HMGH);
    cudaGetSymbolAddress((void**)&pW1,     g_W1);
    cudaGetSymbolAddress((void**)&pW2MU,   g_W2MU);
    cudaGetSymbolAddress((void**)&pW2MG,   g_W2MG);

    static bool attr_set = false;
    if (!attr_set) {
        cudaFuncSetAttribute(gemm_router3, cudaFuncAttributeMaxDynamicSharedMemorySize,
                             2 * RS_ST * 2 + 256);
        attr_set = true;
    }

    k_prep<<<4096, 256>>>(rw1, rw2, muw1, mgw1, muw2, mgw2);
    k_gather_split<<<NROWS, 128>>>(pair, ep, sid, hc, ps, se, he, soe);
    {
        dim3 grid(HDIM / 128, NROWS / 128);    // (4, 512)
        gemm_router3<<<grid, 256, 2 * RS_ST * 2 + 256>>>(pH1);
    }
    k_router2<<<NROWS, 128>>>(ep, rb1, rlg, rlb, rb2, proto, outC, outW);
    k_rescue<<<2048, 128>>>(pair, ep, sid, hc, ps, se, he, soe,
                            rw1, rb1, rlg, rlb, rb2, proto, outC, outW);
    {
        dim3 grid(1024 / HBN, NROWS / HBM);    // (8, 512)
        gemm_bf16<<<grid, 256>>>(pFEATSH, pW1, pH12, KF, 1024);
    }
    k_act<<<NROWS, 256>>>(mub1, mulg, mulb, mgb1);
    {
        dim3 grid(HDIM / HBN, NROWS / HBM);    // (4, 512)
        gemm_bf16<<<grid, 256>>>(pHMUH, pW2MU, pDELTA, HDIM, HDIM);
        gemm_bf16<<<grid, 256>>>(pHMGH, pW2MG, pGATE, HDIM, HDIM);
    }
    k_final<<<NROWS, 256>>>(ep, mub2, mgb2, ng, nb, outU);
}

// round 8
// speedup vs baseline: 3.3194x; 1.2177x over previous
#include <cuda_runtime.h>
#include <cuda_bf16.h>
#include <mma.h>
#include <math.h>
#include <stdint.h>

using namespace nvcuda;

#define NROWS 65536
#define HDIM  512
#define MD    128
#define PROTO 12
#define KR    1408
#define KF    2048
#define RSCALE 0.2f

typedef __nv_bfloat16 bf16;

// ---------------- scratch (device globals; allocation-free) ----------------
__device__ __align__(1024) bf16  g_A2  [(size_t)NROWS * 2 * KR];   // [row][level][k]
__device__ __align__(1024) bf16  g_B0  [(size_t)KR * HDIM];
__device__ __align__(1024) bf16  g_B1  [(size_t)KR * HDIM];
__device__ __align__(16)   float g_H1  [(size_t)NROWS * HDIM];
__device__ __align__(1024) bf16  g_FEATSH[(size_t)NROWS * KF];
__device__ __align__(16)   float g_H12 [(size_t)NROWS * 1024];
__device__ __align__(1024) bf16  g_HMUH[(size_t)NROWS * HDIM];
__device__ __align__(1024) bf16  g_HMGH[(size_t)NROWS * HDIM];
__device__ __align__(16)   float g_DELTA[(size_t)NROWS * HDIM];
__device__ __align__(16)   float g_GATE [(size_t)NROWS * HDIM];
__device__ __align__(1024) bf16  g_W1  [(size_t)KF * 1024];
__device__ __align__(1024) bf16  g_W2MU[(size_t)HDIM * HDIM];
__device__ __align__(1024) bf16  g_W2MG[(size_t)HDIM * HDIM];
__device__ __align__(16)   float g_W2T [(size_t)PROTO * HDIM];
__device__ int g_count;
__device__ int g_LIST[NROWS];

// ---------------- helpers ----------------
__device__ __forceinline__ float gelu_exact(float x) {
    return 0.5f * x * (1.0f + erff(x * 0.70710678118654752440f));
}
__device__ __forceinline__ float2 block_sum2_128(float s1, float s2, float2* sb) {
    #pragma unroll
    for (int o = 16; o; o >>= 1) {
        s1 += __shfl_xor_sync(0xffffffffu, s1, o);
        s2 += __shfl_xor_sync(0xffffffffu, s2, o);
    }
    int w = threadIdx.x >> 5;
    if ((threadIdx.x & 31) == 0) sb[w] = make_float2(s1, s2);
    __syncthreads();
    float2 r = make_float2(sb[0].x + sb[1].x + sb[2].x + sb[3].x,
                           sb[0].y + sb[1].y + sb[2].y + sb[3].y);
    __syncthreads();
    return r;
}
__device__ __forceinline__ double block_sum_128d(double v, double* sbuf) {
    #pragma unroll
    for (int o = 16; o; o >>= 1) v += __shfl_xor_sync(0xffffffffu, v, o);
    int w = threadIdx.x >> 5;
    if ((threadIdx.x & 31) == 0) sbuf[w] = v;
    __syncthreads();
    double r = sbuf[0] + sbuf[1] + sbuf[2] + sbuf[3];
    __syncthreads();
    return r;
}
__device__ __forceinline__ void twosum_acc(float& sum, float& comp, float v) {
    float s = sum + v;
    float z = s - sum;
    float e = (sum - (s - z)) + (v - z);
    sum = s;
    comp += e;
}
__device__ __forceinline__ void split2(float v, bf16& b0, bf16& b1) {
    b0 = __float2bfloat16_rn(v);
    b1 = __float2bfloat16_rn(v - __bfloat162float(b0));
}
__device__ __forceinline__ void cp16(uint32_t dst, const void* src) {
    asm volatile("cp.async.cg.shared.global [%0], [%1], 16;" :: "r"(dst), "l"(src) : "memory");
}
__device__ __forceinline__ uint32_t smem_u32(const void* p) {
    uint32_t a;
    asm("{ .reg .u64 t; cvta.to.shared.u64 t, %1; cvt.u32.u64 %0, t; }" : "=r"(a) : "l"(p));
    return a;
}
#define CP_COMMIT() asm volatile("cp.async.commit_group;" ::: "memory")

__device__ __forceinline__ unsigned pack_bf2(float a, float b) {
    return ((unsigned)__bfloat16_as_ushort(__float2bfloat16_rn(b)) << 16)
         |  (unsigned)__bfloat16_as_ushort(__float2bfloat16_rn(a));
}
__device__ __forceinline__ void st_bf4(bf16* p, float4 v) {
    uint2 u;
    u.x = pack_bf2(v.x, v.y);
    u.y = pack_bf2(v.z, v.w);
    *reinterpret_cast<uint2*>(p) = u;
}

// ---------------- k_prep ----------------
__global__ void k_prep(const float* __restrict__ rw1, const float* __restrict__ rw2,
                       const float* __restrict__ muw1, const float* __restrict__ mgw1,
                       const float* __restrict__ muw2, const float* __restrict__ mgw2) {
    int gtid = blockIdx.x * blockDim.x + threadIdx.x;
    int gs = blockDim.x * gridDim.x;
    if (gtid == 0) g_count = 0;
    for (int i = gtid; i < KR * HDIM; i += gs) {
        bf16 b0, b1;
        split2(rw1[i], b0, b1);
        g_B0[i] = b0; g_B1[i] = b1;
    }
    for (int i = gtid; i < KF * HDIM; i += gs) {
        int k = i / HDIM, c = i - k * HDIM;
        g_W1[(size_t)k * 1024 + c]       = __float2bfloat16_rn(muw1[i]);
        g_W1[(size_t)k * 1024 + 512 + c] = __float2bfloat16_rn(mgw1[i]);
    }
    for (int i = gtid; i < HDIM * HDIM; i += gs) {
        g_W2MU[i] = __float2bfloat16_rn(muw2[i]);
        g_W2MG[i] = __float2bfloat16_rn(mgw2[i]);
    }
    for (int i = gtid; i < PROTO * HDIM; i += gs) {
        int l = i / HDIM, c = i - l * HDIM;
        g_W2T[i] = rw2[(size_t)c * PROTO + l];
    }
}

// ---------------- gather + bf16x2 split (float4 / packed stores) --------------
__global__ void k_gather_split(const float* __restrict__ pair, const float* __restrict__ ep,
                               const int* __restrict__ sid, const int* __restrict__ hc,
                               const int* __restrict__ ps,
                               const float* __restrict__ se, const float* __restrict__ he,
                               const float* __restrict__ soe) {
    int row = blockIdx.x;
    int s = min(max(sid[row], 0), 2048);
    int h = min(max(hc[row], 0), 9);
    int p = min(max(ps[row], 0), 7);
    const float4* pr  = reinterpret_cast<const float4*>(&pair[(size_t)row * HDIM]);
    const float4* er  = reinterpret_cast<const float4*>(&ep[(size_t)row * HDIM]);
    const float4* sev = reinterpret_cast<const float4*>(&se[s * MD]);
    const float4* hev = reinterpret_cast<const float4*>(&he[h * MD]);
    const float4* sov = reinterpret_cast<const float4*>(&soe[p * MD]);
    bf16* dst = &g_A2[(size_t)row * 2 * KR];
    for (int v = threadIdx.x; v < KR / 4; v += blockDim.x) {
        float4 f;
        if      (v < 128) f = pr[v];
        else if (v < 256) f = er[v - 128];
        else if (v < 288) f = sev[v - 256];
        else if (v < 320) f = hev[v - 288];
        else              f = sov[v - 320];
        bf16 b0[4], b1[4];
        split2(f.x, b0[0], b1[0]);
        split2(f.y, b0[1], b1[1]);
        split2(f.z, b0[2], b1[2]);
        split2(f.w, b0[3], b1[3]);
        uint2 u0, u1;
        u0.x = ((unsigned)__bfloat16_as_ushort(b0[1]) << 16) | __bfloat16_as_ushort(b0[0]);
        u0.y = ((unsigned)__bfloat16_as_ushort(b0[3]) << 16) | __bfloat16_as_ushort(b0[2]);
        u1.x = ((unsigned)__bfloat16_as_ushort(b1[1]) << 16) | __bfloat16_as_ushort(b1[0]);
        u1.y = ((unsigned)__bfloat16_as_ushort(b1[3]) << 16) | __bfloat16_as_ushort(b1[2]);
        *reinterpret_cast<uint2*>(dst + 4 * v)      = u0;
        *reinterpret_cast<uint2*>(dst + KR + 4 * v) = u1;
    }
}

// ---------------- router GEMM: 3-term bf16 split (unchanged, proven) ----------
#define RS_A  5120
#define RS_B  4352
#define RS_ST (2 * RS_A + 2 * RS_B)

__global__ void __launch_bounds__(256) gemm_router3(float* __restrict__ C) {
    extern __shared__ __align__(16) bf16 sm[];
    const int tid  = threadIdx.x;
    const int warp = tid >> 5;
    const int wr   = warp >> 1;
    const int wc   = warp & 1;
    const int m0 = blockIdx.y * 128;
    const int n0 = blockIdx.x * 128;
    const uint32_t smb = smem_u32(sm);

    wmma::fragment<wmma::accumulator, 16, 16, 16, float> acc[2][4];
    #pragma unroll
    for (int i = 0; i < 2; i++)
        #pragma unroll
        for (int j = 0; j < 4; j++) wmma::fill_fragment(acc[i][j], 0.0f);

    const bf16* Ab = g_A2 + (size_t)m0 * 2 * KR;

    auto load_stage = [&](int st, int kt) {
        uint32_t sb = smb + st * RS_ST * 2;
        #pragma unroll
        for (int lv = 0; lv < 2; lv++) {
            uint32_t dstb = sb + lv * RS_A * 2;
            #pragma unroll
            for (int q = 0; q < 2; q++) {
                int idx = tid + q * 256;
                int row = idx >> 2, c8 = (idx & 3) << 3;
                cp16(dstb + row * 80 + c8 * 2,
                     Ab + (size_t)row * 2 * KR + (size_t)lv * KR + kt + c8);
            }
        }
        #pragma unroll
        for (int q = 0; q < 2; q++) {
            int idx = tid + q * 256;
            int row = idx >> 4, c8 = (idx & 15) << 3;
            cp16(sb + 2 * RS_A * 2 + row * 272 + c8 * 2,
                 g_B0 + (size_t)(kt + row) * HDIM + n0 + c8);
        }
        #pragma unroll
        for (int q = 0; q < 2; q++) {
            int idx = tid + q * 256;
            int row = idx >> 4, c8 = (idx & 15) << 3;
            cp16(sb + (2 * RS_A + RS_B) * 2 + row * 272 + c8 * 2,
                 g_B1 + (size_t)(kt + row) * HDIM + n0 + c8);
        }
        CP_COMMIT();
    };

    load_stage(0, 0);
    load_stage(1, 32);

    const int nch = KR / 32;
    for (int i = 0; i < nch; i++) {
        int s = i & 1;
        if (i == nch - 1) asm volatile("cp.async.wait_group 0;" ::: "memory");
        else              asm volatile("cp.async.wait_group 1;" ::: "memory");
        __syncthreads();
        const bf16* As0 = sm + s * RS_ST;
        const bf16* As1 = As0 + RS_A;
        const bf16* Bs0 = As0 + 2 * RS_A;
        const bf16* Bs1 = Bs0 + RS_B;
        #pragma unroll
        for (int ks = 0; ks < 32; ks += 16) {
            wmma::fragment<wmma::matrix_a, 16, 16, 16, bf16, wmma::row_major> a0[2], a1[2];
            wmma::fragment<wmma::matrix_b, 16, 16, 16, bf16, wmma::row_major> b0[4], b1[4];
            #pragma unroll
            for (int ii = 0; ii < 2; ii++) {
                wmma::load_matrix_sync(a0[ii], As0 + (wr * 32 + ii * 16) * 40 + ks, 40);
                wmma::load_matrix_sync(a1[ii], As1 + (wr * 32 + ii * 16) * 40 + ks, 40);
            }
            #pragma unroll
            for (int jj = 0; jj < 4; jj++) {
                wmma::load_matrix_sync(b0[jj], Bs0 + ks * 136 + wc * 64 + jj * 16, 136);
                wmma::load_matrix_sync(b1[jj], Bs1 + ks * 136 + wc * 64 + jj * 16, 136);
            }
            #pragma unroll
            for (int ii = 0; ii < 2; ii++)
                #pragma unroll
                for (int jj = 0; jj < 4; jj++) {
                    wmma::mma_sync(acc[ii][jj], a0[ii], b0[jj], acc[ii][jj]);
                    wmma::mma_sync(acc[ii][jj], a0[ii], b1[jj], acc[ii][jj]);
                    wmma::mma_sync(acc[ii][jj], a1[ii], b0[jj], acc[ii][jj]);
                }
        }
        __syncthreads();
        if (i + 2 < nch) load_stage(s, (i + 2) * 32);
    }

    #pragma unroll
    for (int ii = 0; ii < 2; ii++)
        #pragma unroll
        for (int jj = 0; jj < 4; jj++) {
            float* Cp = C + (size_t)(m0 + wr * 32 + ii * 16) * HDIM + n0 + wc * 64 + jj * 16;
            wmma::store_matrix_sync(Cp, acc[ii][jj], HDIM, wmma::mem_row_major);
        }
}

// ---------------- bf16 GEMM (unchanged, proven) -------------------------------
#define HBM 128
#define HBN 128
#define HBK 32
__global__ void __launch_bounds__(256) gemm_bf16(const bf16* __restrict__ A,
                                                 const bf16* __restrict__ B,
                                                 float* __restrict__ C,
                                                 int K, int NC) {
    __shared__ bf16 As[2][HBM][HBK + 8];
    __shared__ bf16 Bs[2][HBK][HBN + 8];
    const int m0 = blockIdx.y * HBM;
    const int n0 = blockIdx.x * HBN;
    const int tid  = threadIdx.x;
    const int warp = tid >> 5;
    const int wr   = warp >> 1;
    const int wc   = warp & 1;

    wmma::fragment<wmma::accumulator, 16, 16, 16, float> acc[2][4];
    #pragma unroll
    for (int i = 0; i < 2; i++)
        #pragma unroll
        for (int j = 0; j < 4; j++) wmma::fill_fragment(acc[i][j], 0.0f);

    #pragma unroll
    for (int r = 0; r < 2; r++) {
        int idx = tid + r * 256;
        int row = idx >> 2, c8 = (idx & 3) << 3;
        float4 v = *reinterpret_cast<const float4*>(&A[(size_t)(m0 + row) * K + c8]);
        *reinterpret_cast<float4*>(&As[0][row][c8]) = v;
    }
    #pragma unroll
    for (int r = 0; r < 2; r++) {
        int idx = tid + r * 256;
        int row = idx >> 4, c8 = (idx & 15) << 3;
        float4 v = *reinterpret_cast<const float4*>(&B[(size_t)row * NC + n0 + c8]);
        *reinterpret_cast<float4*>(&Bs[0][row][c8]) = v;
    }
    __syncthreads();

    int cur = 0;
    for (int kt = 0; kt < K; kt += HBK) {
        float4 pa[2], pb[2];
        const bool has_next = (kt + HBK) < K;
        if (has_next) {
            int nkt = kt + HBK;
            #pragma unroll
            for (int r = 0; r < 2; r++) {
                int idx = tid + r * 256;
                int row = idx >> 2, c8 = (idx & 3) << 3;
                pa[r] = *reinterpret_cast<const float4*>(&A[(size_t)(m0 + row) * K + nkt + c8]);
            }
            #pragma unroll
            for (int r = 0; r < 2; r++) {
                int idx = tid + r * 256;
                int row = idx >> 4, c8 = (idx & 15) << 3;
                pb[r] = *reinterpret_cast<const float4*>(&B[(size_t)(nkt + row) * NC + n0 + c8]);
            }
        }
        #pragma unroll
        for (int ks = 0; ks < HBK; ks += 16) {
            wmma::fragment<wmma::matrix_a, 16, 16, 16, bf16, wmma::row_major> af[2];
            wmma::fragment<wmma::matrix_b, 16, 16, 16, bf16, wmma::row_major> bfr[4];
            #pragma unroll
            for (int i = 0; i < 2; i++)
                wmma::load_matrix_sync(af[i], &As[cur][wr * 32 + i * 16][ks], HBK + 8);
            #pragma unroll
            for (int j = 0; j < 4; j++)
                wmma::load_matrix_sync(bfr[j], &Bs[cur][ks][wc * 64 + j * 16], HBN + 8);
            #pragma unroll
            for (int i = 0; i < 2; i++)
                #pragma unroll
                for (int j = 0; j < 4; j++)
                    wmma::mma_sync(acc[i][j], af[i], bfr[j], acc[i][j]);
        }
        if (has_next) {
            #pragma unroll
            for (int r = 0; r < 2; r++) {
                int idx = tid + r * 256;
                int row = idx >> 2, c8 = (idx & 3) << 3;
                *reinterpret_cast<float4*>(&As[cur ^ 1][row][c8]) = pa[r];
            }
            #pragma unroll
            for (int r = 0; r < 2; r++) {
                int idx = tid + r * 256;
                int row = idx >> 4, c8 = (idx & 15) << 3;
                *reinterpret_cast<float4*>(&Bs[cur ^ 1][row][c8]) = pb[r];
            }
        }
        __syncthreads();
        cur ^= 1;
    }

    #pragma unroll
    for (int i = 0; i < 2; i++)
        #pragma unroll
        for (int j = 0; j < 4; j++) {
            float* Cp = C + (size_t)(m0 + wr * 32 + i * 16) * NC + n0 + wc * 64 + j * 16;
            wmma::store_matrix_sync(Cp, acc[i][j], NC, wmma::mem_row_major);
        }
}

// ---------------- router2: fp32 single-pass LN + plain dot + vectorized -------
__global__ void k_router2(const float* __restrict__ ep,
                          const float* __restrict__ rb1, const float* __restrict__ rlg,
                          const float* __restrict__ rlb,
                          const float* __restrict__ b2, const float* __restrict__ proto,
                          float* __restrict__ outC, float* __restrict__ outW) {
    __shared__ float sh[HDIM];
    __shared__ float2 sb2[4];
    __shared__ float sl[PROTO];
    __shared__ float sw[PROTO];
    int row = blockIdx.x, t = threadIdx.x;    // 128 threads
    const float4 h4 = reinterpret_cast<const float4*>(&g_H1[(size_t)row * HDIM])[t];
    const float4 b4 = reinterpret_cast<const float4*>(rb1)[t];
    float4 pre = make_float4(h4.x + b4.x, h4.y + b4.y, h4.z + b4.z, h4.w + b4.w);
    float s1 = pre.x + pre.y + pre.z + pre.w;
    float s2 = pre.x * pre.x + pre.y * pre.y + pre.z * pre.z + pre.w * pre.w;
    float2 r = block_sum2_128(s1, s2, sb2);
    float mean = r.x * (1.0f / 512.0f);
    float var  = r.y * (1.0f / 512.0f) - mean * mean;
    float rs = rsqrtf(var + 1e-5f);
    const float4 g4  = reinterpret_cast<const float4*>(rlg)[t];
    const float4 be4 = reinterpret_cast<const float4*>(rlb)[t];
    float4 hv;
    hv.x = gelu_exact((pre.x - mean) * rs * g4.x + be4.x);
    hv.y = gelu_exact((pre.y - mean) * rs * g4.y + be4.y);
    hv.z = gelu_exact((pre.z - mean) * rs * g4.z + be4.z);
    hv.w = gelu_exact((pre.w - mean) * rs * g4.w + be4.w);
    reinterpret_cast<float4*>(sh)[t] = hv;
    __syncthreads();
    int warp = t >> 5, lane = t & 31;
    #pragma unroll
    for (int q = 0; q < 3; q++) {
        int l = warp * 3 + q;
        const float* wl = &g_W2T[l * HDIM];
        float sa = 0.0f, sb = 0.0f;
        #pragma unroll
        for (int c = 0; c < HDIM; c += 64) {
            sa = fmaf(sh[c + lane],      wl[c + lane],      sa);
            sb = fmaf(sh[c + lane + 32], wl[c + lane + 32], sb);
        }
        sa += sb;
        #pragma unroll
        for (int o = 16; o; o >>= 1) sa += __shfl_xor_sync(0xffffffffu, sa, o);
        if (lane == 0) sl[l] = sa + b2[l];
    }
    __syncthreads();
    if (t == 0) {
        float v[PROTO];
        #pragma unroll
        for (int i = 0; i < PROTO; i++) v[i] = sl[i];
        float top5[5];
        #pragma unroll
        for (int k = 0; k < 5; k++) {
            int bi = 0; float bv = -1e30f;
            #pragma unroll
            for (int i = 0; i < PROTO; i++)
                if (v[i] > bv) { bv = v[i]; bi = i; }
            top5[k] = bv; v[bi] = -1e30f;
        }
        if (top5[3] - top5[4] < 2e-4f) {
            int pos = atomicAdd(&g_count, 1);
            g_LIST[pos] = row;
        }
        float w[PROTO];
        float mx = -1e30f;
        #pragma unroll
        for (int i = 0; i < PROTO; i++) mx = fmaxf(mx, sl[i]);
        float ssum = 0.0f;
        #pragma unroll
        for (int i = 0; i < PROTO; i++) { w[i] = expf(sl[i] - mx); ssum += w[i]; }
        float inv = 1.0f / ssum;
        #pragma unroll
        for (int i = 0; i < PROTO; i++) w[i] *= inv;
        bool sel[PROTO];
        #pragma unroll
        for (int i = 0; i < PROTO; i++) sel[i] = false;
        for (int k = 0; k < 4; k++) {
            int bi = -1; float bv = -1e30f;
            #pragma unroll
            for (int i = 0; i < PROTO; i++)
                if (!sel[i] && w[i] > bv) { bv = w[i]; bi = i; }
            sel[bi] = true;
        }
        float s22 = 0.0f;
        #pragma unroll
        for (int i = 0; i < PROTO; i++) { float vv = sel[i] ? w[i] : 0.0f; sw[i] = vv; s22 += vv; }
        float d = 1.0f / fmaxf(s22, 1e-6f);
        #pragma unroll
        for (int i = 0; i < PROTO; i++) sw[i] *= d;
    }
    __syncthreads();
    if (t < PROTO) outW[(size_t)row * PROTO + t] = sw[t];
    const float4 e4 = reinterpret_cast<const float4*>(&ep[(size_t)row * HDIM])[t];
    float4 c4 = make_float4(0.f, 0.f, 0.f, 0.f);
    #pragma unroll
    for (int p = 0; p < PROTO; p++) {
        float wv = sw[p];
        const float4 p4 = reinterpret_cast<const float4*>(&proto[p * HDIM])[t];
        c4.x = fmaf(wv, p4.x, c4.x);
        c4.y = fmaf(wv, p4.y, c4.y);
        c4.z = fmaf(wv, p4.z, c4.z);
        c4.w = fmaf(wv, p4.w, c4.w);
    }
    reinterpret_cast<float4*>(&outC[(size_t)row * HDIM])[t] = c4;
    bf16* frow = &g_FEATSH[(size_t)row * KF];
    st_bf4(frow + 4 * t, e4);
    st_bf4(frow + 512 + 4 * t, c4);
    st_bf4(frow + 1024 + 4 * t, make_float4(fabsf(e4.x - c4.x), fabsf(e4.y - c4.y),
                                            fabsf(e4.z - c4.z), fabsf(e4.w - c4.w)));
    st_bf4(frow + 1536 + 4 * t, make_float4(e4.x * c4.x, e4.y * c4.y,
                                            e4.z * c4.z, e4.w * c4.w));
}

// ---------------- rescue (unchanged, exact) -----------------------------------
__global__ void __launch_bounds__(128) k_rescue(
        const float* __restrict__ pair, const float* __restrict__ ep,
        const int* __restrict__ sid, const int* __restrict__ hc, const int* __restrict__ ps,
        const float* __restrict__ se, const float* __restrict__ he, const float* __restrict__ soe,
        const float* __restrict__ rw1, const float* __restrict__ rb1,
        const float* __restrict__ rlg, const float* __restrict__ rlb,
        const float* __restrict__ b2, const float* __restrict__ proto,
        float* __restrict__ outC, float* __restrict__ outW) {
    __shared__ float sa[KR];
    __shared__ float shd[HDIM];
    __shared__ double dbuf[4];
    __shared__ float sl[PROTO];
    __shared__ float sw[PROTO];
    int t = threadIdx.x, warp = t >> 5, lane = t & 31;
    int cnt = g_count;
    for (int li = blockIdx.x; li < cnt; li += gridDim.x) {
        int row = g_LIST[li];
        int s = min(max(sid[row], 0), 2048);
        int h = min(max(hc[row], 0), 9);
        int p = min(max(ps[row], 0), 7);
        const float* pr = &pair[(size_t)row * HDIM];
        const float* er = &ep[(size_t)row * HDIM];
        for (int k = t; k < KR; k += 128) {
            float v;
            if      (k < 512)  v = pr[k];
            else if (k < 1024) v = er[k - 512];
            else if (k < 1152) v = se[s * MD + (k - 1024)];
            else if (k < 1280) v = he[h * MD + (k - 1152)];
            else               v = soe[p * MD + (k - 1280)];
            sa[k] = v;
        }
        __syncthreads();
        float hs[4], hcmp[4];
        #pragma unroll
        for (int j = 0; j < 4; j++) { hs[j] = 0.0f; hcmp[j] = 0.0f; }
        for (int k = 0; k < KR; k++) {
            float a = sa[k];
            const float* wr = &rw1[(size_t)k * HDIM];
            #pragma unroll
            for (int j = 0; j < 4; j++) {
                int c = t + j * 128;
                float w = wr[c];
                float pp = a * w;
                float pe = fmaf(a, w, -pp);
                twosum_acc(hs[j], hcmp[j], pp);
                hcmp[j] += pe;
            }
        }
        float pre[4];
        double msum = 0.0;
        #pragma unroll
        for (int j = 0; j < 4; j++) {
            pre[j] = (hs[j] + hcmp[j]) + rb1[t + j * 128];
            msum += (double)pre[j];
        }
        double mean = block_sum_128d(msum, dbuf) * (1.0 / 512.0);
        double vsum = 0.0;
        #pragma unroll
        for (int j = 0; j < 4; j++) {
            double e0 = (double)pre[j] - mean;
            vsum += e0 * e0;
        }
        double var = block_sum_128d(vsum, dbuf) * (1.0 / 512.0);
        float rs = (float)(1.0 / sqrt(var + 1e-5));
        #pragma unroll
        for (int j = 0; j < 4; j++) {
            int c = t + j * 128;
            shd[c] = gelu_exact((float)((double)pre[j] - mean) * rs * rlg[c] + rlb[c]);
        }
        __syncthreads();
        for (int l = warp; l < PROTO; l += 4) {
            float ss = 0.0f, cmp = 0.0f;
            const float* wl = &g_W2T[l * HDIM];
            for (int c = lane; c < HDIM; c += 32) {
                float a = shd[c], w = wl[c];
                float pp = a * w;
                float pe = fmaf(a, w, -pp);
                twosum_acc(ss, cmp, pp);
                cmp += pe;
            }
            #pragma unroll
            for (int o = 16; o; o >>= 1) {
                ss  += __shfl_xor_sync(0xffffffffu, ss, o);
                cmp += __shfl_xor_sync(0xffffffffu, cmp, o);
            }
            if (lane == 0) sl[l] = (ss + cmp) + b2[l];
        }
        __syncthreads();
        if (t == 0) {
            float w[PROTO];
            float mx = -1e30f;
            #pragma unroll
            for (int i = 0; i < PROTO; i++) mx = fmaxf(mx, sl[i]);
            float ssum = 0.0f;
            #pragma unroll
            for (int i = 0; i < PROTO; i++) { w[i] = expf(sl[i] - mx); ssum += w[i]; }
            float inv = 1.0f / ssum;
            #pragma unroll
            for (int i = 0; i < PROTO; i++) w[i] *= inv;
            bool sel[PROTO];
            #pragma unroll
            for (int i = 0; i < PROTO; i++) sel[i] = false;
            for (int k = 0; k < 4; k++) {
                int bi = -1; float bv = -1e30f;
                #pragma unroll
                for (int i = 0; i < PROTO; i++)
                    if (!sel[i] && w[i] > bv) { bv = w[i]; bi = i; }
                sel[bi] = true;
            }
            float s2 = 0.0f;
            #pragma unroll
            for (int i = 0; i < PROTO; i++) { float vv = sel[i] ? w[i] : 0.0f; sw[i] = vv; s2 += vv; }
            float d = 1.0f / fmaxf(s2, 1e-6f);
            #pragma unroll
            for (int i = 0; i < PROTO; i++) sw[i] *= d;
        }
        __syncthreads();
        if (t < PROTO) outW[(size_t)row * PROTO + t] = sw[t];
        bf16* frow = &g_FEATSH[(size_t)row * KF];
        for (int j = t; j < HDIM; j += 128) {
            float c = 0.0f;
            #pragma unroll
            for (int pp = 0; pp < PROTO; pp++) c += sw[pp] * proto[pp * HDIM + j];
            float e = er[j];
            outC[(size_t)row * HDIM + j] = c;
            frow[j]        = __float2bfloat16_rn(e);
            frow[512 + j]  = __float2bfloat16_rn(c);
            frow[1024 + j] = __float2bfloat16_rn(fabsf(e - c));
            frow[1536 + j] = __float2bfloat16_rn(e * c);
        }
        __syncthreads();
    }
}

// ---------------- activations (float4, single-pass LN) ------------------------
__global__ void k_act(const float* __restrict__ b_mu, const float* __restrict__ g_mu,
                      const float* __restrict__ be_mu, const float* __restrict__ b_mg) {
    __shared__ float2 sb2[4];
    int row = blockIdx.x, t = threadIdx.x;    // 128 threads
    const float4* h12 = reinterpret_cast<const float4*>(&g_H12[(size_t)row * 1024]);
    const float4 m4i = h12[t];
    const float4 b4 = reinterpret_cast<const float4*>(b_mu)[t];
    float4 m4 = make_float4(m4i.x + b4.x, m4i.y + b4.y, m4i.z + b4.z, m4i.w + b4.w);
    float s1 = m4.x + m4.y + m4.z + m4.w;
    float s2 = m4.x * m4.x + m4.y * m4.y + m4.z * m4.z + m4.w * m4.w;
    float2 r = block_sum2_128(s1, s2, sb2);
    float mean = r.x * (1.0f / 512.0f);
    float var  = r.y * (1.0f / 512.0f) - mean * mean;
    float rs = rsqrtf(var + 1e-5f);
    const float4 g4  = reinterpret_cast<const float4*>(g_mu)[t];
    const float4 be4 = reinterpret_cast<const float4*>(be_mu)[t];
    float4 xm;
    xm.x = gelu_exact((m4.x - mean) * rs * g4.x + be4.x);
    xm.y = gelu_exact((m4.y - mean) * rs * g4.y + be4.y);
    xm.z = gelu_exact((m4.z - mean) * rs * g4.z + be4.z);
    xm.w = gelu_exact((m4.w - mean) * rs * g4.w + be4.w);
    st_bf4(&g_HMUH[(size_t)row * HDIM] + 4 * t, xm);
    const float4 gg4i = h12[128 + t];
    const float4 bg4 = reinterpret_cast<const float4*>(b_mg)[t];
    float4 xg;
    xg.x = gelu_exact(gg4i.x + bg4.x);
    xg.y = gelu_exact(gg4i.y + bg4.y);
    xg.z = gelu_exact(gg4i.z + bg4.z);
    xg.w = gelu_exact(gg4i.w + bg4.w);
    st_bf4(&g_HMGH[(size_t)row * HDIM] + 4 * t, xg);
}

// ---------------- final (float4, single-pass LN) ------------------------------
__global__ void k_final(const float* __restrict__ ep, const float* __restrict__ mub2,
                        const float* __restrict__ mgb2, const float* __restrict__ ng,
                        const float* __restrict__ nb, float* __restrict__ outU) {
    __shared__ float2 sb2[4];
    int row = blockIdx.x, t = threadIdx.x;    // 128 threads
    const float4 e4 = reinterpret_cast<const float4*>(&ep[(size_t)row * HDIM])[t];
    const float4 d4 = reinterpret_cast<const float4*>(&g_DELTA[(size_t)row * HDIM])[t];
    const float4 gp4 = reinterpret_cast<const float4*>(&g_GATE[(size_t)row * HDIM])[t];
    const float4 db4 = reinterpret_cast<const float4*>(mub2)[t];
    const float4 gb4 = reinterpret_cast<const float4*>(mgb2)[t];
    float4 u;
    u.x = e4.x + RSCALE * (1.0f / (1.0f + expf(-(gp4.x + gb4.x)))) * (d4.x + db4.x);
    u.y = e4.y + RSCALE * (1.0f / (1.0f + expf(-(gp4.y + gb4.y)))) * (d4.y + db4.y);
    u.z = e4.z + RSCALE * (1.0f / (1.0f + expf(-(gp4.z + gb4.z)))) * (d4.z + db4.z);
    u.w = e4.w + RSCALE * (1.0f / (1.0f + expf(-(gp4.w + gb4.w)))) * (d4.w + db4.w);
    float s1 = u.x + u.y + u.z + u.w;
    float s2 = u.x * u.x + u.y * u.y + u.z * u.z + u.w * u.w;
    float2 r = block_sum2_128(s1, s2, sb2);
    float mean = r.x * (1.0f / 512.0f);
    float var  = r.y * (1.0f / 512.0f) - mean * mean;
    float rs = rsqrtf(var + 1e-5f);
    const float4 g4 = reinterpret_cast<const float4*>(ng)[t];
    const float4 b4 = reinterpret_cast<const float4*>(nb)[t];
    float4 o;
    o.x = (u.x - mean) * rs * g4.x + b4.x;
    o.y = (u.y - mean) * rs * g4.y + b4.y;
    o.z = (u.z - mean) * rs * g4.z + b4.z;
    o.w = (u.w - mean) * rs * g4.w + b4.w;
    reinterpret_cast<float4*>(&outU[(size_t)row * HDIM])[t] = o;
}

// ---------------- launch ----------------
extern "C" void kernel_launch(void* const* d_in, const int* in_sizes, int n_in,
                              void* d_out, int out_size) {
    const float* pair = (const float*)d_in[0];
    const float* ep   = (const float*)d_in[1];
    const int*   sid  = (const int*)d_in[2];
    const int*   hc   = (const int*)d_in[3];
    const int*   ps   = (const int*)d_in[4];
    const float* se   = (const float*)d_in[5];
    const float* he   = (const float*)d_in[6];
    const float* soe  = (const float*)d_in[7];
    const float* proto= (const float*)d_in[8];
    const float* rw1  = (const float*)d_in[9];
    const float* rb1  = (const float*)d_in[10];
    const float* rlg  = (const float*)d_in[11];
    const float* rlb  = (const float*)d_in[12];
    const float* rw2  = (const float*)d_in[13];
    const float* rb2  = (const float*)d_in[14];
    const float* muw1 = (const float*)d_in[15];
    const float* mub1 = (const float*)d_in[16];
    const float* mulg = (const float*)d_in[17];
    const float* mulb = (const float*)d_in[18];
    const float* muw2 = (const float*)d_in[19];
    const float* mub2 = (const float*)d_in[20];
    const float* mgw1 = (const float*)d_in[21];
    const float* mgb1 = (const float*)d_in[22];
    const float* mgw2 = (const float*)d_in[23];
    const float* mgb2 = (const float*)d_in[24];
    const float* ng   = (const float*)d_in[25];
    const float* nb   = (const float*)d_in[26];

    float* outU = (float*)d_out;
    float* outC = outU + (size_t)NROWS * HDIM;
    float* outW = outC + (size_t)NROWS * HDIM;

    float *pH1, *pH12, *pDELTA, *pGATE;
    bf16 *pFEATSH, *pHMUH, *pHMGH, *pW1, *pW2MU, *pW2MG;
    cudaGetSymbolAddress((void**)&pH1,     g_H1);
    cudaGetSymbolAddress((void**)&pH12,    g_H12);
    cudaGetSymbolAddress((void**)&pDELTA,  g_DELTA);
    cudaGetSymbolAddress((void**)&pGATE,   g_GATE);
    cudaGetSymbolAddress((void**)&pFEATSH, g_FEATSH);
    cudaGetSymbolAddress((void**)&pHMUH,   g_HMUH);
    cudaGetSymbolAddress((void**)&pHMGH,   g_HMGH);
    cudaGetSymbolAddress((void**)&pW1,     g_W1);
    cudaGetSymbolAddress((void**)&pW2MU,   g_W2MU);
    cudaGetSymbolAddress((void**)&pW2MG,   g_W2MG);

    static bool attr_set = false;
    if (!attr_set) {
        cudaFuncSetAttribute(gemm_router3, cudaFuncAttributeMaxDynamicSharedMemorySize,
                             2 * RS_ST * 2 + 256);
        attr_set = true;
    }

    k_prep<<<4096, 256>>>(rw1, rw2, muw1, mgw1, muw2, mgw2);
    k_gather_split<<<NROWS, 128>>>(pair, ep, sid, hc, ps, se, he, soe);
    {
        dim3 grid(HDIM / 128, NROWS / 128);
        gemm_router3<<<grid, 256, 2 * RS_ST * 2 + 256>>>(pH1);
    }
    k_router2<<<NROWS, 128>>>(ep, rb1, rlg, rlb, rb2, proto, outC, outW);
    k_rescue<<<2048, 128>>>(pair, ep, sid, hc, ps, se, he, soe,
                            rw1, rb1, rlg, rlb, rb2, proto, outC, outW);
    {
        dim3 grid(1024 / HBN, NROWS / HBM);
        gemm_bf16<<<grid, 256>>>(pFEATSH, pW1, pH12, KF, 1024);
    }
    k_act<<<NROWS, 128>>>(mub1, mulg, mulb, mgb1);
    {
        dim3 grid(HDIM / HBN, NROWS / HBM);
        gemm_bf16<<<grid, 256>>>(pHMUH, pW2MU, pDELTA, HDIM, HDIM);
        gemm_bf16<<<grid, 256>>>(pHMGH, pW2MG, pGATE, HDIM, HDIM);
    }
    k_final<<<NROWS, 128>>>(ep, mub2, mgb2, ng, nb, outU);
}

// round 9
// speedup vs baseline: 3.8822x; 1.1696x over previous
#include <cuda_runtime.h>
#include <cuda_bf16.h>
#include <cuda_fp16.h>
#include <mma.h>
#include <math.h>
#include <stdint.h>

using namespace nvcuda;

#define NROWS 65536
#define HDIM  512
#define MD    128
#define PROTO 12
#define KR    1408
#define KF    2048
#define RSCALE 0.2f

typedef __nv_bfloat16 bf16;

// ---------------- scratch (device globals; allocation-free) ----------------
__device__ __align__(1024) __half g_A1 [(size_t)NROWS * KR];      // fp16(router input)
__device__ __align__(1024) __half g_B0 [(size_t)KR * HDIM];       // hi fp16(rw1)
__device__ __align__(1024) __half g_B1 [(size_t)KR * HDIM];       // lo fp16(rw1 - hi)
__device__ __align__(16)   float g_H1  [(size_t)NROWS * HDIM];
__device__ __align__(1024) bf16  g_FEATSH[(size_t)NROWS * KF];
__device__ __align__(16)   float g_H12 [(size_t)NROWS * 1024];
__device__ __align__(1024) bf16  g_HMUH[(size_t)NROWS * HDIM];
__device__ __align__(1024) bf16  g_HMGH[(size_t)NROWS * HDIM];
__device__ __align__(16)   float g_DELTA[(size_t)NROWS * HDIM];
__device__ __align__(16)   float g_GATE [(size_t)NROWS * HDIM];
__device__ __align__(1024) bf16  g_W1  [(size_t)KF * 1024];
__device__ __align__(1024) bf16  g_W2MU[(size_t)HDIM * HDIM];
__device__ __align__(1024) bf16  g_W2MG[(size_t)HDIM * HDIM];
__device__ __align__(16)   float g_W2T [(size_t)PROTO * HDIM];
__device__ int g_count;
__device__ int g_LIST[NROWS];

// ---------------- helpers ----------------
__device__ __forceinline__ float gelu_exact(float x) {
    return 0.5f * x * (1.0f + erff(x * 0.70710678118654752440f));
}
__device__ __forceinline__ float2 block_sum2_128(float s1, float s2, float2* sb) {
    #pragma unroll
    for (int o = 16; o; o >>= 1) {
        s1 += __shfl_xor_sync(0xffffffffu, s1, o);
        s2 += __shfl_xor_sync(0xffffffffu, s2, o);
    }
    int w = threadIdx.x >> 5;
    if ((threadIdx.x & 31) == 0) sb[w] = make_float2(s1, s2);
    __syncthreads();
    float2 r = make_float2(sb[0].x + sb[1].x + sb[2].x + sb[3].x,
                           sb[0].y + sb[1].y + sb[2].y + sb[3].y);
    __syncthreads();
    return r;
}
__device__ __forceinline__ double block_sum_128d(double v, double* sbuf) {
    #pragma unroll
    for (int o = 16; o; o >>= 1) v += __shfl_xor_sync(0xffffffffu, v, o);
    int w = threadIdx.x >> 5;
    if ((threadIdx.x & 31) == 0) sbuf[w] = v;
    __syncthreads();
    double r = sbuf[0] + sbuf[1] + sbuf[2] + sbuf[3];
    __syncthreads();
    return r;
}
__device__ __forceinline__ void twosum_acc(float& sum, float& comp, float v) {
    float s = sum + v;
    float z = s - sum;
    float e = (sum - (s - z)) + (v - z);
    sum = s;
    comp += e;
}
__device__ __forceinline__ void cp16(uint32_t dst, const void* src) {
    asm volatile("cp.async.cg.shared.global [%0], [%1], 16;" :: "r"(dst), "l"(src) : "memory");
}
__device__ __forceinline__ uint32_t smem_u32(const void* p) {
    uint32_t a;
    asm("{ .reg .u64 t; cvta.to.shared.u64 t, %1; cvt.u32.u64 %0, t; }" : "=r"(a) : "l"(p));
    return a;
}
#define CP_COMMIT() asm volatile("cp.async.commit_group;" ::: "memory")

__device__ __forceinline__ unsigned pack_bf2(float a, float b) {
    return ((unsigned)__bfloat16_as_ushort(__float2bfloat16_rn(b)) << 16)
         |  (unsigned)__bfloat16_as_ushort(__float2bfloat16_rn(a));
}
__device__ __forceinline__ void st_bf4(bf16* p, float4 v) {
    uint2 u;
    u.x = pack_bf2(v.x, v.y);
    u.y = pack_bf2(v.z, v.w);
    *reinterpret_cast<uint2*>(p) = u;
}

// ---------------- k_prep ----------------
__global__ void k_prep(const float* __restrict__ rw1, const float* __restrict__ rw2,
                       const float* __restrict__ muw1, const float* __restrict__ mgw1,
                       const float* __restrict__ muw2, const float* __restrict__ mgw2) {
    int gtid = blockIdx.x * blockDim.x + threadIdx.x;
    int gs = blockDim.x * gridDim.x;
    if (gtid == 0) g_count = 0;
    for (int i = gtid; i < KR * HDIM; i += gs) {
        float v = rw1[i];
        __half h0 = __float2half_rn(v);
        __half h1 = __float2half_rn(v - __half2float(h0));
        g_B0[i] = h0; g_B1[i] = h1;
    }
    for (int i = gtid; i < KF * HDIM; i += gs) {
        int k = i / HDIM, c = i - k * HDIM;
        g_W1[(size_t)k * 1024 + c]       = __float2bfloat16_rn(muw1[i]);
        g_W1[(size_t)k * 1024 + 512 + c] = __float2bfloat16_rn(mgw1[i]);
    }
    for (int i = gtid; i < HDIM * HDIM; i += gs) {
        g_W2MU[i] = __float2bfloat16_rn(muw2[i]);
        g_W2MG[i] = __float2bfloat16_rn(mgw2[i]);
    }
    for (int i = gtid; i < PROTO * HDIM; i += gs) {
        int l = i / HDIM, c = i - l * HDIM;
        g_W2T[i] = rw2[(size_t)c * PROTO + l];
    }
}

// ---------------- gather -> fp16 router input ---------------------------------
__global__ void k_gather_split(const float* __restrict__ pair, const float* __restrict__ ep,
                               const int* __restrict__ sid, const int* __restrict__ hc,
                               const int* __restrict__ ps,
                               const float* __restrict__ se, const float* __restrict__ he,
                               const float* __restrict__ soe) {
    int row = blockIdx.x;
    int s = min(max(sid[row], 0), 2048);
    int h = min(max(hc[row], 0), 9);
    int p = min(max(ps[row], 0), 7);
    const float4* pr  = reinterpret_cast<const float4*>(&pair[(size_t)row * HDIM]);
    const float4* er  = reinterpret_cast<const float4*>(&ep[(size_t)row * HDIM]);
    const float4* sev = reinterpret_cast<const float4*>(&se[s * MD]);
    const float4* hev = reinterpret_cast<const float4*>(&he[h * MD]);
    const float4* sov = reinterpret_cast<const float4*>(&soe[p * MD]);
    __half* dst = &g_A1[(size_t)row * KR];
    for (int v = threadIdx.x; v < KR / 4; v += blockDim.x) {
        float4 f;
        if      (v < 128) f = pr[v];
        else if (v < 256) f = er[v - 128];
        else if (v < 288) f = sev[v - 256];
        else if (v < 320) f = hev[v - 288];
        else              f = sov[v - 320];
        uint2 u;
        u.x = ((unsigned)__half_as_ushort(__float2half_rn(f.y)) << 16)
            |  (unsigned)__half_as_ushort(__float2half_rn(f.x));
        u.y = ((unsigned)__half_as_ushort(__float2half_rn(f.w)) << 16)
            |  (unsigned)__half_as_ushort(__float2half_rn(f.z));
        *reinterpret_cast<uint2*>(dst + 4 * v) = u;
    }
}

// ---------------- router GEMM: 2-term fp16 (A single, B 2-level) --------------
// C[M,512] = A@B0 + A@B1 ; tile 128x128, BK=32, cp.async double-buffered.
// smem stage (half units): As[128][40]=5120, B0s[32][136]=4352, B1s[32][136]=4352
#define R2_A  5120
#define R2_B  4352
#define R2_ST (R2_A + 2 * R2_B)   // 13824 half = 27648 B

__global__ void __launch_bounds__(256) gemm_router2(float* __restrict__ C) {
    extern __shared__ __align__(16) __half sm[];
    const int tid  = threadIdx.x;
    const int warp = tid >> 5;
    const int wr   = warp >> 1;
    const int wc   = warp & 1;
    const int m0 = blockIdx.y * 128;
    const int n0 = blockIdx.x * 128;
    const uint32_t smb = smem_u32(sm);

    wmma::fragment<wmma::accumulator, 16, 16, 16, float> acc[2][4];
    #pragma unroll
    for (int i = 0; i < 2; i++)
        #pragma unroll
        for (int j = 0; j < 4; j++) wmma::fill_fragment(acc[i][j], 0.0f);

    const __half* Ab = g_A1 + (size_t)m0 * KR;

    auto load_stage = [&](int st, int kt) {
        uint32_t sb = smb + st * R2_ST * 2;   // byte address
        // A: 128x32 half = 512 x 16B
        #pragma unroll
        for (int q = 0; q < 2; q++) {
            int idx = tid + q * 256;
            int row = idx >> 2, c8 = (idx & 3) << 3;
            cp16(sb + row * 80 + c8 * 2, Ab + (size_t)row * KR + kt + c8);
        }
        // B0, B1: 32x128 half each = 512 x 16B each
        #pragma unroll
        for (int q = 0; q < 2; q++) {
            int idx = tid + q * 256;
            int row = idx >> 4, c8 = (idx & 15) << 3;
            cp16(sb + R2_A * 2 + row * 272 + c8 * 2,
                 g_B0 + (size_t)(kt + row) * HDIM + n0 + c8);
        }
        #pragma unroll
        for (int q = 0; q < 2; q++) {
            int idx = tid + q * 256;
            int row = idx >> 4, c8 = (idx & 15) << 3;
            cp16(sb + (R2_A + R2_B) * 2 + row * 272 + c8 * 2,
                 g_B1 + (size_t)(kt + row) * HDIM + n0 + c8);
        }
        CP_COMMIT();
    };

    load_stage(0, 0);
    load_stage(1, 32);

    const int nch = KR / 32;   // 44
    for (int i = 0; i < nch; i++) {
        int s = i & 1;
        if (i == nch - 1) asm volatile("cp.async.wait_group 0;" ::: "memory");
        else              asm volatile("cp.async.wait_group 1;" ::: "memory");
        __syncthreads();
        const __half* As  = sm + s * R2_ST;
        const __half* B0s = As + R2_A;
        const __half* B1s = B0s + R2_B;
        #pragma unroll
        for (int ks = 0; ks < 32; ks += 16) {
            wmma::fragment<wmma::matrix_a, 16, 16, 16, __half, wmma::row_major> a0[2];
            wmma::fragment<wmma::matrix_b, 16, 16, 16, __half, wmma::row_major> b0[4], b1[4];
            #pragma unroll
            for (int ii = 0; ii < 2; ii++)
                wmma::load_matrix_sync(a0[ii], As + (wr * 32 + ii * 16) * 40 + ks, 40);
            #pragma unroll
            for (int jj = 0; jj < 4; jj++) {
                wmma::load_matrix_sync(b0[jj], B0s + ks * 136 + wc * 64 + jj * 16, 136);
                wmma::load_matrix_sync(b1[jj], B1s + ks * 136 + wc * 64 + jj * 16, 136);
            }
            #pragma unroll
            for (int ii = 0; ii < 2; ii++)
                #pragma unroll
                for (int jj = 0; jj < 4; jj++) {
                    wmma::mma_sync(acc[ii][jj], a0[ii], b0[jj], acc[ii][jj]);
                    wmma::mma_sync(acc[ii][jj], a0[ii], b1[jj], acc[ii][jj]);
                }
        }
        __syncthreads();
        if (i + 2 < nch) load_stage(s, (i + 2) * 32);
    }

    #pragma unroll
    for (int ii = 0; ii < 2; ii++)
        #pragma unroll
        for (int jj = 0; jj < 4; jj++) {
            float* Cp = C + (size_t)(m0 + wr * 32 + ii * 16) * HDIM + n0 + wc * 64 + jj * 16;
            wmma::store_matrix_sync(Cp, acc[ii][jj], HDIM, wmma::mem_row_major);
        }
}

// ---------------- bf16 GEMM with cp.async double buffering --------------------
__global__ void __launch_bounds__(256) gemm_bf16(const bf16* __restrict__ A,
                                                 const bf16* __restrict__ B,
                                                 float* __restrict__ C,
                                                 int K, int NC) {
    __shared__ __align__(16) bf16 As[2][128][40];
    __shared__ __align__(16) bf16 Bs[2][32][136];
    const int m0 = blockIdx.y * 128;
    const int n0 = blockIdx.x * 128;
    const int tid  = threadIdx.x;
    const int warp = tid >> 5;
    const int wr   = warp >> 1;
    const int wc   = warp & 1;
    const uint32_t sa = smem_u32(&As[0][0][0]);
    const uint32_t sbb = smem_u32(&Bs[0][0][0]);

    wmma::fragment<wmma::accumulator, 16, 16, 16, float> acc[2][4];
    #pragma unroll
    for (int i = 0; i < 2; i++)
        #pragma unroll
        for (int j = 0; j < 4; j++) wmma::fill_fragment(acc[i][j], 0.0f);

    auto load_stage = [&](int st, int kt) {
        uint32_t ab = sa + st * (128 * 40 * 2);
        uint32_t bb = sbb + st * (32 * 136 * 2);
        #pragma unroll
        for (int q = 0; q < 2; q++) {
            int idx = tid + q * 256;
            int row = idx >> 2, c8 = (idx & 3) << 3;
            cp16(ab + row * 80 + c8 * 2, A + (size_t)(m0 + row) * K + kt + c8);
        }
        #pragma unroll
        for (int q = 0; q < 2; q++) {
            int idx = tid + q * 256;
            int row = idx >> 4, c8 = (idx & 15) << 3;
            cp16(bb + row * 272 + c8 * 2, B + (size_t)(kt + row) * NC + n0 + c8);
        }
        CP_COMMIT();
    };

    load_stage(0, 0);
    load_stage(1, 32);

    const int nch = K / 32;
    for (int i = 0; i < nch; i++) {
        int s = i & 1;
        if (i == nch - 1) asm volatile("cp.async.wait_group 0;" ::: "memory");
        else              asm volatile("cp.async.wait_group 1;" ::: "memory");
        __syncthreads();
        #pragma unroll
        for (int ks = 0; ks < 32; ks += 16) {
            wmma::fragment<wmma::matrix_a, 16, 16, 16, bf16, wmma::row_major> af[2];
            wmma::fragment<wmma::matrix_b, 16, 16, 16, bf16, wmma::row_major> bfr[4];
            #pragma unroll
            for (int ii = 0; ii < 2; ii++)
                wmma::load_matrix_sync(af[ii], &As[s][wr * 32 + ii * 16][ks], 40);
            #pragma unroll
            for (int jj = 0; jj < 4; jj++)
                wmma::load_matrix_sync(bfr[jj], &Bs[s][ks][wc * 64 + jj * 16], 136);
            #pragma unroll
            for (int ii = 0; ii < 2; ii++)
                #pragma unroll
                for (int jj = 0; jj < 4; jj++)
                    wmma::mma_sync(acc[ii][jj], af[ii], bfr[jj], acc[ii][jj]);
        }
        __syncthreads();
        if (i + 2 < nch) load_stage(s, (i + 2) * 32);
    }

    #pragma unroll
    for (int i = 0; i < 2; i++)
        #pragma unroll
        for (int j = 0; j < 4; j++) {
            float* Cp = C + (size_t)(m0 + wr * 32 + i * 16) * NC + n0 + wc * 64 + j * 16;
            wmma::store_matrix_sync(Cp, acc[i][j], NC, wmma::mem_row_major);
        }
}

// ---------------- router2: fp32 single-pass LN + plain dot --------------------
__global__ void k_router2(const float* __restrict__ ep,
                          const float* __restrict__ rb1, const float* __restrict__ rlg,
                          const float* __restrict__ rlb,
                          const float* __restrict__ b2, const float* __restrict__ proto,
                          float* __restrict__ outC, float* __restrict__ outW) {
    __shared__ float sh[HDIM];
    __shared__ float2 sb2[4];
    __shared__ float sl[PROTO];
    __shared__ float sw[PROTO];
    int row = blockIdx.x, t = threadIdx.x;    // 128 threads
    const float4 h4 = reinterpret_cast<const float4*>(&g_H1[(size_t)row * HDIM])[t];
    const float4 b4 = reinterpret_cast<const float4*>(rb1)[t];
    float4 pre = make_float4(h4.x + b4.x, h4.y + b4.y, h4.z + b4.z, h4.w + b4.w);
    float s1 = pre.x + pre.y + pre.z + pre.w;
    float s2 = pre.x * pre.x + pre.y * pre.y + pre.z * pre.z + pre.w * pre.w;
    float2 r = block_sum2_128(s1, s2, sb2);
    float mean = r.x * (1.0f / 512.0f);
    float var  = r.y * (1.0f / 512.0f) - mean * mean;
    float rs = rsqrtf(var + 1e-5f);
    const float4 g4  = reinterpret_cast<const float4*>(rlg)[t];
    const float4 be4 = reinterpret_cast<const float4*>(rlb)[t];
    float4 hv;
    hv.x = gelu_exact((pre.x - mean) * rs * g4.x + be4.x);
    hv.y = gelu_exact((pre.y - mean) * rs * g4.y + be4.y);
    hv.z = gelu_exact((pre.z - mean) * rs * g4.z + be4.z);
    hv.w = gelu_exact((pre.w - mean) * rs * g4.w + be4.w);
    reinterpret_cast<float4*>(sh)[t] = hv;
    __syncthreads();
    int warp = t >> 5, lane = t & 31;
    #pragma unroll
    for (int q = 0; q < 3; q++) {
        int l = warp * 3 + q;
        const float* wl = &g_W2T[l * HDIM];
        float sa = 0.0f, sb = 0.0f;
        #pragma unroll
        for (int c = 0; c < HDIM; c += 64) {
            sa = fmaf(sh[c + lane],      wl[c + lane],      sa);
            sb = fmaf(sh[c + lane + 32], wl[c + lane + 32], sb);
        }
        sa += sb;
        #pragma unroll
        for (int o = 16; o; o >>= 1) sa += __shfl_xor_sync(0xffffffffu, sa, o);
        if (lane == 0) sl[l] = sa + b2[l];
    }
    __syncthreads();
    if (t == 0) {
        float v[PROTO];
        #pragma unroll
        for (int i = 0; i < PROTO; i++) v[i] = sl[i];
        float top5[5];
        #pragma unroll
        for (int k = 0; k < 5; k++) {
            int bi = 0; float bv = -1e30f;
            #pragma unroll
            for (int i = 0; i < PROTO; i++)
                if (v[i] > bv) { bv = v[i]; bi = i; }
            top5[k] = bv; v[bi] = -1e30f;
        }
        if (top5[3] - top5[4] < 2e-3f) {
            int pos = atomicAdd(&g_count, 1);
            g_LIST[pos] = row;
        }
        float w[PROTO];
        float mx = -1e30f;
        #pragma unroll
        for (int i = 0; i < PROTO; i++) mx = fmaxf(mx, sl[i]);
        float ssum = 0.0f;
        #pragma unroll
        for (int i = 0; i < PROTO; i++) { w[i] = expf(sl[i] - mx); ssum += w[i]; }
        float inv = 1.0f / ssum;
        #pragma unroll
        for (int i = 0; i < PROTO; i++) w[i] *= inv;
        bool sel[PROTO];
        #pragma unroll
        for (int i = 0; i < PROTO; i++) sel[i] = false;
        for (int k = 0; k < 4; k++) {
            int bi = -1; float bv = -1e30f;
            #pragma unroll
            for (int i = 0; i < PROTO; i++)
                if (!sel[i] && w[i] > bv) { bv = w[i]; bi = i; }
            sel[bi] = true;
        }
        float s22 = 0.0f;
        #pragma unroll
        for (int i = 0; i < PROTO; i++) { float vv = sel[i] ? w[i] : 0.0f; sw[i] = vv; s22 += vv; }
        float d = 1.0f / fmaxf(s22, 1e-6f);
        #pragma unroll
        for (int i = 0; i < PROTO; i++) sw[i] *= d;
    }
    __syncthreads();
    if (t < PROTO) outW[(size_t)row * PROTO + t] = sw[t];
    const float4 e4 = reinterpret_cast<const float4*>(&ep[(size_t)row * HDIM])[t];
    float4 c4 = make_float4(0.f, 0.f, 0.f, 0.f);
    #pragma unroll
    for (int p = 0; p < PROTO; p++) {
        float wv = sw[p];
        const float4 p4 = reinterpret_cast<const float4*>(&proto[p * HDIM])[t];
        c4.x = fmaf(wv, p4.x, c4.x);
        c4.y = fmaf(wv, p4.y, c4.y);
        c4.z = fmaf(wv, p4.z, c4.z);
        c4.w = fmaf(wv, p4.w, c4.w);
    }
    reinterpret_cast<float4*>(&outC[(size_t)row * HDIM])[t] = c4;
    bf16* frow = &g_FEATSH[(size_t)row * KF];
    st_bf4(frow + 4 * t, e4);
    st_bf4(frow + 512 + 4 * t, c4);
    st_bf4(frow + 1024 + 4 * t, make_float4(fabsf(e4.x - c4.x), fabsf(e4.y - c4.y),
                                            fabsf(e4.z - c4.z), fabsf(e4.w - c4.w)));
    st_bf4(frow + 1536 + 4 * t, make_float4(e4.x * c4.x, e4.y * c4.y,
                                            e4.z * c4.z, e4.w * c4.w));
}

// ---------------- rescue (exact fp32 path, unchanged) -------------------------
__global__ void __launch_bounds__(128) k_rescue(
        const float* __restrict__ pair, const float* __restrict__ ep,
        const int* __restrict__ sid, const int* __restrict__ hc, const int* __restrict__ ps,
        const float* __restrict__ se, const float* __restrict__ he, const float* __restrict__ soe,
        const float* __restrict__ rw1, const float* __restrict__ rb1,
        const float* __restrict__ rlg, const float* __restrict__ rlb,
        const float* __restrict__ b2, const float* __restrict__ proto,
        float* __restrict__ outC, float* __restrict__ outW) {
    __shared__ float sa[KR];
    __shared__ float shd[HDIM];
    __shared__ double dbuf[4];
    __shared__ float sl[PROTO];
    __shared__ float sw[PROTO];
    int t = threadIdx.x, warp = t >> 5, lane = t & 31;
    int cnt = g_count;
    for (int li = blockIdx.x; li < cnt; li += gridDim.x) {
        int row = g_LIST[li];
        int s = min(max(sid[row], 0), 2048);
        int h = min(max(hc[row], 0), 9);
        int p = min(max(ps[row], 0), 7);
        const float* pr = &pair[(size_t)row * HDIM];
        const float* er = &ep[(size_t)row * HDIM];
        for (int k = t; k < KR; k += 128) {
            float v;
            if      (k < 512)  v = pr[k];
            else if (k < 1024) v = er[k - 512];
            else if (k < 1152) v = se[s * MD + (k - 1024)];
            else if (k < 1280) v = he[h * MD + (k - 1152)];
            else               v = soe[p * MD + (k - 1280)];
            sa[k] = v;
        }
        __syncthreads();
        float hs[4], hcmp[4];
        #pragma unroll
        for (int j = 0; j < 4; j++) { hs[j] = 0.0f; hcmp[j] = 0.0f; }
        for (int k = 0; k < KR; k++) {
            float a = sa[k];
            const float* wr = &rw1[(size_t)k * HDIM];
            #pragma unroll
            for (int j = 0; j < 4; j++) {
                int c = t + j * 128;
                float w = wr[c];
                float pp = a * w;
                float pe = fmaf(a, w, -pp);
                twosum_acc(hs[j], hcmp[j], pp);
                hcmp[j] += pe;
            }
        }
        float pre[4];
        double msum = 0.0;
        #pragma unroll
        for (int j = 0; j < 4; j++) {
            pre[j] = (hs[j] + hcmp[j]) + rb1[t + j * 128];
            msum += (double)pre[j];
        }
        double mean = block_sum_128d(msum, dbuf) * (1.0 / 512.0);
        double vsum = 0.0;
        #pragma unroll
        for (int j = 0; j < 4; j++) {
            double e0 = (double)pre[j] - mean;
            vsum += e0 * e0;
        }
        double var = block_sum_128d(vsum, dbuf) * (1.0 / 512.0);
        float rs = (float)(1.0 / sqrt(var + 1e-5));
        #pragma unroll
        for (int j = 0; j < 4; j++) {
            int c = t + j * 128;
            shd[c] = gelu_exact((float)((double)pre[j] - mean) * rs * rlg[c] + rlb[c]);
        }
        __syncthreads();
        for (int l = warp; l < PROTO; l += 4) {
            float ss = 0.0f, cmp = 0.0f;
            const float* wl = &g_W2T[l * HDIM];
            for (int c = lane; c < HDIM; c += 32) {
                float a = shd[c], w = wl[c];
                float pp = a * w;
                float pe = fmaf(a, w, -pp);
                twosum_acc(ss, cmp, pp);
                cmp += pe;
            }
            #pragma unroll
            for (int o = 16; o; o >>= 1) {
                ss  += __shfl_xor_sync(0xffffffffu, ss, o);
                cmp += __shfl_xor_sync(0xffffffffu, cmp, o);
            }
            if (lane == 0) sl[l] = (ss + cmp) + b2[l];
        }
        __syncthreads();
        if (t == 0) {
            float w[PROTO];
            float mx = -1e30f;
            #pragma unroll
            for (int i = 0; i < PROTO; i++) mx = fmaxf(mx, sl[i]);
            float ssum = 0.0f;
            #pragma unroll
            for (int i = 0; i < PROTO; i++) { w[i] = expf(sl[i] - mx); ssum += w[i]; }
            float inv = 1.0f / ssum;
            #pragma unroll
            for (int i = 0; i < PROTO; i++) w[i] *= inv;
            bool sel[PROTO];
            #pragma unroll
            for (int i = 0; i < PROTO; i++) sel[i] = false;
            for (int k = 0; k < 4; k++) {
                int bi = -1; float bv = -1e30f;
                #pragma unroll
                for (int i = 0; i < PROTO; i++)
                    if (!sel[i] && w[i] > bv) { bv = w[i]; bi = i; }
                sel[bi] = true;
            }
            float s2 = 0.0f;
            #pragma unroll
            for (int i = 0; i < PROTO; i++) { float vv = sel[i] ? w[i] : 0.0f; sw[i] = vv; s2 += vv; }
            float d = 1.0f / fmaxf(s2, 1e-6f);
            #pragma unroll
            for (int i = 0; i < PROTO; i++) sw[i] *= d;
        }
        __syncthreads();
        if (t < PROTO) outW[(size_t)row * PROTO + t] = sw[t];
        bf16* frow = &g_FEATSH[(size_t)row * KF];
        for (int j = t; j < HDIM; j += 128) {
            float c = 0.0f;
            #pragma unroll
            for (int pp = 0; pp < PROTO; pp++) c += sw[pp] * proto[pp * HDIM + j];
            float e = er[j];
            outC[(size_t)row * HDIM + j] = c;
            frow[j]        = __float2bfloat16_rn(e);
            frow[512 + j]  = __float2bfloat16_rn(c);
            frow[1024 + j] = __float2bfloat16_rn(fabsf(e - c));
            frow[1536 + j] = __float2bfloat16_rn(e * c);
        }
        __syncthreads();
    }
}

// ---------------- activations (float4, single-pass LN) ------------------------
__global__ void k_act(const float* __restrict__ b_mu, const float* __restrict__ g_mu,
                      const float* __restrict__ be_mu, const float* __restrict__ b_mg) {
    __shared__ float2 sb2[4];
    int row = blockIdx.x, t = threadIdx.x;
    const float4* h12 = reinterpret_cast<const float4*>(&g_H12[(size_t)row * 1024]);
    const float4 m4i = h12[t];
    const float4 b4 = reinterpret_cast<const float4*>(b_mu)[t];
    float4 m4 = make_float4(m4i.x + b4.x, m4i.y + b4.y, m4i.z + b4.z, m4i.w + b4.w);
    float s1 = m4.x + m4.y + m4.z + m4.w;
    float s2 = m4.x * m4.x + m4.y * m4.y + m4.z * m4.z + m4.w * m4.w;
    float2 r = block_sum2_128(s1, s2, sb2);
    float mean = r.x * (1.0f / 512.0f);
    float var  = r.y * (1.0f / 512.0f) - mean * mean;
    float rs = rsqrtf(var + 1e-5f);
    const float4 g4  = reinterpret_cast<const float4*>(g_mu)[t];
    const float4 be4 = reinterpret_cast<const float4*>(be_mu)[t];
    float4 xm;
    xm.x = gelu_exact((m4.x - mean) * rs * g4.x + be4.x);
    xm.y = gelu_exact((m4.y - mean) * rs * g4.y + be4.y);
    xm.z = gelu_exact((m4.z - mean) * rs * g4.z + be4.z);
    xm.w = gelu_exact((m4.w - mean) * rs * g4.w + be4.w);
    st_bf4(&g_HMUH[(size_t)row * HDIM] + 4 * t, xm);
    const float4 gg4i = h12[128 + t];
    const float4 bg4 = reinterpret_cast<const float4*>(b_mg)[t];
    float4 xg;
    xg.x = gelu_exact(gg4i.x + bg4.x);
    xg.y = gelu_exact(gg4i.y + bg4.y);
    xg.z = gelu_exact(gg4i.z + bg4.z);
    xg.w = gelu_exact(gg4i.w + bg4.w);
    st_bf4(&g_HMGH[(size_t)row * HDIM] + 4 * t, xg);
}

// ---------------- final (float4, single-pass LN) ------------------------------
__global__ void k_final(const float* __restrict__ ep, const float* __restrict__ mub2,
                        const float* __restrict__ mgb2, const float* __restrict__ ng,
                        const float* __restrict__ nb, float* __restrict__ outU) {
    __shared__ float2 sb2[4];
    int row = blockIdx.x, t = threadIdx.x;
    const float4 e4 = reinterpret_cast<const float4*>(&ep[(size_t)row * HDIM])[t];
    const float4 d4 = reinterpret_cast<const float4*>(&g_DELTA[(size_t)row * HDIM])[t];
    const float4 gp4 = reinterpret_cast<const float4*>(&g_GATE[(size_t)row * HDIM])[t];
    const float4 db4 = reinterpret_cast<const float4*>(mub2)[t];
    const float4 gb4 = reinterpret_cast<const float4*>(mgb2)[t];
    float4 u;
    u.x = e4.x + RSCALE * (1.0f / (1.0f + expf(-(gp4.x + gb4.x)))) * (d4.x + db4.x);
    u.y = e4.y + RSCALE * (1.0f / (1.0f + expf(-(gp4.y + gb4.y)))) * (d4.y + db4.y);
    u.z = e4.z + RSCALE * (1.0f / (1.0f + expf(-(gp4.z + gb4.z)))) * (d4.z + db4.z);
    u.w = e4.w + RSCALE * (1.0f / (1.0f + expf(-(gp4.w + gb4.w)))) * (d4.w + db4.w);
    float s1 = u.x + u.y + u.z + u.w;
    float s2 = u.x * u.x + u.y * u.y + u.z * u.z + u.w * u.w;
    float2 r = block_sum2_128(s1, s2, sb2);
    float mean = r.x * (1.0f / 512.0f);
    float var  = r.y * (1.0f / 512.0f) - mean * mean;
    float rs = rsqrtf(var + 1e-5f);
    const float4 g4 = reinterpret_cast<const float4*>(ng)[t];
    const float4 b4 = reinterpret_cast<const float4*>(nb)[t];
    float4 o;
    o.x = (u.x - mean) * rs * g4.x + b4.x;
    o.y = (u.y - mean) * rs * g4.y + b4.y;
    o.z = (u.z - mean) * rs * g4.z + b4.z;
    o.w = (u.w - mean) * rs * g4.w + b4.w;
    reinterpret_cast<float4*>(&outU[(size_t)row * HDIM])[t] = o;
}

// ---------------- launch ----------------
extern "C" void kernel_launch(void* const* d_in, const int* in_sizes, int n_in,
                              void* d_out, int out_size) {
    const float* pair = (const float*)d_in[0];
    const float* ep   = (const float*)d_in[1];
    const int*   sid  = (const int*)d_in[2];
    const int*   hc   = (const int*)d_in[3];
    const int*   ps   = (const int*)d_in[4];
    const float* se   = (const float*)d_in[5];
    const float* he   = (const float*)d_in[6];
    const float* soe  = (const float*)d_in[7];
    const float* proto= (const float*)d_in[8];
    const float* rw1  = (const float*)d_in[9];
    const float* rb1  = (const float*)d_in[10];
    const float* rlg  = (const float*)d_in[11];
    const float* rlb  = (const float*)d_in[12];
    const float* rw2  = (const float*)d_in[13];
    const float* rb2  = (const float*)d_in[14];
    const float* muw1 = (const float*)d_in[15];
    const float* mub1 = (const float*)d_in[16];
    const float* mulg = (const float*)d_in[17];
    const float* mulb = (const float*)d_in[18];
    const float* muw2 = (const float*)d_in[19];
    const float* mub2 = (const float*)d_in[20];
    const float* mgw1 = (const float*)d_in[21];
    const float* mgb1 = (const float*)d_in[22];
    const float* mgw2 = (const float*)d_in[23];
    const float* mgb2 = (const float*)d_in[24];
    const float* ng   = (const float*)d_in[25];
    const float* nb   = (const float*)d_in[26];

    float* outU = (float*)d_out;
    float* outC = outU + (size_t)NROWS * HDIM;
    float* outW = outC + (size_t)NROWS * HDIM;

    float *pH1, *pH12, *pDELTA, *pGATE;
    bf16 *pFEATSH, *pHMUH, *pHMGH, *pW1, *pW2MU, *pW2MG;
    cudaGetSymbolAddress((void**)&pH1,     g_H1);
    cudaGetSymbolAddress((void**)&pH12,    g_H12);
    cudaGetSymbolAddress((void**)&pDELTA,  g_DELTA);
    cudaGetSymbolAddress((void**)&pGATE,   g_GATE);
    cudaGetSymbolAddress((void**)&pFEATSH, g_FEATSH);
    cudaGetSymbolAddress((void**)&pHMUH,   g_HMUH);
    cudaGetSymbolAddress((void**)&pHMGH,   g_HMGH);
    cudaGetSymbolAddress((void**)&pW1,     g_W1);
    cudaGetSymbolAddress((void**)&pW2MU,   g_W2MU);
    cudaGetSymbolAddress((void**)&pW2MG,   g_W2MG);

    static bool attr_set = false;
    if (!attr_set) {
        cudaFuncSetAttribute(gemm_router2, cudaFuncAttributeMaxDynamicSharedMemorySize,
                             2 * R2_ST * 2 + 256);
        attr_set = true;
    }

    k_prep<<<4096, 256>>>(rw1, rw2, muw1, mgw1, muw2, mgw2);
    k_gather_split<<<NROWS, 128>>>(pair, ep, sid, hc, ps, se, he, soe);
    {
        dim3 grid(HDIM / 128, NROWS / 128);
        gemm_router2<<<grid, 256, 2 * R2_ST * 2 + 256>>>(pH1);
    }
    k_router2<<<NROWS, 128>>>(ep, rb1, rlg, rlb, rb2, proto, outC, outW);
    k_rescue<<<2048, 128>>>(pair, ep, sid, hc, ps, se, he, soe,
                            rw1, rb1, rlg, rlb, rb2, proto, outC, outW);
    {
        dim3 grid(1024 / 128, NROWS / 128);
        gemm_bf16<<<grid, 256>>>(pFEATSH, pW1, pH12, KF, 1024);
    }
    k_act<<<NROWS, 128>>>(mub1, mulg, mulb, mgb1);
    {
        dim3 grid(HDIM / 128, NROWS / 128);
        gemm_bf16<<<grid, 256>>>(pHMUH, pW2MU, pDELTA, HDIM, HDIM);
        gemm_bf16<<<grid, 256>>>(pHMGH, pW2MG, pGATE, HDIM, HDIM);
    }
    k_final<<<NROWS, 128>>>(ep, mub2, mgb2, ng, nb, outU);
}

// round 11
// speedup vs baseline: 4.3989x; 1.1331x over previous
#include <cuda_runtime.h>
#include <cuda_bf16.h>
#include <cuda_fp16.h>
#include <mma.h>
#include <math.h>
#include <stdint.h>

using namespace nvcuda;

#define NROWS 65536
#define HDIM  512
#define MD    128
#define PROTO 12
#define KR    1408     // full router K (rescue path)
#define KRR   1024     // fast-path router K (pair|ep only)
#define KFN   1568     // feats K: ep(512) + |d|(512) + ep*ctx(512) + w(12) + pad(20)
#define RSCALE 0.2f

typedef __nv_bfloat16 bf16;

// ---------------- scratch (device globals; allocation-free) ----------------
__device__ __align__(1024) __half g_A1 [(size_t)NROWS * KRR];
__device__ __align__(1024) __half g_B0 [(size_t)KRR * HDIM];
__device__ __align__(1024) __half g_B1 [(size_t)KRR * HDIM];
__device__ __align__(16)   float g_TS  [(size_t)2049 * HDIM];
__device__ __align__(16)   float g_TH  [(size_t)10 * HDIM];
__device__ __align__(16)   float g_TP  [(size_t)8 * HDIM];
__device__ __align__(16)   float g_H1  [(size_t)NROWS * HDIM];
__device__ __align__(1024) bf16  g_FEATSH[(size_t)NROWS * KFN];
__device__ __align__(16)   float g_H12 [(size_t)NROWS * 1024];
__device__ __align__(1024) bf16  g_HMUH[(size_t)NROWS * HDIM];
__device__ __align__(1024) bf16  g_HMGH[(size_t)NROWS * HDIM];
__device__ __align__(16)   float g_DELTA[(size_t)NROWS * HDIM];
__device__ __align__(16)   float g_GATE [(size_t)NROWS * HDIM];
__device__ __align__(1024) bf16  g_W1  [(size_t)KFN * 1024];
__device__ __align__(1024) bf16  g_W2MU[(size_t)HDIM * HDIM];
__device__ __align__(1024) bf16  g_W2MG[(size_t)HDIM * HDIM];
__device__ __align__(16)   float g_W2T [(size_t)PROTO * HDIM];
__device__ int g_count;
__device__ int g_LIST[NROWS];

// ---------------- helpers ----------------
__device__ __forceinline__ float gelu_exact(float x) {
    return 0.5f * x * (1.0f + erff(x * 0.70710678118654752440f));
}
__device__ __forceinline__ float2 block_sum2_128(float s1, float s2, float2* sb) {
    #pragma unroll
    for (int o = 16; o; o >>= 1) {
        s1 += __shfl_xor_sync(0xffffffffu, s1, o);
        s2 += __shfl_xor_sync(0xffffffffu, s2, o);
    }
    int w = threadIdx.x >> 5;
    if ((threadIdx.x & 31) == 0) sb[w] = make_float2(s1, s2);
    __syncthreads();
    float2 r = make_float2(sb[0].x + sb[1].x + sb[2].x + sb[3].x,
                           sb[0].y + sb[1].y + sb[2].y + sb[3].y);
    __syncthreads();
    return r;
}
__device__ __forceinline__ double block_sum_128d(double v, double* sbuf) {
    #pragma unroll
    for (int o = 16; o; o >>= 1) v += __shfl_xor_sync(0xffffffffu, v, o);
    int w = threadIdx.x >> 5;
    if ((threadIdx.x & 31) == 0) sbuf[w] = v;
    __syncthreads();
    double r = sbuf[0] + sbuf[1] + sbuf[2] + sbuf[3];
    __syncthreads();
    return r;
}
__device__ __forceinline__ void twosum_acc(float& sum, float& comp, float v) {
    float s = sum + v;
    float z = s - sum;
    float e = (sum - (s - z)) + (v - z);
    sum = s;
    comp += e;
}
__device__ __forceinline__ void cp16(uint32_t dst, const void* src) {
    asm volatile("cp.async.cg.shared.global [%0], [%1], 16;" :: "r"(dst), "l"(src) : "memory");
}
__device__ __forceinline__ uint32_t smem_u32(const void* p) {
    uint32_t a;
    asm("{ .reg .u64 t; cvta.to.shared.u64 t, %1; cvt.u32.u64 %0, t; }" : "=r"(a) : "l"(p));
    return a;
}
#define CP_COMMIT() asm volatile("cp.async.commit_group;" ::: "memory")

__device__ __forceinline__ unsigned pack_bf2(float a, float b) {
    return ((unsigned)__bfloat16_as_ushort(__float2bfloat16_rn(b)) << 16)
         |  (unsigned)__bfloat16_as_ushort(__float2bfloat16_rn(a));
}
__device__ __forceinline__ void st_bf4(bf16* p, float4 v) {
    uint2 u;
    u.x = pack_bf2(v.x, v.y);
    u.y = pack_bf2(v.z, v.w);
    *reinterpret_cast<uint2*>(p) = u;
}

// ---------------- k_prep: weights, tables, low-rank fold ----------------------
__global__ void k_prep(const float* __restrict__ rw1, const float* __restrict__ rw2,
                       const float* __restrict__ muw1, const float* __restrict__ mgw1,
                       const float* __restrict__ muw2, const float* __restrict__ mgw2,
                       const float* __restrict__ se, const float* __restrict__ he,
                       const float* __restrict__ soe, const float* __restrict__ proto) {
    int gtid = blockIdx.x * blockDim.x + threadIdx.x;
    int gs = blockDim.x * gridDim.x;
    if (gtid == 0) g_count = 0;
    // router B split (rows 0:1024 of rw1 only)
    for (int i = gtid; i < KRR * HDIM; i += gs) {
        float v = rw1[i];
        __half h0 = __float2half_rn(v);
        __half h1 = __float2half_rn(v - __half2float(h0));
        g_B0[i] = h0; g_B1[i] = h1;
    }
    // metadata tables: T_s/T_h/T_p = emb @ rw1[meta block]
    for (int i = gtid; i < 2049 * HDIM; i += gs) {
        int b = i >> 9, c = i & 511;
        float acc = 0.0f;
        for (int j = 0; j < MD; j++)
            acc = fmaf(se[b * MD + j], rw1[(size_t)(1024 + j) * HDIM + c], acc);
        g_TS[i] = acc;
    }
    for (int i = gtid; i < 10 * HDIM; i += gs) {
        int b = i >> 9, c = i & 511;
        float acc = 0.0f;
        for (int j = 0; j < MD; j++)
            acc = fmaf(he[b * MD + j], rw1[(size_t)(1152 + j) * HDIM + c], acc);
        g_TH[i] = acc;
    }
    for (int i = gtid; i < 8 * HDIM; i += gs) {
        int b = i >> 9, c = i & 511;
        float acc = 0.0f;
        for (int j = 0; j < MD; j++)
            acc = fmaf(soe[b * MD + j], rw1[(size_t)(1280 + j) * HDIM + c], acc);
        g_TP[i] = acc;
    }
    // W1 main: new rows 0:512 = orig 0:512 (ep), 512:1024 = orig 1024:1536 (|d|),
    //          1024:1536 = orig 1536:2048 (ep*ctx)
    for (int i = gtid; i < 1536 * HDIM; i += gs) {
        int k = i >> 9, c = i & 511;
        int ok = (k < 512) ? k : k + 512;
        g_W1[(size_t)k * 1024 + c]       = __float2bfloat16_rn(muw1[(size_t)ok * HDIM + c]);
        g_W1[(size_t)k * 1024 + 512 + c] = __float2bfloat16_rn(mgw1[(size_t)ok * HDIM + c]);
    }
    // W1 low-rank rows 1536:1568 = PW1 = proto @ W1[ctx block] (12 rows) + zero pad
    for (int i = gtid; i < 32 * 1024; i += gs) {
        int kk = i >> 10, c = i & 1023;
        float acc = 0.0f;
        if (kk < PROTO) {
            if (c < 512) {
                for (int j = 0; j < 512; j++)
                    acc = fmaf(proto[kk * HDIM + j], muw1[(size_t)(512 + j) * HDIM + c], acc);
            } else {
                for (int j = 0; j < 512; j++)
                    acc = fmaf(proto[kk * HDIM + j], mgw1[(size_t)(512 + j) * HDIM + (c - 512)], acc);
            }
        }
        g_W1[(size_t)(1536 + kk) * 1024 + c] = __float2bfloat16_rn(acc);
    }
    for (int i = gtid; i < HDIM * HDIM; i += gs) {
        g_W2MU[i] = __float2bfloat16_rn(muw2[i]);
        g_W2MG[i] = __float2bfloat16_rn(mgw2[i]);
    }
    for (int i = gtid; i < PROTO * HDIM; i += gs) {
        int l = i / HDIM, c = i - l * HDIM;
        g_W2T[i] = rw2[(size_t)c * PROTO + l];
    }
}

// ---------------- gather -> fp16 router input (pair|ep) -----------------------
__global__ void k_gather(const float* __restrict__ pair, const float* __restrict__ ep) {
    int row = blockIdx.x;
    const float4* pr = reinterpret_cast<const float4*>(&pair[(size_t)row * HDIM]);
    const float4* er = reinterpret_cast<const float4*>(&ep[(size_t)row * HDIM]);
    __half* dst = &g_A1[(size_t)row * KRR];
    for (int v = threadIdx.x; v < KRR / 4; v += blockDim.x) {
        float4 f = (v < 128) ? pr[v] : er[v - 128];
        uint2 u;
        u.x = ((unsigned)__half_as_ushort(__float2half_rn(f.y)) << 16)
            |  (unsigned)__half_as_ushort(__float2half_rn(f.x));
        u.y = ((unsigned)__half_as_ushort(__float2half_rn(f.w)) << 16)
            |  (unsigned)__half_as_ushort(__float2half_rn(f.z));
        *reinterpret_cast<uint2*>(dst + 4 * v) = u;
    }
}

// ---------------- router GEMM: 2-term fp16, K=1024 ----------------------------
#define R2_A  5120
#define R2_B  4352
#define R2_ST (R2_A + 2 * R2_B)

__global__ void __launch_bounds__(256) gemm_router2(float* __restrict__ C) {
    extern __shared__ __align__(16) __half sm[];
    const int tid  = threadIdx.x;
    const int warp = tid >> 5;
    const int wr   = warp >> 1;
    const int wc   = warp & 1;
    const int m0 = blockIdx.y * 128;
    const int n0 = blockIdx.x * 128;
    const uint32_t smb = smem_u32(sm);

    wmma::fragment<wmma::accumulator, 16, 16, 16, float> acc[2][4];
    #pragma unroll
    for (int i = 0; i < 2; i++)
        #pragma unroll
        for (int j = 0; j < 4; j++) wmma::fill_fragment(acc[i][j], 0.0f);

    const __half* Ab = g_A1 + (size_t)m0 * KRR;

    auto load_stage = [&](int st, int kt) {
        uint32_t sb = smb + st * R2_ST * 2;
        #pragma unroll
        for (int q = 0; q < 2; q++) {
            int idx = tid + q * 256;
            int row = idx >> 2, c8 = (idx & 3) << 3;
            cp16(sb + row * 80 + c8 * 2, Ab + (size_t)row * KRR + kt + c8);
        }
        #pragma unroll
        for (int q = 0; q < 2; q++) {
            int idx = tid + q * 256;
            int row = idx >> 4, c8 = (idx & 15) << 3;
            cp16(sb + R2_A * 2 + row * 272 + c8 * 2,
                 g_B0 + (size_t)(kt + row) * HDIM + n0 + c8);
        }
        #pragma unroll
        for (int q = 0; q < 2; q++) {
            int idx = tid + q * 256;
            int row = idx >> 4, c8 = (idx & 15) << 3;
            cp16(sb + (R2_A + R2_B) * 2 + row * 272 + c8 * 2,
                 g_B1 + (size_t)(kt + row) * HDIM + n0 + c8);
        }
        CP_COMMIT();
    };

    load_stage(0, 0);
    load_stage(1, 32);

    const int nch = KRR / 32;   // 32
    for (int i = 0; i < nch; i++) {
        int s = i & 1;
        if (i == nch - 1) asm volatile("cp.async.wait_group 0;" ::: "memory");
        else              asm volatile("cp.async.wait_group 1;" ::: "memory");
        __syncthreads();
        const __half* As  = sm + s * R2_ST;
        const __half* B0s = As + R2_A;
        const __half* B1s = B0s + R2_B;
        #pragma unroll
        for (int ks = 0; ks < 32; ks += 16) {
            wmma::fragment<wmma::matrix_a, 16, 16, 16, __half, wmma::row_major> a0[2];
            wmma::fragment<wmma::matrix_b, 16, 16, 16, __half, wmma::row_major> b0[4], b1[4];
            #pragma unroll
            for (int ii = 0; ii < 2; ii++)
                wmma::load_matrix_sync(a0[ii], As + (wr * 32 + ii * 16) * 40 + ks, 40);
            #pragma unroll
            for (int jj = 0; jj < 4; jj++) {
                wmma::load_matrix_sync(b0[jj], B0s + ks * 136 + wc * 64 + jj * 16, 136);
                wmma::load_matrix_sync(b1[jj], B1s + ks * 136 + wc * 64 + jj * 16, 136);
            }
            #pragma unroll
            for (int ii = 0; ii < 2; ii++)
                #pragma unroll
                for (int jj = 0; jj < 4; jj++) {
                    wmma::mma_sync(acc[ii][jj], a0[ii], b0[jj], acc[ii][jj]);
                    wmma::mma_sync(acc[ii][jj], a0[ii], b1[jj], acc[ii][jj]);
                }
        }
        __syncthreads();
        if (i + 2 < nch) load_stage(s, (i + 2) * 32);
    }

    #pragma unroll
    for (int ii = 0; ii < 2; ii++)
        #pragma unroll
        for (int jj = 0; jj < 4; jj++) {
            float* Cp = C + (size_t)(m0 + wr * 32 + ii * 16) * HDIM + n0 + wc * 64 + jj * 16;
            wmma::store_matrix_sync(Cp, acc[ii][jj], HDIM, wmma::mem_row_major);
        }
}

// ---------------- bf16 GEMM with cp.async double buffering --------------------
__global__ void __launch_bounds__(256) gemm_bf16(const bf16* __restrict__ A,
                                                 const bf16* __restrict__ B,
                                                 float* __restrict__ C,
                                                 int K, int NC) {
    __shared__ __align__(16) bf16 As[2][128][40];
    __shared__ __align__(16) bf16 Bs[2][32][136];
    const int m0 = blockIdx.y * 128;
    const int n0 = blockIdx.x * 128;
    const int tid  = threadIdx.x;
    const int warp = tid >> 5;
    const int wr   = warp >> 1;
    const int wc   = warp & 1;
    const uint32_t sa = smem_u32(&As[0][0][0]);
    const uint32_t sbb = smem_u32(&Bs[0][0][0]);

    wmma::fragment<wmma::accumulator, 16, 16, 16, float> acc[2][4];
    #pragma unroll
    for (int i = 0; i < 2; i++)
        #pragma unroll
        for (int j = 0; j < 4; j++) wmma::fill_fragment(acc[i][j], 0.0f);

    auto load_stage = [&](int st, int kt) {
        uint32_t ab = sa + st * (128 * 40 * 2);
        uint32_t bb = sbb + st * (32 * 136 * 2);
        #pragma unroll
        for (int q = 0; q < 2; q++) {
            int idx = tid + q * 256;
            int row = idx >> 2, c8 = (idx & 3) << 3;
            cp16(ab + row * 80 + c8 * 2, A + (size_t)(m0 + row) * K + kt + c8);
        }
        #pragma unroll
        for (int q = 0; q < 2; q++) {
            int idx = tid + q * 256;
            int row = idx >> 4, c8 = (idx & 15) << 3;
            cp16(bb + row * 272 + c8 * 2, B + (size_t)(kt + row) * NC + n0 + c8);
        }
        CP_COMMIT();
    };

    load_stage(0, 0);
    load_stage(1, 32);

    const int nch = K / 32;
    for (int i = 0; i < nch; i++) {
        int s = i & 1;
        if (i == nch - 1) asm volatile("cp.async.wait_group 0;" ::: "memory");
        else              asm volatile("cp.async.wait_group 1;" ::: "memory");
        __syncthreads();
        #pragma unroll
        for (int ks = 0; ks < 32; ks += 16) {
            wmma::fragment<wmma::matrix_a, 16, 16, 16, bf16, wmma::row_major> af[2];
            wmma::fragment<wmma::matrix_b, 16, 16, 16, bf16, wmma::row_major> bfr[4];
            #pragma unroll
            for (int ii = 0; ii < 2; ii++)
                wmma::load_matrix_sync(af[ii], &As[s][wr * 32 + ii * 16][ks], 40);
            #pragma unroll
            for (int jj = 0; jj < 4; jj++)
                wmma::load_matrix_sync(bfr[jj], &Bs[s][ks][wc * 64 + jj * 16], 136);
            #pragma unroll
            for (int ii = 0; ii < 2; ii++)
                #pragma unroll
                for (int jj = 0; jj < 4; jj++)
                    wmma::mma_sync(acc[ii][jj], af[ii], bfr[jj], acc[ii][jj]);
        }
        __syncthreads();
        if (i + 2 < nch) load_stage(s, (i + 2) * 32);
    }

    #pragma unroll
    for (int i = 0; i < 2; i++)
        #pragma unroll
        for (int j = 0; j < 4; j++) {
            float* Cp = C + (size_t)(m0 + wr * 32 + i * 16) * NC + n0 + wc * 64 + j * 16;
            wmma::store_matrix_sync(Cp, acc[i][j], NC, wmma::mem_row_major);
        }
}

// ---------------- router2: tables + LN + logits + top4 + ctx + feats ----------
__global__ void k_router2(const float* __restrict__ ep,
                          const int* __restrict__ sid, const int* __restrict__ hc,
                          const int* __restrict__ ps,
                          const float* __restrict__ rb1, const float* __restrict__ rlg,
                          const float* __restrict__ rlb,
                          const float* __restrict__ b2, const float* __restrict__ proto,
                          float* __restrict__ outC, float* __restrict__ outW) {
    __shared__ float sh[HDIM];
    __shared__ float2 sb2[4];
    __shared__ float sl[PROTO];
    __shared__ float sw[PROTO];
    int row = blockIdx.x, t = threadIdx.x;    // 128 threads
    int sI = min(max(sid[row], 0), 2048);
    int hI = min(max(hc[row], 0), 9);
    int pI = min(max(ps[row], 0), 7);
    const float4 h4 = reinterpret_cast<const float4*>(&g_H1[(size_t)row * HDIM])[t];
    const float4 b4 = reinterpret_cast<const float4*>(rb1)[t];
    const float4 ts4 = reinterpret_cast<const float4*>(&g_TS[(size_t)sI * HDIM])[t];
    const float4 th4 = reinterpret_cast<const float4*>(&g_TH[(size_t)hI * HDIM])[t];
    const float4 tp4 = reinterpret_cast<const float4*>(&g_TP[(size_t)pI * HDIM])[t];
    float4 pre;
    pre.x = h4.x + b4.x + ts4.x + th4.x + tp4.x;
    pre.y = h4.y + b4.y + ts4.y + th4.y + tp4.y;
    pre.z = h4.z + b4.z + ts4.z + th4.z + tp4.z;
    pre.w = h4.w + b4.w + ts4.w + th4.w + tp4.w;
    float s1 = pre.x + pre.y + pre.z + pre.w;
    float s2 = pre.x * pre.x + pre.y * pre.y + pre.z * pre.z + pre.w * pre.w;
    float2 r = block_sum2_128(s1, s2, sb2);
    float mean = r.x * (1.0f / 512.0f);
    float var  = r.y * (1.0f / 512.0f) - mean * mean;
    float rs = rsqrtf(var + 1e-5f);
    const float4 g4  = reinterpret_cast<const float4*>(rlg)[t];
    const float4 be4 = reinterpret_cast<const float4*>(rlb)[t];
    float4 hv;
    hv.x = gelu_exact((pre.x - mean) * rs * g4.x + be4.x);
    hv.y = gelu_exact((pre.y - mean) * rs * g4.y + be4.y);
    hv.z = gelu_exact((pre.z - mean) * rs * g4.z + be4.z);
    hv.w = gelu_exact((pre.w - mean) * rs * g4.w + be4.w);
    reinterpret_cast<float4*>(sh)[t] = hv;
    __syncthreads();
    int warp = t >> 5, lane = t & 31;
    #pragma unroll
    for (int q = 0; q < 3; q++) {
        int l = warp * 3 + q;
        const float* wl = &g_W2T[l * HDIM];
        float sa = 0.0f, sb = 0.0f;
        #pragma unroll
        for (int c = 0; c < HDIM; c += 64) {
            sa = fmaf(sh[c + lane],      wl[c + lane],      sa);
            sb = fmaf(sh[c + lane + 32], wl[c + lane + 32], sb);
        }
        sa += sb;
        #pragma unroll
        for (int o = 16; o; o >>= 1) sa += __shfl_xor_sync(0xffffffffu, sa, o);
        if (lane == 0) sl[l] = sa + b2[l];
    }
    __syncthreads();
    if (t == 0) {
        float v[PROTO];
        #pragma unroll
        for (int i = 0; i < PROTO; i++) v[i] = sl[i];
        float top5[5];
        #pragma unroll
        for (int k = 0; k < 5; k++) {
            int bi = 0; float bv = -1e30f;
            #pragma unroll
            for (int i = 0; i < PROTO; i++)
                if (v[i] > bv) { bv = v[i]; bi = i; }
            top5[k] = bv; v[bi] = -1e30f;
        }
        if (top5[3] - top5[4] < 2e-3f) {
            int pos = atomicAdd(&g_count, 1);
            g_LIST[pos] = row;
        }
        float w[PROTO];
        float mx = -1e30f;
        #pragma unroll
        for (int i = 0; i < PROTO; i++) mx = fmaxf(mx, sl[i]);
        float ssum = 0.0f;
        #pragma unroll
        for (int i = 0; i < PROTO; i++) { w[i] = expf(sl[i] - mx); ssum += w[i]; }
        float inv = 1.0f / ssum;
        #pragma unroll
        for (int i = 0; i < PROTO; i++) w[i] *= inv;
        bool sel[PROTO];
        #pragma unroll
        for (int i = 0; i < PROTO; i++) sel[i] = false;
        for (int k = 0; k < 4; k++) {
            int bi = -1; float bv = -1e30f;
            #pragma unroll
            for (int i = 0; i < PROTO; i++)
                if (!sel[i] && w[i] > bv) { bv = w[i]; bi = i; }
            sel[bi] = true;
        }
        float s22 = 0.0f;
        #pragma unroll
        for (int i = 0; i < PROTO; i++) { float vv = sel[i] ? w[i] : 0.0f; sw[i] = vv; s22 += vv; }
        float d = 1.0f / fmaxf(s22, 1e-6f);
        #pragma unroll
        for (int i = 0; i < PROTO; i++) sw[i] *= d;
    }
    __syncthreads();
    if (t < PROTO) outW[(size_t)row * PROTO + t] = sw[t];
    const float4 e4 = reinterpret_cast<const float4*>(&ep[(size_t)row * HDIM])[t];
    float4 c4 = make_float4(0.f, 0.f, 0.f, 0.f);
    #pragma unroll
    for (int p = 0; p < PROTO; p++) {
        float wv = sw[p];
        const float4 p4 = reinterpret_cast<const float4*>(&proto[p * HDIM])[t];
        c4.x = fmaf(wv, p4.x, c4.x);
        c4.y = fmaf(wv, p4.y, c4.y);
        c4.z = fmaf(wv, p4.z, c4.z);
        c4.w = fmaf(wv, p4.w, c4.w);
    }
    reinterpret_cast<float4*>(&outC[(size_t)row * HDIM])[t] = c4;
    bf16* frow = &g_FEATSH[(size_t)row * KFN];
    st_bf4(frow + 4 * t, e4);
    st_bf4(frow + 512 + 4 * t, make_float4(fabsf(e4.x - c4.x), fabsf(e4.y - c4.y),
                                           fabsf(e4.z - c4.z), fabsf(e4.w - c4.w)));
    st_bf4(frow + 1024 + 4 * t, make_float4(e4.x * c4.x, e4.y * c4.y,
                                            e4.z * c4.z, e4.w * c4.w));
    if (t < 32) frow[1536 + t] = __float2bfloat16_rn(t < PROTO ? sw[t] : 0.0f);
}

// ---------------- rescue (exact fp32 path) ------------------------------------
__global__ void __launch_bounds__(128) k_rescue(
        const float* __restrict__ pair, const float* __restrict__ ep,
        const int* __restrict__ sid, const int* __restrict__ hc, const int* __restrict__ ps,
        const float* __restrict__ se, const float* __restrict__ he, const float* __restrict__ soe,
        const float* __restrict__ rw1, const float* __restrict__ rb1,
        const float* __restrict__ rlg, const float* __restrict__ rlb,
        const float* __restrict__ b2, const float* __restrict__ proto,
        float* __restrict__ outC, float* __restrict__ outW) {
    __shared__ float sa[KR];
    __shared__ float shd[HDIM];
    __shared__ double dbuf[4];
    __shared__ float sl[PROTO];
    __shared__ float sw[PROTO];
    int t = threadIdx.x, warp = t >> 5, lane = t & 31;
    int cnt = g_count;
    for (int li = blockIdx.x; li < cnt; li += gridDim.x) {
        int row = g_LIST[li];
        int s = min(max(sid[row], 0), 2048);
        int h = min(max(hc[row], 0), 9);
        int p = min(max(ps[row], 0), 7);
        const float* pr = &pair[(size_t)row * HDIM];
        const float* er = &ep[(size_t)row * HDIM];
        for (int k = t; k < KR; k += 128) {
            float v;
            if      (k < 512)  v = pr[k];
            else if (k < 1024) v = er[k - 512];
            else if (k < 1152) v = se[s * MD + (k - 1024)];
            else if (k < 1280) v = he[h * MD + (k - 1152)];
            else               v = soe[p * MD + (k - 1280)];
            sa[k] = v;
        }
        __syncthreads();
        float hs[4], hcmp[4];
        #pragma unroll
        for (int j = 0; j < 4; j++) { hs[j] = 0.0f; hcmp[j] = 0.0f; }
        for (int k = 0; k < KR; k++) {
            float a = sa[k];
            const float* wr = &rw1[(size_t)k * HDIM];
            #pragma unroll
            for (int j = 0; j < 4; j++) {
                int c = t + j * 128;
                float w = wr[c];
                float pp = a * w;
                float pe = fmaf(a, w, -pp);
                twosum_acc(hs[j], hcmp[j], pp);
                hcmp[j] += pe;
            }
        }
        float pre[4];
        double msum = 0.0;
        #pragma unroll
        for (int j = 0; j < 4; j++) {
            pre[j] = (hs[j] + hcmp[j]) + rb1[t + j * 128];
            msum += (double)pre[j];
        }
        double mean = block_sum_128d(msum, dbuf) * (1.0 / 512.0);
        double vsum = 0.0;
        #pragma unroll
        for (int j = 0; j < 4; j++) {
            double e0 = (double)pre[j] - mean;
            vsum += e0 * e0;
        }
        double var = block_sum_128d(vsum, dbuf) * (1.0 / 512.0);
        float rs = (float)(1.0 / sqrt(var + 1e-5));
        #pragma unroll
        for (int j = 0; j < 4; j++) {
            int c = t + j * 128;
            shd[c] = gelu_exact((float)((double)pre[j] - mean) * rs * rlg[c] + rlb[c]);
        }
        __syncthreads();
        for (int l = warp; l < PROTO; l += 4) {
            float ss = 0.0f, cmp = 0.0f;
            const float* wl = &g_W2T[l * HDIM];
            for (int c = lane; c < HDIM; c += 32) {
                float a = shd[c], w = wl[c];
                float pp = a * w;
                float pe = fmaf(a, w, -pp);
                twosum_acc(ss, cmp, pp);
                cmp += pe;
            }
            #pragma unroll
            for (int o = 16; o; o >>= 1) {
                ss  += __shfl_xor_sync(0xffffffffu, ss, o);
                cmp += __shfl_xor_sync(0xffffffffu, cmp, o);
            }
            if (lane == 0) sl[l] = (ss + cmp) + b2[l];
        }
        __syncthreads();
        if (t == 0) {
            float w[PROTO];
            float mx = -1e30f;
            #pragma unroll
            for (int i = 0; i < PROTO; i++) mx = fmaxf(mx, sl[i]);
            float ssum = 0.0f;
            #pragma unroll
            for (int i = 0; i < PROTO; i++) { w[i] = expf(sl[i] - mx); ssum += w[i]; }
            float inv = 1.0f / ssum;
            #pragma unroll
            for (int i = 0; i < PROTO; i++) w[i] *= inv;
            bool sel[PROTO];
            #pragma unroll
            for (int i = 0; i < PROTO; i++) sel[i] = false;
            for (int k = 0; k < 4; k++) {
                int bi = -1; float bv = -1e30f;
                #pragma unroll
                for (int i = 0; i < PROTO; i++)
                    if (!sel[i] && w[i] > bv) { bv = w[i]; bi = i; }
                sel[bi] = true;
            }
            float s2 = 0.0f;
            #pragma unroll
            for (int i = 0; i < PROTO; i++) { float vv = sel[i] ? w[i] : 0.0f; sw[i] = vv; s2 += vv; }
            float d = 1.0f / fmaxf(s2, 1e-6f);
            #pragma unroll
            for (int i = 0; i < PROTO; i++) sw[i] *= d;
        }
        __syncthreads();
        if (t < PROTO) outW[(size_t)row * PROTO + t] = sw[t];
        bf16* frow = &g_FEATSH[(size_t)row * KFN];
        for (int j = t; j < HDIM; j += 128) {
            float c = 0.0f;
            #pragma unroll
            for (int pp = 0; pp < PROTO; pp++) c += sw[pp] * proto[pp * HDIM + j];
            float e = er[j];
            outC[(size_t)row * HDIM + j] = c;
            frow[j]        = __float2bfloat16_rn(e);
            frow[512 + j]  = __float2bfloat16_rn(fabsf(e - c));
            frow[1024 + j] = __float2bfloat16_rn(e * c);
        }
        if (t < 32) frow[1536 + t] = __float2bfloat16_rn(t < PROTO ? sw[t] : 0.0f);
        __syncthreads();
    }
}

// ---------------- activations (float4, single-pass LN) ------------------------
__global__ void k_act(const float* __restrict__ b_mu, const float* __restrict__ g_mu,
                      const float* __restrict__ be_mu, const float* __restrict__ b_mg) {
    __shared__ float2 sb2[4];
    int row = blockIdx.x, t = threadIdx.x;
    const float4* h12 = reinterpret_cast<const float4*>(&g_H12[(size_t)row * 1024]);
    const float4 m4i = h12[t];
    const float4 b4 = reinterpret_cast<const float4*>(b_mu)[t];
    float4 m4 = make_float4(m4i.x + b4.x, m4i.y + b4.y, m4i.z + b4.z, m4i.w + b4.w);
    float s1 = m4.x + m4.y + m4.z + m4.w;
    float s2 = m4.x * m4.x + m4.y * m4.y + m4.z * m4.z + m4.w * m4.w;
    float2 r = block_sum2_128(s1, s2, sb2);
    float mean = r.x * (1.0f / 512.0f);
    float var  = r.y * (1.0f / 512.0f) - mean * mean;
    float rs = rsqrtf(var + 1e-5f);
    const float4 g4  = reinterpret_cast<const float4*>(g_mu)[t];
    const float4 be4 = reinterpret_cast<const float4*>(be_mu)[t];
    float4 xm;
    xm.x = gelu_exact((m4.x - mean) * rs * g4.x + be4.x);
    xm.y = gelu_exact((m4.y - mean) * rs * g4.y + be4.y);
    xm.z = gelu_exact((m4.z - mean) * rs * g4.z + be4.z);
    xm.w = gelu_exact((m4.w - mean) * rs * g4.w + be4.w);
    st_bf4(&g_HMUH[(size_t)row * HDIM] + 4 * t, xm);
    const float4 gg4i = h12[128 + t];
    const float4 bg4 = reinterpret_cast<const float4*>(b_mg)[t];
    float4 xg;
    xg.x = gelu_exact(gg4i.x + bg4.x);
    xg.y = gelu_exact(gg4i.y + bg4.y);
    xg.z = gelu_exact(gg4i.z + bg4.z);
    xg.w = gelu_exact(gg4i.w + bg4.w);
    st_bf4(&g_HMGH[(size_t)row * HDIM] + 4 * t, xg);
}

// ---------------- final (float4, single-pass LN) ------------------------------
__global__ void k_final(const float* __restrict__ ep, const float* __restrict__ mub2,
                        const float* __restrict__ mgb2, const float* __restrict__ ng,
                        const float* __restrict__ nb, float* __restrict__ outU) {
    __shared__ float2 sb2[4];
    int row = blockIdx.x, t = threadIdx.x;
    const float4 e4 = reinterpret_cast<const float4*>(&ep[(size_t)row * HDIM])[t];
    const float4 d4 = reinterpret_cast<const float4*>(&g_DELTA[(size_t)row * HDIM])[t];
    const float4 gp4 = reinterpret_cast<const float4*>(&g_GATE[(size_t)row * HDIM])[t];
    const float4 db4 = reinterpret_cast<const float4*>(mub2)[t];
    const float4 gb4 = reinterpret_cast<const float4*>(mgb2)[t];
    float4 u;
    u.x = e4.x + RSCALE * (1.0f / (1.0f + expf(-(gp4.x + gb4.x)))) * (d4.x + db4.x);
    u.y = e4.y + RSCALE * (1.0f / (1.0f + expf(-(gp4.y + gb4.y)))) * (d4.y + db4.y);
    u.z = e4.z + RSCALE * (1.0f / (1.0f + expf(-(gp4.z + gb4.z)))) * (d4.z + db4.z);
    u.w = e4.w + RSCALE * (1.0f / (1.0f + expf(-(gp4.w + gb4.w)))) * (d4.w + db4.w);
    float s1 = u.x + u.y + u.z + u.w;
    float s2 = u.x * u.x + u.y * u.y + u.z * u.z + u.w * u.w;
    float2 r = block_sum2_128(s1, s2, sb2);
    float mean = r.x * (1.0f / 512.0f);
    float var  = r.y * (1.0f / 512.0f) - mean * mean;
    float rs = rsqrtf(var + 1e-5f);
    const float4 g4 = reinterpret_cast<const float4*>(ng)[t];
    const float4 b4 = reinterpret_cast<const float4*>(nb)[t];
    float4 o;
    o.x = (u.x - mean) * rs * g4.x + b4.x;
    o.y = (u.y - mean) * rs * g4.y + b4.y;
    o.z = (u.z - mean) * rs * g4.z + b4.z;
    o.w = (u.w - mean) * rs * g4.w + b4.w;
    reinterpret_cast<float4*>(&outU[(size_t)row * HDIM])[t] = o;
}

// ---------------- launch ----------------
extern "C" void kernel_launch(void* const* d_in, const int* in_sizes, int n_in,
                              void* d_out, int out_size) {
    const float* pair = (const float*)d_in[0];
    const float* ep   = (const float*)d_in[1];
    const int*   sid  = (const int*)d_in[2];
    const int*   hc   = (const int*)d_in[3];
    const int*   ps   = (const int*)d_in[4];
    const float* se   = (const float*)d_in[5];
    const float* he   = (const float*)d_in[6];
    const float* soe  = (const float*)d_in[7];
    const float* proto= (const float*)d_in[8];
    const float* rw1  = (const float*)d_in[9];
    const float* rb1  = (const float*)d_in[10];
    const float* rlg  = (const float*)d_in[11];
    const float* rlb  = (const float*)d_in[12];
    const float* rw2  = (const float*)d_in[13];
    const float* rb2  = (const float*)d_in[14];
    const float* muw1 = (const float*)d_in[15];
    const float* mub1 = (const float*)d_in[16];
    const float* mulg = (const float*)d_in[17];
    const float* mulb = (const float*)d_in[18];
    const float* muw2 = (const float*)d_in[19];
    const float* mub2 = (const float*)d_in[20];
    const float* mgw1 = (const float*)d_in[21];
    const float* mgb1 = (const float*)d_in[22];
    const float* mgw2 = (const float*)d_in[23];
    const float* mgb2 = (const float*)d_in[24];
    const float* ng   = (const float*)d_in[25];
    const float* nb   = (const float*)d_in[26];

    float* outU = (float*)d_out;
    float* outC = outU + (size_t)NROWS * HDIM;
    float* outW = outC + (size_t)NROWS * HDIM;

    float *pH1, *pH12, *pDELTA, *pGATE;
    bf16 *pFEATSH, *pHMUH, *pHMGH, *pW1, *pW2MU, *pW2MG;
    cudaGetSymbolAddress((void**)&pH1,     g_H1);
    cudaGetSymbolAddress((void**)&pH12,    g_H12);
    cudaGetSymbolAddress((void**)&pDELTA,  g_DELTA);
    cudaGetSymbolAddress((void**)&pGATE,   g_GATE);
    cudaGetSymbolAddress((void**)&pFEATSH, g_FEATSH);
    cudaGetSymbolAddress((void**)&pHMUH,   g_HMUH);
    cudaGetSymbolAddress((void**)&pHMGH,   g_HMGH);
    cudaGetSymbolAddress((void**)&pW1,     g_W1);
    cudaGetSymbolAddress((void**)&pW2MU,   g_W2MU);
    cudaGetSymbolAddress((void**)&pW2MG,   g_W2MG);

    static bool attr_set = false;
    if (!attr_set) {
        cudaFuncSetAttribute(gemm_router2, cudaFuncAttributeMaxDynamicSharedMemorySize,
                             2 * R2_ST * 2 + 256);
        attr_set = true;
    }

    k_prep<<<4096, 256>>>(rw1, rw2, muw1, mgw1, muw2, mgw2, se, he, soe, proto);
    k_gather<<<NROWS, 128>>>(pair, ep);
    {
        dim3 grid(HDIM / 128, NROWS / 128);
        gemm_router2<<<grid, 256, 2 * R2_ST * 2 + 256>>>(pH1);
    }
    k_router2<<<NROWS, 128>>>(ep, sid, hc, ps, rb1, rlg, rlb, rb2, proto, outC, outW);
    k_rescue<<<2048, 128>>>(pair, ep, sid, hc, ps, se, he, soe,
                            rw1, rb1, rlg, rlb, rb2, proto, outC, outW);
    {
        dim3 grid(1024 / 128, NROWS / 128);
        gemm_bf16<<<grid, 256>>>(pFEATSH, pW1, pH12, KFN, 1024);
    }
    k_act<<<NROWS, 128>>>(mub1, mulg, mulb, mgb1);
    {
        dim3 grid(HDIM / 128, NROWS / 128);
        gemm_bf16<<<grid, 256>>>(pHMUH, pW2MU, pDELTA, HDIM, HDIM);
        gemm_bf16<<<grid, 256>>>(pHMGH, pW2MG, pGATE, HDIM, HDIM);
    }
    k_final<<<NROWS, 128>>>(ep, mub2, mgb2, ng, nb, outU);
}